// round 3
// baseline (speedup 1.0000x reference)
#include <cuda_runtime.h>
#include <cuda_bf16.h>
#include <math.h>

// Problem constants
#define TT   512
#define BB   64
#define II   512
#define CC   512            // cell size
#define HH   1024           // output hidden (2*CC)
#define G4   2048           // 4*CC gate rows
#define M1   (TT*BB)        // 32768 rows for input gemm

// d_out layout: output [T,B,H] | final_h [1,B,H] | final_c [1,B,H] | context [B,H]
#define OFF_OUT  0
#define OFF_H    ((size_t)TT*BB*HH)               // 33554432
#define OFF_C    (OFF_H + (size_t)BB*HH)          // +65536
#define OFF_CTX  (OFF_C + (size_t)BB*HH)          // +65536

// ---------------- device scratch (static; no runtime allocation) ----------------
__device__ float g_gx[(size_t)2 * M1 * G4];   // precomputed x@Wih^T + bih + bhh, per dir: [T*B][2048]
__device__ float g_scores[(size_t)BB * TT * TT];
__device__ float g_hbuf[2 * 2 * BB * CC];     // [parity][dir][b][c]
__device__ float g_c[2 * BB * CC];            // [dir][b][c]
__device__ float g_rowmax[BB * TT];
__device__ float g_rowinv[BB * TT];
__device__ float g_w[BB * TT];
__device__ float g_pre[BB * HH];

// ---------------- init ----------------
__global__ void k_zero() {
    int i = blockIdx.x * 256 + threadIdx.x;   // 65536 threads
    if (i < 2 * BB * CC) {
        g_hbuf[i] = 0.f;   // parity-0 buffer (both dirs)
        g_c[i]    = 0.f;
    }
}

// ---------------- phase 1: gx[dir][t*B+b][j] = x @ Wih_dir^T + bih + bhh ----------------
// M=32768, N=2048, K=512. BM=BN=128, BK=16, 256 threads, 8x8 microtile.
__global__ void __launch_bounds__(256) k_gatesx(
    const float* __restrict__ x,
    const float* __restrict__ Wf, const float* __restrict__ Wb,
    const float* __restrict__ bif, const float* __restrict__ bhf,
    const float* __restrict__ bib, const float* __restrict__ bhb)
{
    __shared__ __align__(16) float As[16][128];
    __shared__ __align__(16) float Bs[16][128];

    const int dir = blockIdx.z;
    const float* W  = dir ? Wb  : Wf;
    const float* bi = dir ? bib : bif;
    const float* bh = dir ? bhb : bhf;
    float* out = g_gx + (size_t)dir * M1 * G4;

    const int tid = threadIdx.x;
    const int m0 = blockIdx.y * 128;
    const int n0 = blockIdx.x * 128;
    const int lr = tid >> 1;              // 0..127
    const int lk = (tid & 1) << 3;        // 0 or 8
    const float* Ap = x + (size_t)(m0 + lr) * II + lk;
    const float* Bp = W + (size_t)(n0 + lr) * II + lk;
    const int ty = tid >> 4, tx = tid & 15;

    float acc[8][8];
#pragma unroll
    for (int i = 0; i < 8; i++)
#pragma unroll
        for (int j = 0; j < 8; j++) acc[i][j] = 0.f;

    for (int k0 = 0; k0 < II; k0 += 16) {
        float4 a0 = *(const float4*)(Ap + k0);
        float4 a1 = *(const float4*)(Ap + k0 + 4);
        float4 b0 = *(const float4*)(Bp + k0);
        float4 b1 = *(const float4*)(Bp + k0 + 4);
        __syncthreads();
        As[lk+0][lr]=a0.x; As[lk+1][lr]=a0.y; As[lk+2][lr]=a0.z; As[lk+3][lr]=a0.w;
        As[lk+4][lr]=a1.x; As[lk+5][lr]=a1.y; As[lk+6][lr]=a1.z; As[lk+7][lr]=a1.w;
        Bs[lk+0][lr]=b0.x; Bs[lk+1][lr]=b0.y; Bs[lk+2][lr]=b0.z; Bs[lk+3][lr]=b0.w;
        Bs[lk+4][lr]=b1.x; Bs[lk+5][lr]=b1.y; Bs[lk+6][lr]=b1.z; Bs[lk+7][lr]=b1.w;
        __syncthreads();
#pragma unroll
        for (int k = 0; k < 16; k++) {
            float a[8], b[8];
            *(float4*)&a[0] = *(const float4*)&As[k][ty*8];
            *(float4*)&a[4] = *(const float4*)&As[k][ty*8+4];
            *(float4*)&b[0] = *(const float4*)&Bs[k][tx*8];
            *(float4*)&b[4] = *(const float4*)&Bs[k][tx*8+4];
#pragma unroll
            for (int i = 0; i < 8; i++)
#pragma unroll
                for (int j = 0; j < 8; j++)
                    acc[i][j] += a[i] * b[j];
        }
    }

    float bias[8];
#pragma unroll
    for (int j = 0; j < 8; j++) {
        int n = n0 + tx*8 + j;
        bias[j] = bi[n] + bh[n];
    }
#pragma unroll
    for (int i = 0; i < 8; i++) {
        size_t base = (size_t)(m0 + ty*8 + i) * G4 + n0 + tx*8;
#pragma unroll
        for (int j = 0; j < 8; j++)
            out[base + j] = acc[i][j] + bias[j];
    }
}

// ---------------- phase 2: one LSTM timestep, both directions fused ----------------
// 128 blocks: dir = blk>>6, cell group = (blk&63)*8 cells -> 32 gate cols.
// Tile: 64 batches x 32 gate cols, K=512. 256 threads, 4x2 microtile.
__global__ void __launch_bounds__(256) k_step(
    const float* __restrict__ Whhf, const float* __restrict__ Whhb,
    const int* __restrict__ length, float* __restrict__ outp, int step)
{
    __shared__ __align__(16) float hs[16][64];
    __shared__ __align__(16) float ws[16][32];
    __shared__ float gsm[64][33];

    const int tid = threadIdx.x;
    const int dir = blockIdx.x >> 6;
    const int c0  = (blockIdx.x & 63) << 3;
    const int t   = dir ? (TT - 1 - step) : step;
    const int p   = step & 1;
    const float* Whh  = dir ? Whhb : Whhf;
    const float* hin  = g_hbuf + ((size_t)p * 2 + dir) * BB * CC;
    float*       hout = g_hbuf + ((size_t)(p ^ 1) * 2 + dir) * BB * CC;

    const int rg  = tid & 15;   // rows rg*4 .. rg*4+3
    const int cgp = tid >> 4;   // cols cgp*2, cgp*2+1
    float acc[4][2] = {{0.f,0.f},{0.f,0.f},{0.f,0.f},{0.f,0.f}};

    const int lb = tid >> 2;            // batch for h load
    const int lk = (tid & 3) << 2;      // 0,4,8,12
    const int wj = tid >> 2;            // gate col for w load (tid<128)
    const int wG = ((wj >> 3) << 9) + c0 + (wj & 7);   // gate row in Whh

    const float* hp = hin + lb * CC + lk;
    const float* wp = Whh + (size_t)wG * CC + lk;

    for (int k0 = 0; k0 < CC; k0 += 16) {
        float4 hv = *(const float4*)(hp + k0);
        float4 wv = make_float4(0.f,0.f,0.f,0.f);
        if (tid < 128) wv = *(const float4*)(wp + k0);
        __syncthreads();
        hs[lk+0][lb]=hv.x; hs[lk+1][lb]=hv.y; hs[lk+2][lb]=hv.z; hs[lk+3][lb]=hv.w;
        if (tid < 128) {
            ws[lk+0][wj]=wv.x; ws[lk+1][wj]=wv.y; ws[lk+2][wj]=wv.z; ws[lk+3][wj]=wv.w;
        }
        __syncthreads();
#pragma unroll
        for (int k = 0; k < 16; k++) {
            float4 h4 = *(const float4*)&hs[k][rg*4];
            float w0 = ws[k][cgp*2], w1 = ws[k][cgp*2+1];
            acc[0][0] += h4.x*w0;  acc[0][1] += h4.x*w1;
            acc[1][0] += h4.y*w0;  acc[1][1] += h4.y*w1;
            acc[2][0] += h4.z*w0;  acc[2][1] += h4.z*w1;
            acc[3][0] += h4.w*w0;  acc[3][1] += h4.w*w1;
        }
    }

    // add precomputed x-gates, stash to smem for per-cell recombination
#pragma unroll
    for (int i = 0; i < 4; i++) {
        int b = rg*4 + i;
        size_t rowbase = ((size_t)dir * M1 + (size_t)t * BB + b) * G4;
#pragma unroll
        for (int jj = 0; jj < 2; jj++) {
            int j = cgp*2 + jj;
            int G = ((j >> 3) << 9) + c0 + (j & 7);
            gsm[b][j] = acc[i][jj] + g_gx[rowbase + G];
        }
    }
    __syncthreads();

    // activations + masked state update (2 cell-states per thread)
#pragma unroll
    for (int u = 0; u < 2; u++) {
        int idx = tid + (u << 8);          // 0..511
        int b = idx >> 3, cc = idx & 7;
        int cell = c0 + cc;
        float ig = gsm[b][cc];
        float fg = gsm[b][8  + cc];
        float gg = gsm[b][16 + cc];
        float og = gsm[b][24 + cc];
        ig = 1.f / (1.f + expf(-ig));
        fg = 1.f / (1.f + expf(-fg));
        gg = tanhf(gg);
        og = 1.f / (1.f + expf(-og));
        int cidx = (dir * BB + b) * CC + cell;
        float c_old = g_c[cidx];
        float h_old = hin[b * CC + cell];
        float cn = fg * c_old + ig * gg;
        float hn = og * tanhf(cn);
        bool m = (t < length[b]);
        g_c[cidx]             = m ? cn : c_old;
        hout[b * CC + cell]   = m ? hn : h_old;
        outp[(size_t)t * (BB*HH) + b * HH + (dir << 9) + cell] = m ? hn : 0.f;
    }
}

// ---------------- final states ----------------
__global__ void k_final(float* __restrict__ outp) {
    int idx = blockIdx.x * 256 + threadIdx.x;   // 0..65535
    int dir = idx >> 15;
    int r = idx & 32767;
    int b = r >> 9, c = r & 511;
    // final h lives in parity-0 buffer after 512 steps
    outp[OFF_H + b * HH + dir * CC + c] = g_hbuf[((size_t)0 * 2 + dir) * BB * CC + b * CC + c];
    outp[OFF_C + b * HH + dir * CC + c] = g_c[(dir * BB + b) * CC + c];
}

// ---------------- attention scores: scores[b,t,s] = <out[t,b,:], out[s,b,:]> ----------------
// per-batch symmetric GEMM, 64x64 tiles, BK=16, exploit symmetry (ti<=tj, mirror write)
__global__ void __launch_bounds__(256) k_scores(const float* __restrict__ outp) {
    const int tj = blockIdx.x, ti = blockIdx.y, b = blockIdx.z;
    if (ti > tj) return;
    __shared__ __align__(16) float As[16][64];
    __shared__ __align__(16) float Bs[16][64];
    const int tid = threadIdx.x;
    const int rg = tid & 15, cg = tid >> 4;
    const int lr = tid >> 2, lk = (tid & 3) << 2;
    const float* Ap = outp + (size_t)(ti*64 + lr) * (BB*HH) + b * HH + lk;
    const float* Bp = outp + (size_t)(tj*64 + lr) * (BB*HH) + b * HH + lk;
    float acc[4][4];
#pragma unroll
    for (int i = 0; i < 4; i++)
#pragma unroll
        for (int j = 0; j < 4; j++) acc[i][j] = 0.f;

    for (int k0 = 0; k0 < HH; k0 += 16) {
        float4 av = *(const float4*)(Ap + k0);
        float4 bv = *(const float4*)(Bp + k0);
        __syncthreads();
        As[lk+0][lr]=av.x; As[lk+1][lr]=av.y; As[lk+2][lr]=av.z; As[lk+3][lr]=av.w;
        Bs[lk+0][lr]=bv.x; Bs[lk+1][lr]=bv.y; Bs[lk+2][lr]=bv.z; Bs[lk+3][lr]=bv.w;
        __syncthreads();
#pragma unroll
        for (int k = 0; k < 16; k++) {
            float4 a4 = *(const float4*)&As[k][rg*4];
            float4 b4 = *(const float4*)&Bs[k][cg*4];
            acc[0][0]+=a4.x*b4.x; acc[0][1]+=a4.x*b4.y; acc[0][2]+=a4.x*b4.z; acc[0][3]+=a4.x*b4.w;
            acc[1][0]+=a4.y*b4.x; acc[1][1]+=a4.y*b4.y; acc[1][2]+=a4.y*b4.z; acc[1][3]+=a4.y*b4.w;
            acc[2][0]+=a4.z*b4.x; acc[2][1]+=a4.z*b4.y; acc[2][2]+=a4.z*b4.z; acc[2][3]+=a4.z*b4.w;
            acc[3][0]+=a4.w*b4.x; acc[3][1]+=a4.w*b4.y; acc[3][2]+=a4.w*b4.z; acc[3][3]+=a4.w*b4.w;
        }
    }
#pragma unroll
    for (int i = 0; i < 4; i++) {
        int trow = ti*64 + rg*4 + i;
#pragma unroll
        for (int j = 0; j < 4; j++) {
            int scol = tj*64 + cg*4 + j;
            g_scores[((size_t)b * TT + trow) * TT + scol] = acc[i][j];
            if (ti < tj)
                g_scores[((size_t)b * TT + scol) * TT + trow] = acc[i][j];
        }
    }
}

// ---------------- per-row softmax stats (max, 1/sumexp) ----------------
__global__ void k_rowstats() {
    int warp = threadIdx.x >> 5, lane = threadIdx.x & 31;
    int row = blockIdx.x * 8 + warp;           // 0..32767 = b*512+t
    const float* sc = g_scores + (size_t)row * TT;
    float mx = -1e30f;
    for (int s = lane; s < TT; s += 32) mx = fmaxf(mx, sc[s]);
#pragma unroll
    for (int o = 16; o > 0; o >>= 1) mx = fmaxf(mx, __shfl_xor_sync(0xffffffffu, mx, o));
    float sum = 0.f;
    for (int s = lane; s < TT; s += 32) sum += expf(sc[s] - mx);
#pragma unroll
    for (int o = 16; o > 0; o >>= 1) sum += __shfl_xor_sync(0xffffffffu, sum, o);
    if (lane == 0) {
        g_rowmax[row] = mx;
        g_rowinv[row] = 1.f / sum;
    }
}

// ---------------- w[b,s] = sum_t attn[b,t,s] ----------------
__global__ void k_colsum() {
    int s = blockIdx.x * 256 + threadIdx.x;
    int b = blockIdx.y;
    float acc = 0.f;
    const float* sc = g_scores + (size_t)b * TT * TT + s;
    const float* rm = g_rowmax + b * TT;
    const float* ri = g_rowinv + b * TT;
    for (int t = 0; t < TT; t++)
        acc += expf(sc[(size_t)t * TT] - rm[t]) * ri[t];
    g_w[b * TT + s] = acc;
}

// ---------------- pre[b,h] = sum_s w[b,s] * out[s,b,h] ----------------
__global__ void k_ctxpre(const float* __restrict__ outp) {
    int h = blockIdx.x * 256 + threadIdx.x;
    int b = blockIdx.y;
    const float* w = g_w + b * TT;
    float acc = 0.f;
    for (int s = 0; s < TT; s++)
        acc += w[s] * outp[(size_t)s * (BB*HH) + b * HH + h];
    g_pre[b * HH + h] = acc;
}

// ---------------- context[b,n] = pre[b,:] @ Wctx[n,:] + bctx[n] ----------------
__global__ void __launch_bounds__(128) k_ctxgemm(
    const float* __restrict__ Wctx, const float* __restrict__ bctx,
    float* __restrict__ outp)
{
    __shared__ float sp[HH];
    int tid = threadIdx.x;
    int b = blockIdx.y;
    for (int i = tid; i < HH; i += 128) sp[i] = g_pre[b * HH + i];
    __syncthreads();
    int n = blockIdx.x * 128 + tid;
    const float* wr = Wctx + (size_t)n * HH;
    float acc = bctx[n];
    for (int h = 0; h < HH; h += 4) {
        float4 w4 = *(const float4*)(wr + h);
        acc += sp[h]*w4.x + sp[h+1]*w4.y + sp[h+2]*w4.z + sp[h+3]*w4.w;
    }
    outp[OFF_CTX + b * HH + n] = acc;
}

// ---------------- launch ----------------
extern "C" void kernel_launch(void* const* d_in, const int* in_sizes, int n_in,
                              void* d_out, int out_size)
{
    const float* x      = (const float*)d_in[0];
    const int*   length = (const int*)  d_in[1];
    const float* Wih_f  = (const float*)d_in[2];
    const float* Whh_f  = (const float*)d_in[3];
    const float* bih_f  = (const float*)d_in[4];
    const float* bhh_f  = (const float*)d_in[5];
    const float* Wih_b  = (const float*)d_in[6];
    const float* Whh_b  = (const float*)d_in[7];
    const float* bih_b  = (const float*)d_in[8];
    const float* bhh_b  = (const float*)d_in[9];
    const float* Wctx   = (const float*)d_in[10];
    const float* bctx   = (const float*)d_in[11];
    float* out = (float*)d_out;

    k_zero<<<256, 256>>>();
    k_gatesx<<<dim3(16, 256, 2), 256>>>(x, Wih_f, Wih_b, bih_f, bhh_f, bih_b, bhh_b);
    for (int s = 0; s < TT; s++)
        k_step<<<128, 256>>>(Whh_f, Whh_b, length, out, s);
    k_final<<<256, 256>>>(out);
    k_scores<<<dim3(8, 8, 64), 256>>>(out);
    k_rowstats<<<TT * BB / 8, 256>>>();
    k_colsum<<<dim3(2, 64), 256>>>();
    k_ctxpre<<<dim3(4, 64), 256>>>(out);
    k_ctxgemm<<<dim3(8, 64), 128>>>(Wctx, bctx, out);
}

// round 4
// speedup vs baseline: 1.0110x; 1.0110x over previous
#include <cuda_runtime.h>
#include <cuda_bf16.h>
#include <math.h>

// Problem constants
#define TT   512
#define BB   64
#define II   512
#define CC   512            // cell size
#define HH   1024           // output hidden (2*CC)
#define G4   2048           // 4*CC gate rows
#define M1   (TT*BB)        // 32768 rows for input gemm

// d_out layout: output [T,B,H] | final_h [1,B,H] | final_c [1,B,H] | context [B,H]
#define OFF_OUT  0
#define OFF_H    ((size_t)TT*BB*HH)               // 33554432
#define OFF_C    (OFF_H + (size_t)BB*HH)          // +65536
#define OFF_CTX  (OFF_C + (size_t)BB*HH)          // +65536

// ---------------- device scratch (static; no runtime allocation) ----------------
__device__ float g_gx[(size_t)2 * M1 * G4];   // precomputed x@Wih^T + bih + bhh, per dir: [T*B][2048]
__device__ float g_scores[(size_t)BB * TT * TT];
__device__ float g_hbuf[2 * 2 * BB * CC];     // [parity][dir][b][c]
__device__ float g_c[2 * BB * CC];            // [dir][b][c]
__device__ float g_rowmax[BB * TT];
__device__ float g_rowinv[BB * TT];
__device__ float g_w[BB * TT];
__device__ float g_pre[BB * HH];

// ---------------- init ----------------
__global__ void k_zero() {
    int i = blockIdx.x * 256 + threadIdx.x;   // 65536 threads
    if (i < 2 * BB * CC) {
        g_hbuf[i] = 0.f;   // parity-0 buffer (both dirs)
        g_c[i]    = 0.f;
    }
}

// ---------------- phase 1: gx[dir][t*B+b][j] = x @ Wih_dir^T + bih + bhh ----------------
// M=32768, N=2048, K=512. BM=BN=128, BK=16, 256 threads, 8x8 microtile.
__global__ void __launch_bounds__(256) k_gatesx(
    const float* __restrict__ x,
    const float* __restrict__ Wf, const float* __restrict__ Wb,
    const float* __restrict__ bif, const float* __restrict__ bhf,
    const float* __restrict__ bib, const float* __restrict__ bhb)
{
    __shared__ __align__(16) float As[16][128];
    __shared__ __align__(16) float Bs[16][128];

    const int dir = blockIdx.z;
    const float* W  = dir ? Wb  : Wf;
    const float* bi = dir ? bib : bif;
    const float* bh = dir ? bhb : bhf;
    float* out = g_gx + (size_t)dir * M1 * G4;

    const int tid = threadIdx.x;
    const int m0 = blockIdx.y * 128;
    const int n0 = blockIdx.x * 128;
    const int lr = tid >> 1;              // 0..127
    const int lk = (tid & 1) << 3;        // 0 or 8
    const float* Ap = x + (size_t)(m0 + lr) * II + lk;
    const float* Bp = W + (size_t)(n0 + lr) * II + lk;
    const int ty = tid >> 4, tx = tid & 15;

    float acc[8][8];
#pragma unroll
    for (int i = 0; i < 8; i++)
#pragma unroll
        for (int j = 0; j < 8; j++) acc[i][j] = 0.f;

    for (int k0 = 0; k0 < II; k0 += 16) {
        float4 a0 = *(const float4*)(Ap + k0);
        float4 a1 = *(const float4*)(Ap + k0 + 4);
        float4 b0 = *(const float4*)(Bp + k0);
        float4 b1 = *(const float4*)(Bp + k0 + 4);
        __syncthreads();
        As[lk+0][lr]=a0.x; As[lk+1][lr]=a0.y; As[lk+2][lr]=a0.z; As[lk+3][lr]=a0.w;
        As[lk+4][lr]=a1.x; As[lk+5][lr]=a1.y; As[lk+6][lr]=a1.z; As[lk+7][lr]=a1.w;
        Bs[lk+0][lr]=b0.x; Bs[lk+1][lr]=b0.y; Bs[lk+2][lr]=b0.z; Bs[lk+3][lr]=b0.w;
        Bs[lk+4][lr]=b1.x; Bs[lk+5][lr]=b1.y; Bs[lk+6][lr]=b1.z; Bs[lk+7][lr]=b1.w;
        __syncthreads();
#pragma unroll
        for (int k = 0; k < 16; k++) {
            float a[8], b[8];
            *(float4*)&a[0] = *(const float4*)&As[k][ty*8];
            *(float4*)&a[4] = *(const float4*)&As[k][ty*8+4];
            *(float4*)&b[0] = *(const float4*)&Bs[k][tx*8];
            *(float4*)&b[4] = *(const float4*)&Bs[k][tx*8+4];
#pragma unroll
            for (int i = 0; i < 8; i++)
#pragma unroll
                for (int j = 0; j < 8; j++)
                    acc[i][j] += a[i] * b[j];
        }
    }

    float bias[8];
#pragma unroll
    for (int j = 0; j < 8; j++) {
        int n = n0 + tx*8 + j;
        bias[j] = bi[n] + bh[n];
    }
#pragma unroll
    for (int i = 0; i < 8; i++) {
        size_t base = (size_t)(m0 + ty*8 + i) * G4 + n0 + tx*8;
#pragma unroll
        for (int j = 0; j < 8; j++)
            out[base + j] = acc[i][j] + bias[j];
    }
}

// ---------------- phase 2: one LSTM timestep, both directions fused ----------------
// 128 blocks: dir = blk>>6, cell group = (blk&63)*8 cells -> 32 gate cols.
// Tile: 64 batches x 32 gate cols, K=512. 256 threads, 4x2 microtile.
__global__ void __launch_bounds__(256) k_step(
    const float* __restrict__ Whhf, const float* __restrict__ Whhb,
    const int* __restrict__ length, float* __restrict__ outp, int step)
{
    __shared__ __align__(16) float hs[16][64];
    __shared__ __align__(16) float ws[16][32];
    __shared__ float gsm[64][33];

    const int tid = threadIdx.x;
    const int dir = blockIdx.x >> 6;
    const int c0  = (blockIdx.x & 63) << 3;
    const int t   = dir ? (TT - 1 - step) : step;
    const int p   = step & 1;
    const float* Whh  = dir ? Whhb : Whhf;
    const float* hin  = g_hbuf + ((size_t)p * 2 + dir) * BB * CC;
    float*       hout = g_hbuf + ((size_t)(p ^ 1) * 2 + dir) * BB * CC;

    const int rg  = tid & 15;   // rows rg*4 .. rg*4+3
    const int cgp = tid >> 4;   // cols cgp*2, cgp*2+1
    float acc[4][2] = {{0.f,0.f},{0.f,0.f},{0.f,0.f},{0.f,0.f}};

    const int lb = tid >> 2;            // batch for h load
    const int lk = (tid & 3) << 2;      // 0,4,8,12
    const int wj = tid >> 2;            // gate col for w load (tid<128)
    const int wG = ((wj >> 3) << 9) + c0 + (wj & 7);   // gate row in Whh

    const float* hp = hin + lb * CC + lk;
    const float* wp = Whh + (size_t)wG * CC + lk;

    for (int k0 = 0; k0 < CC; k0 += 16) {
        float4 hv = *(const float4*)(hp + k0);
        float4 wv = make_float4(0.f,0.f,0.f,0.f);
        if (tid < 128) wv = *(const float4*)(wp + k0);
        __syncthreads();
        hs[lk+0][lb]=hv.x; hs[lk+1][lb]=hv.y; hs[lk+2][lb]=hv.z; hs[lk+3][lb]=hv.w;
        if (tid < 128) {
            ws[lk+0][wj]=wv.x; ws[lk+1][wj]=wv.y; ws[lk+2][wj]=wv.z; ws[lk+3][wj]=wv.w;
        }
        __syncthreads();
#pragma unroll
        for (int k = 0; k < 16; k++) {
            float4 h4 = *(const float4*)&hs[k][rg*4];
            float w0 = ws[k][cgp*2], w1 = ws[k][cgp*2+1];
            acc[0][0] += h4.x*w0;  acc[0][1] += h4.x*w1;
            acc[1][0] += h4.y*w0;  acc[1][1] += h4.y*w1;
            acc[2][0] += h4.z*w0;  acc[2][1] += h4.z*w1;
            acc[3][0] += h4.w*w0;  acc[3][1] += h4.w*w1;
        }
    }

    // add precomputed x-gates, stash to smem for per-cell recombination
#pragma unroll
    for (int i = 0; i < 4; i++) {
        int b = rg*4 + i;
        size_t rowbase = ((size_t)dir * M1 + (size_t)t * BB + b) * G4;
#pragma unroll
        for (int jj = 0; jj < 2; jj++) {
            int j = cgp*2 + jj;
            int G = ((j >> 3) << 9) + c0 + (j & 7);
            gsm[b][j] = acc[i][jj] + g_gx[rowbase + G];
        }
    }
    __syncthreads();

    // activations + masked state update (2 cell-states per thread)
#pragma unroll
    for (int u = 0; u < 2; u++) {
        int idx = tid + (u << 8);          // 0..511
        int b = idx >> 3, cc = idx & 7;
        int cell = c0 + cc;
        float ig = gsm[b][cc];
        float fg = gsm[b][8  + cc];
        float gg = gsm[b][16 + cc];
        float og = gsm[b][24 + cc];
        ig = 1.f / (1.f + expf(-ig));
        fg = 1.f / (1.f + expf(-fg));
        gg = tanhf(gg);
        og = 1.f / (1.f + expf(-og));
        int cidx = (dir * BB + b) * CC + cell;
        float c_old = g_c[cidx];
        float h_old = hin[b * CC + cell];
        float cn = fg * c_old + ig * gg;
        float hn = og * tanhf(cn);
        bool m = (t < length[b]);
        g_c[cidx]             = m ? cn : c_old;
        hout[b * CC + cell]   = m ? hn : h_old;
        outp[(size_t)t * (BB*HH) + b * HH + (dir << 9) + cell] = m ? hn : 0.f;
    }
}

// ---------------- final states ----------------
__global__ void k_final(float* __restrict__ outp) {
    int idx = blockIdx.x * 256 + threadIdx.x;   // 0..65535
    int dir = idx >> 15;
    int r = idx & 32767;
    int b = r >> 9, c = r & 511;
    // final h lives in parity-0 buffer after 512 steps
    outp[OFF_H + b * HH + dir * CC + c] = g_hbuf[((size_t)0 * 2 + dir) * BB * CC + b * CC + c];
    outp[OFF_C + b * HH + dir * CC + c] = g_c[(dir * BB + b) * CC + c];
}

// ---------------- attention scores: scores[b,t,s] = <out[t,b,:], out[s,b,:]> ----------------
// per-batch symmetric GEMM, 64x64 tiles, BK=16, exploit symmetry (ti<=tj, mirror write)
__global__ void __launch_bounds__(256) k_scores(const float* __restrict__ outp) {
    const int tj = blockIdx.x, ti = blockIdx.y, b = blockIdx.z;
    if (ti > tj) return;
    __shared__ __align__(16) float As[16][64];
    __shared__ __align__(16) float Bs[16][64];
    const int tid = threadIdx.x;
    const int rg = tid & 15, cg = tid >> 4;
    const int lr = tid >> 2, lk = (tid & 3) << 2;
    const float* Ap = outp + (size_t)(ti*64 + lr) * (BB*HH) + b * HH + lk;
    const float* Bp = outp + (size_t)(tj*64 + lr) * (BB*HH) + b * HH + lk;
    float acc[4][4];
#pragma unroll
    for (int i = 0; i < 4; i++)
#pragma unroll
        for (int j = 0; j < 4; j++) acc[i][j] = 0.f;

    for (int k0 = 0; k0 < HH; k0 += 16) {
        float4 av = *(const float4*)(Ap + k0);
        float4 bv = *(const float4*)(Bp + k0);
        __syncthreads();
        As[lk+0][lr]=av.x; As[lk+1][lr]=av.y; As[lk+2][lr]=av.z; As[lk+3][lr]=av.w;
        Bs[lk+0][lr]=bv.x; Bs[lk+1][lr]=bv.y; Bs[lk+2][lr]=bv.z; Bs[lk+3][lr]=bv.w;
        __syncthreads();
#pragma unroll
        for (int k = 0; k < 16; k++) {
            float4 a4 = *(const float4*)&As[k][rg*4];
            float4 b4 = *(const float4*)&Bs[k][cg*4];
            acc[0][0]+=a4.x*b4.x; acc[0][1]+=a4.x*b4.y; acc[0][2]+=a4.x*b4.z; acc[0][3]+=a4.x*b4.w;
            acc[1][0]+=a4.y*b4.x; acc[1][1]+=a4.y*b4.y; acc[1][2]+=a4.y*b4.z; acc[1][3]+=a4.y*b4.w;
            acc[2][0]+=a4.z*b4.x; acc[2][1]+=a4.z*b4.y; acc[2][2]+=a4.z*b4.z; acc[2][3]+=a4.z*b4.w;
            acc[3][0]+=a4.w*b4.x; acc[3][1]+=a4.w*b4.y; acc[3][2]+=a4.w*b4.z; acc[3][3]+=a4.w*b4.w;
        }
    }
#pragma unroll
    for (int i = 0; i < 4; i++) {
        int trow = ti*64 + rg*4 + i;
#pragma unroll
        for (int j = 0; j < 4; j++) {
            int scol = tj*64 + cg*4 + j;
            g_scores[((size_t)b * TT + trow) * TT + scol] = acc[i][j];
            if (ti < tj)
                g_scores[((size_t)b * TT + scol) * TT + trow] = acc[i][j];
        }
    }
}

// ---------------- per-row softmax stats (max, 1/sumexp) ----------------
__global__ void k_rowstats() {
    int warp = threadIdx.x >> 5, lane = threadIdx.x & 31;
    int row = blockIdx.x * 8 + warp;           // 0..32767 = b*512+t
    const float* sc = g_scores + (size_t)row * TT;
    float mx = -1e30f;
    for (int s = lane; s < TT; s += 32) mx = fmaxf(mx, sc[s]);
#pragma unroll
    for (int o = 16; o > 0; o >>= 1) mx = fmaxf(mx, __shfl_xor_sync(0xffffffffu, mx, o));
    float sum = 0.f;
    for (int s = lane; s < TT; s += 32) sum += expf(sc[s] - mx);
#pragma unroll
    for (int o = 16; o > 0; o >>= 1) sum += __shfl_xor_sync(0xffffffffu, sum, o);
    if (lane == 0) {
        g_rowmax[row] = mx;
        g_rowinv[row] = 1.f / sum;
    }
}

// ---------------- w[b,s] = sum_t attn[b,t,s] ----------------
__global__ void k_colsum() {
    int s = blockIdx.x * 256 + threadIdx.x;
    int b = blockIdx.y;
    float acc = 0.f;
    const float* sc = g_scores + (size_t)b * TT * TT + s;
    const float* rm = g_rowmax + b * TT;
    const float* ri = g_rowinv + b * TT;
    for (int t = 0; t < TT; t++)
        acc += expf(sc[(size_t)t * TT] - rm[t]) * ri[t];
    g_w[b * TT + s] = acc;
}

// ---------------- pre[b,h] = sum_s w[b,s] * out[s,b,h] ----------------
__global__ void k_ctxpre(const float* __restrict__ outp) {
    int h = blockIdx.x * 256 + threadIdx.x;
    int b = blockIdx.y;
    const float* w = g_w + b * TT;
    float acc = 0.f;
    for (int s = 0; s < TT; s++)
        acc += w[s] * outp[(size_t)s * (BB*HH) + b * HH + h];
    g_pre[b * HH + h] = acc;
}

// ---------------- context[b,n] = pre[b,:] @ Wctx[n,:] + bctx[n] ----------------
__global__ void __launch_bounds__(128) k_ctxgemm(
    const float* __restrict__ Wctx, const float* __restrict__ bctx,
    float* __restrict__ outp)
{
    __shared__ float sp[HH];
    int tid = threadIdx.x;
    int b = blockIdx.y;
    for (int i = tid; i < HH; i += 128) sp[i] = g_pre[b * HH + i];
    __syncthreads();
    int n = blockIdx.x * 128 + tid;
    const float* wr = Wctx + (size_t)n * HH;
    float acc = bctx[n];
    for (int h = 0; h < HH; h += 4) {
        float4 w4 = *(const float4*)(wr + h);
        acc += sp[h]*w4.x + sp[h+1]*w4.y + sp[h+2]*w4.z + sp[h+3]*w4.w;
    }
    outp[OFF_CTX + b * HH + n] = acc;
}

// ---------------- launch ----------------
extern "C" void kernel_launch(void* const* d_in, const int* in_sizes, int n_in,
                              void* d_out, int out_size)
{
    const float* x      = (const float*)d_in[0];
    const int*   length = (const int*)  d_in[1];
    const float* Wih_f  = (const float*)d_in[2];
    const float* Whh_f  = (const float*)d_in[3];
    const float* bih_f  = (const float*)d_in[4];
    const float* bhh_f  = (const float*)d_in[5];
    const float* Wih_b  = (const float*)d_in[6];
    const float* Whh_b  = (const float*)d_in[7];
    const float* bih_b  = (const float*)d_in[8];
    const float* bhh_b  = (const float*)d_in[9];
    const float* Wctx   = (const float*)d_in[10];
    const float* bctx   = (const float*)d_in[11];
    float* out = (float*)d_out;

    k_zero<<<256, 256>>>();
    k_gatesx<<<dim3(16, 256, 2), 256>>>(x, Wih_f, Wih_b, bih_f, bhh_f, bih_b, bhh_b);
    for (int s = 0; s < TT; s++)
        k_step<<<128, 256>>>(Whh_f, Whh_b, length, out, s);
    k_final<<<256, 256>>>(out);
    k_scores<<<dim3(8, 8, 64), 256>>>(out);
    k_rowstats<<<TT * BB / 8, 256>>>();
    k_colsum<<<dim3(2, 64), 256>>>();
    k_ctxpre<<<dim3(4, 64), 256>>>(out);
    k_ctxgemm<<<dim3(8, 64), 128>>>(Wctx, bctx, out);
}

// round 6
// speedup vs baseline: 1.3925x; 1.3773x over previous
#include <cuda_runtime.h>
#include <cuda_bf16.h>
#include <math.h>

// Problem constants
#define TT   512
#define BB   64
#define II   512
#define CC   512            // cell size
#define HH   1024           // output hidden (2*CC)
#define G4   2048           // 4*CC gate rows
#define M1   (TT*BB)        // 32768 rows for input gemm

// d_out layout: output [T,B,H] | final_h [1,B,H] | final_c [1,B,H] | context [B,H]
#define OFF_OUT  0
#define OFF_H    ((size_t)TT*BB*HH)
#define OFF_C    (OFF_H + (size_t)BB*HH)
#define OFF_CTX  (OFF_C + (size_t)BB*HH)

// ---------------- device scratch ----------------
__device__ float    g_gx[(size_t)2 * M1 * G4];     // x@Wih^T + bih + bhh per dir
__device__ float    g_scores[(size_t)BB * TT * TT];
__device__ float    g_hbuf[2 * 2 * BB * CC];       // fp32 h: [parity][dir][b][c]
__device__ unsigned g_htf_hi[2 * 2 * BB * CC];     // tf32 hi split of h
__device__ unsigned g_htf_lo[2 * 2 * BB * CC];     // tf32 lo split of h
__device__ unsigned g_wtf[(size_t)2 * G4 * 2 * CC];// Whh pre-split: [(dir*2048+row)][hi 512 | lo 512]
__device__ float    g_c[2 * BB * CC];
__device__ float    g_rowmax[BB * TT];
__device__ float    g_rowinv[BB * TT];
__device__ float    g_w[BB * TT];
__device__ float    g_pre[BB * HH];

// ---------------- helpers ----------------
__device__ __forceinline__ unsigned f2tf(float f) {
    unsigned r;
    asm("cvt.rna.tf32.f32 %0, %1;" : "=r"(r) : "f"(f));
    return r;
}
__device__ __forceinline__ void split_tf(float v, unsigned& hi, unsigned& lo) {
    hi = f2tf(v);
    lo = f2tf(v - __uint_as_float(hi));
}
__device__ __forceinline__ void mma8(float* d, const unsigned* a, const unsigned* b) {
    asm volatile(
        "mma.sync.aligned.m16n8k8.row.col.f32.tf32.tf32.f32 "
        "{%0,%1,%2,%3},{%4,%5,%6,%7},{%8,%9},{%0,%1,%2,%3};"
        : "+f"(d[0]), "+f"(d[1]), "+f"(d[2]), "+f"(d[3])
        : "r"(a[0]), "r"(a[1]), "r"(a[2]), "r"(a[3]), "r"(b[0]), "r"(b[1]));
}
__device__ __forceinline__ void cp16(void* dst, const void* src) {
    unsigned d = (unsigned)__cvta_generic_to_shared(dst);
    asm volatile("cp.async.cg.shared.global [%0], [%1], 16;" :: "r"(d), "l"(src));
}
#define CP_COMMIT() asm volatile("cp.async.commit_group;" ::: "memory")
#define CP_WAIT0()  asm volatile("cp.async.wait_group 0;" ::: "memory")
#define CP_WAIT1()  asm volatile("cp.async.wait_group 1;" ::: "memory")

// ---------------- init ----------------
__global__ void k_zero() {
    int i = blockIdx.x * 256 + threadIdx.x;   // 65536 threads
    g_hbuf[i] = 0.f;       // parity-0 region (both dirs)
    g_htf_hi[i] = 0u;
    g_htf_lo[i] = 0u;
    g_c[i] = 0.f;          // full c
}

// ---------------- weight prep: gather + tf32 split of Whh into block-local layout ----------------
// row = blkc*64 + j  (j = grp*16 + cc -> global gate G = grp*512 + blkc*16 + cc)
__global__ void k_prep(const float* __restrict__ Whhf, const float* __restrict__ Whhb) {
    const int dir = blockIdx.y;
    const float* W = dir ? Whhb : Whhf;
    int v = blockIdx.x * 256 + threadIdx.x;    // 0..1048575
    int k = v & 511, row = v >> 9;             // row 0..2047
    int blkc = row >> 6, j = row & 63;
    int G = ((j >> 4) << 9) + blkc * 16 + (j & 15);
    float val = W[(size_t)G * CC + k];
    unsigned hi, lo;
    split_tf(val, hi, lo);
    size_t base = ((size_t)dir * G4 + row) * 1024;
    g_wtf[base + k]       = hi;
    g_wtf[base + 512 + k] = lo;
}

// ---------------- phase 1: gx = x @ Wih^T + bih + bhh  (3xTF32 mma) ----------------
// M=32768, N=2048 per dir, K=512. Block tile 128x64, BK=32, 256 threads.
#define GX_SMEM_WORDS ((128 + 128 + 64 + 64) * 36)
#define GX_SMEM_BYTES (GX_SMEM_WORDS * 4)

__global__ void __launch_bounds__(256) k_gatesx3(
    const float* __restrict__ x,
    const float* __restrict__ Wf, const float* __restrict__ Wb,
    const float* __restrict__ bif, const float* __restrict__ bhf,
    const float* __restrict__ bib, const float* __restrict__ bhb)
{
    extern __shared__ unsigned sg[];
    unsigned* Ahi = sg;                 // 128*36
    unsigned* Alo = sg + 4608;
    unsigned* Bhi = sg + 9216;          // 64*36
    unsigned* Blo = sg + 11520;

    const int dir = blockIdx.z;
    const float* W  = dir ? Wb  : Wf;
    const float* bi = dir ? bib : bif;
    const float* bh = dir ? bhb : bhf;
    float* out = g_gx + (size_t)dir * M1 * G4;

    const int m0 = blockIdx.y * 128;
    const int n0 = blockIdx.x * 64;
    const int tid = threadIdx.x;
    const int w = tid >> 5, lane = tid & 31;
    const int mg = w & 3;       // rows mg*32 .. +31
    const int ng = w >> 2;      // cols ng*32 .. +31

    float d[2][4][4];
#pragma unroll
    for (int i = 0; i < 2; i++)
#pragma unroll
        for (int j = 0; j < 4; j++)
#pragma unroll
            for (int r = 0; r < 4; r++) d[i][j][r] = 0.f;

    const unsigned aoff = (mg * 32 + (lane >> 2)) * 36 + (lane & 3);
    const unsigned boff = (ng * 32 + (lane >> 2)) * 36 + (lane & 3);

    for (int kc = 0; kc < 16; kc++) {
        const int k0 = kc * 32;
        float4 av[4], bv[2];
#pragma unroll
        for (int it = 0; it < 4; it++) {
            int v = it * 256 + tid, r = v >> 3, kq = v & 7;
            av[it] = *(const float4*)(x + (size_t)(m0 + r) * II + k0 + kq * 4);
        }
#pragma unroll
        for (int it = 0; it < 2; it++) {
            int v = it * 256 + tid, r = v >> 3, kq = v & 7;
            bv[it] = *(const float4*)(W + (size_t)(n0 + r) * II + k0 + kq * 4);
        }
        __syncthreads();
#pragma unroll
        for (int it = 0; it < 4; it++) {
            int v = it * 256 + tid, r = v >> 3, kq = v & 7;
            unsigned* dh = Ahi + r * 36 + kq * 4;
            unsigned* dl = Alo + r * 36 + kq * 4;
            split_tf(av[it].x, dh[0], dl[0]); split_tf(av[it].y, dh[1], dl[1]);
            split_tf(av[it].z, dh[2], dl[2]); split_tf(av[it].w, dh[3], dl[3]);
        }
#pragma unroll
        for (int it = 0; it < 2; it++) {
            int v = it * 256 + tid, r = v >> 3, kq = v & 7;
            unsigned* dh = Bhi + r * 36 + kq * 4;
            unsigned* dl = Blo + r * 36 + kq * 4;
            split_tf(bv[it].x, dh[0], dl[0]); split_tf(bv[it].y, dh[1], dl[1]);
            split_tf(bv[it].z, dh[2], dl[2]); split_tf(bv[it].w, dh[3], dl[3]);
        }
        __syncthreads();
        unsigned* ah = Ahi + aoff;  unsigned* al = Alo + aoff;
        unsigned* bhp = Bhi + boff; unsigned* blp = Blo + boff;
#pragma unroll
        for (int kt = 0; kt < 4; kt++) {
            unsigned ahi[2][4], alo[2][4];
            ahi[0][0] = ah[0];            ahi[0][1] = ah[8 * 36];
            ahi[0][2] = ah[4];            ahi[0][3] = ah[8 * 36 + 4];
            ahi[1][0] = ah[16 * 36];      ahi[1][1] = ah[24 * 36];
            ahi[1][2] = ah[16 * 36 + 4];  ahi[1][3] = ah[24 * 36 + 4];
            alo[0][0] = al[0];            alo[0][1] = al[8 * 36];
            alo[0][2] = al[4];            alo[0][3] = al[8 * 36 + 4];
            alo[1][0] = al[16 * 36];      alo[1][1] = al[24 * 36];
            alo[1][2] = al[16 * 36 + 4];  alo[1][3] = al[24 * 36 + 4];
#pragma unroll
            for (int j = 0; j < 4; j++) {
                unsigned bhi2[2], blo2[2];
                bhi2[0] = bhp[j * 8 * 36];     bhi2[1] = bhp[j * 8 * 36 + 4];
                blo2[0] = blp[j * 8 * 36];     blo2[1] = blp[j * 8 * 36 + 4];
#pragma unroll
                for (int i = 0; i < 2; i++) {
                    mma8(d[i][j], alo[i], bhi2);
                    mma8(d[i][j], ahi[i], blo2);
                    mma8(d[i][j], ahi[i], bhi2);
                }
            }
            ah += 8; al += 8; bhp += 8; blp += 8;
        }
    }

    // epilogue: add bias, store
#pragma unroll
    for (int i = 0; i < 2; i++) {
        int rb = m0 + mg * 32 + i * 16 + (lane >> 2);
#pragma unroll
        for (int j = 0; j < 4; j++) {
            int cb = n0 + ng * 32 + j * 8 + 2 * (lane & 3);
            float bs0 = bi[cb] + bh[cb];
            float bs1 = bi[cb + 1] + bh[cb + 1];
            out[(size_t)rb * G4 + cb]           = d[i][j][0] + bs0;
            out[(size_t)rb * G4 + cb + 1]       = d[i][j][1] + bs1;
            out[(size_t)(rb + 8) * G4 + cb]     = d[i][j][2] + bs0;
            out[(size_t)(rb + 8) * G4 + cb + 1] = d[i][j][3] + bs1;
        }
    }
}

// ---------------- phase 2: one LSTM timestep (3xTF32 mma, cp.async double-buffer) ----------------
// grid 64: dir = blk>>5, 16 cells (=64 gate cols) per block. Tile C[64 batch, 64 gates], K=512.
#define SSTR 68                       // 68 % 32 == 4 -> conflict-free frag LDS; 272B rows (16B-aligned)
#define ABUF 4352                     // 64*SSTR
#define STEP_SMEM_WORDS (8 * ABUF + 64 * 65)
#define STEP_SMEM_BYTES (STEP_SMEM_WORDS * 4)

__global__ void __launch_bounds__(256, 1) k_step3(
    const int* __restrict__ length, float* __restrict__ outp, int step)
{
    extern __shared__ unsigned sm[];
    unsigned* Ah = sm;                 // [2][64*SSTR]
    unsigned* Al = sm + 2 * ABUF;
    unsigned* Bh = sm + 4 * ABUF;
    unsigned* Bl = sm + 6 * ABUF;
    float*   gsm = (float*)(sm + 8 * ABUF);   // [64][65]

    const int tid = threadIdx.x, w = tid >> 5, lane = tid & 31;
    const int dir  = blockIdx.x >> 5;
    const int blkc = blockIdx.x & 31;
    const int c0   = blkc << 4;
    const int t    = dir ? (TT - 1 - step) : step;
    const int p    = step & 1;
    const size_t hin_off  = (size_t)(p * 2 + dir) * BB * CC;
    const size_t hout_off = (size_t)((p ^ 1) * 2 + dir) * BB * CC;
    const unsigned* hhi = g_htf_hi + hin_off;
    const unsigned* hlo = g_htf_lo + hin_off;
    const unsigned* Wrow = g_wtf + ((size_t)dir * G4 + blkc * 64) * 1024;

    // preload gsm with precomputed x-gates (fp32)
    {
        const float* gx = g_gx + ((size_t)dir * M1 + (size_t)t * BB) * G4;
#pragma unroll
        for (int u = 0; u < 16; u++) {
            int v = u * 256 + tid;       // 0..4095
            int b = v >> 6, j = v & 63;
            int G = ((j >> 4) << 9) + c0 + (j & 15);
            gsm[b * 65 + j] = gx[(size_t)b * G4 + G];
        }
    }

    auto stage = [&](int c, int buf) {
        const int k0 = c * 64;
#pragma unroll
        for (int it = 0; it < 4; it++) {
            int v = it * 256 + tid;
            int row = v >> 4, q = v & 15;
            unsigned doff = buf * ABUF + row * SSTR + q * 4;
            cp16(Ah + doff, hhi + row * CC + k0 + q * 4);
            cp16(Al + doff, hlo + row * CC + k0 + q * 4);
            cp16(Bh + doff, Wrow + (size_t)row * 1024 + k0 + q * 4);
            cp16(Bl + doff, Wrow + (size_t)row * 1024 + 512 + k0 + q * 4);
        }
    };

    const int mw = w & 1, nw = w >> 1;
    const unsigned aoff = (mw * 32 + (lane >> 2)) * SSTR + (lane & 3);
    const unsigned boff = (nw * 16 + (lane >> 2)) * SSTR + (lane & 3);

    float d[2][2][4];
#pragma unroll
    for (int i = 0; i < 2; i++)
#pragma unroll
        for (int j = 0; j < 2; j++)
#pragma unroll
            for (int r = 0; r < 4; r++) d[i][j][r] = 0.f;

    stage(0, 0);
    CP_COMMIT();

    for (int c = 0; c < 8; c++) {
        if (c < 7) { stage(c + 1, (c + 1) & 1); CP_COMMIT(); CP_WAIT1(); }
        else       { CP_WAIT0(); }
        __syncthreads();
        const int buf = c & 1;
        unsigned* ah = Ah + buf * ABUF + aoff;
        unsigned* al = Al + buf * ABUF + aoff;
        unsigned* bhp = Bh + buf * ABUF + boff;
        unsigned* blp = Bl + buf * ABUF + boff;
#pragma unroll
        for (int kt = 0; kt < 8; kt++) {
            unsigned ahi[2][4], alo[2][4], bhi2[2][2], blo2[2][2];
            ahi[0][0] = ah[0];              ahi[0][1] = ah[8 * SSTR];
            ahi[0][2] = ah[4];              ahi[0][3] = ah[8 * SSTR + 4];
            ahi[1][0] = ah[16 * SSTR];      ahi[1][1] = ah[24 * SSTR];
            ahi[1][2] = ah[16 * SSTR + 4];  ahi[1][3] = ah[24 * SSTR + 4];
            alo[0][0] = al[0];              alo[0][1] = al[8 * SSTR];
            alo[0][2] = al[4];              alo[0][3] = al[8 * SSTR + 4];
            alo[1][0] = al[16 * SSTR];      alo[1][1] = al[24 * SSTR];
            alo[1][2] = al[16 * SSTR + 4];  alo[1][3] = al[24 * SSTR + 4];
            bhi2[0][0] = bhp[0];            bhi2[0][1] = bhp[4];
            bhi2[1][0] = bhp[8 * SSTR];     bhi2[1][1] = bhp[8 * SSTR + 4];
            blo2[0][0] = blp[0];            blo2[0][1] = blp[4];
            blo2[1][0] = blp[8 * SSTR];     blo2[1][1] = blp[8 * SSTR + 4];
#pragma unroll
            for (int i = 0; i < 2; i++)
#pragma unroll
                for (int j = 0; j < 2; j++) {
                    mma8(d[i][j], alo[i], bhi2[j]);
                    mma8(d[i][j], ahi[i], blo2[j]);
                    mma8(d[i][j], ahi[i], bhi2[j]);
                }
            ah += 8; al += 8; bhp += 8; blp += 8;
        }
        __syncthreads();
    }

    // epilogue: accumulate into gsm (gx preloaded)
    {
        const int gr = lane >> 2, q2 = 2 * (lane & 3);
#pragma unroll
        for (int i = 0; i < 2; i++)
#pragma unroll
            for (int j = 0; j < 2; j++) {
                int rb = mw * 32 + i * 16 + gr;
                int cb = nw * 16 + j * 8 + q2;
                gsm[rb * 65 + cb]           += d[i][j][0];
                gsm[rb * 65 + cb + 1]       += d[i][j][1];
                gsm[(rb + 8) * 65 + cb]     += d[i][j][2];
                gsm[(rb + 8) * 65 + cb + 1] += d[i][j][3];
            }
    }
    __syncthreads();

    // activations + masked state update: 64 b x 16 cells, 4 per thread
    const float* hb_in  = g_hbuf + hin_off;
    float*       hb_out = g_hbuf + hout_off;
    unsigned*    hh_out = g_htf_hi + hout_off;
    unsigned*    hl_out = g_htf_lo + hout_off;
#pragma unroll
    for (int u = 0; u < 4; u++) {
        int idx = u * 256 + tid;          // 0..1023
        int b = idx >> 4, cc = idx & 15;
        float ig = gsm[b * 65 + cc];
        float fg = gsm[b * 65 + 16 + cc];
        float gg = gsm[b * 65 + 32 + cc];
        float og = gsm[b * 65 + 48 + cc];
        ig = 1.f / (1.f + expf(-ig));
        fg = 1.f / (1.f + expf(-fg));
        gg = tanhf(gg);
        og = 1.f / (1.f + expf(-og));
        int cell = c0 + cc;
        int ci = (dir * BB + b) * CC + cell;
        float c_old = g_c[ci];
        float h_old = hb_in[b * CC + cell];
        float cn = fg * c_old + ig * gg;
        float hn = og * tanhf(cn);
        bool m = (t < length[b]);
        float hf = m ? hn : h_old;
        g_c[ci] = m ? cn : c_old;
        hb_out[b * CC + cell] = hf;
        unsigned hi, lo;
        split_tf(hf, hi, lo);
        hh_out[b * CC + cell] = hi;
        hl_out[b * CC + cell] = lo;
        outp[(size_t)t * (BB * HH) + b * HH + (dir << 9) + cell] = m ? hn : 0.f;
    }
}

// ---------------- final states ----------------
__global__ void k_final(float* __restrict__ outp) {
    int idx = blockIdx.x * 256 + threadIdx.x;   // 0..65535
    int dir = idx >> 15;
    int r = idx & 32767;
    int b = r >> 9, c = r & 511;
    outp[OFF_H + b * HH + dir * CC + c] = g_hbuf[(size_t)dir * BB * CC + b * CC + c];
    outp[OFF_C + b * HH + dir * CC + c] = g_c[(dir * BB + b) * CC + c];
}

// ---------------- attention scores (fp32, symmetric) ----------------
__global__ void __launch_bounds__(256) k_scores(const float* __restrict__ outp) {
    const int tj = blockIdx.x, ti = blockIdx.y, b = blockIdx.z;
    if (ti > tj) return;
    __shared__ __align__(16) float As[16][64];
    __shared__ __align__(16) float Bs[16][64];
    const int tid = threadIdx.x;
    const int rg = tid & 15, cg = tid >> 4;
    const int lr = tid >> 2, lk = (tid & 3) << 2;
    const float* Ap = outp + (size_t)(ti * 64 + lr) * (BB * HH) + b * HH + lk;
    const float* Bp = outp + (size_t)(tj * 64 + lr) * (BB * HH) + b * HH + lk;
    float acc[4][4];
#pragma unroll
    for (int i = 0; i < 4; i++)
#pragma unroll
        for (int j = 0; j < 4; j++) acc[i][j] = 0.f;

    for (int k0 = 0; k0 < HH; k0 += 16) {
        float4 av = *(const float4*)(Ap + k0);
        float4 bv = *(const float4*)(Bp + k0);
        __syncthreads();
        As[lk + 0][lr] = av.x; As[lk + 1][lr] = av.y; As[lk + 2][lr] = av.z; As[lk + 3][lr] = av.w;
        Bs[lk + 0][lr] = bv.x; Bs[lk + 1][lr] = bv.y; Bs[lk + 2][lr] = bv.z; Bs[lk + 3][lr] = bv.w;
        __syncthreads();
#pragma unroll
        for (int k = 0; k < 16; k++) {
            float4 a4 = *(const float4*)&As[k][rg * 4];
            float4 b4 = *(const float4*)&Bs[k][cg * 4];
            acc[0][0] += a4.x * b4.x; acc[0][1] += a4.x * b4.y; acc[0][2] += a4.x * b4.z; acc[0][3] += a4.x * b4.w;
            acc[1][0] += a4.y * b4.x; acc[1][1] += a4.y * b4.y; acc[1][2] += a4.y * b4.z; acc[1][3] += a4.y * b4.w;
            acc[2][0] += a4.z * b4.x; acc[2][1] += a4.z * b4.y; acc[2][2] += a4.z * b4.z; acc[2][3] += a4.z * b4.w;
            acc[3][0] += a4.w * b4.x; acc[3][1] += a4.w * b4.y; acc[3][2] += a4.w * b4.z; acc[3][3] += a4.w * b4.w;
        }
    }
#pragma unroll
    for (int i = 0; i < 4; i++) {
        int trow = ti * 64 + rg * 4 + i;
#pragma unroll
        for (int j = 0; j < 4; j++) {
            int scol = tj * 64 + cg * 4 + j;
            g_scores[((size_t)b * TT + trow) * TT + scol] = acc[i][j];
            if (ti < tj)
                g_scores[((size_t)b * TT + scol) * TT + trow] = acc[i][j];
        }
    }
}

// ---------------- per-row softmax stats ----------------
__global__ void k_rowstats() {
    int warp = threadIdx.x >> 5, lane = threadIdx.x & 31;
    int row = blockIdx.x * 8 + warp;
    const float* sc = g_scores + (size_t)row * TT;
    float mx = -1e30f;
    for (int s = lane; s < TT; s += 32) mx = fmaxf(mx, sc[s]);
#pragma unroll
    for (int o = 16; o > 0; o >>= 1) mx = fmaxf(mx, __shfl_xor_sync(0xffffffffu, mx, o));
    float sum = 0.f;
    for (int s = lane; s < TT; s += 32) sum += expf(sc[s] - mx);
#pragma unroll
    for (int o = 16; o > 0; o >>= 1) sum += __shfl_xor_sync(0xffffffffu, sum, o);
    if (lane == 0) {
        g_rowmax[row] = mx;
        g_rowinv[row] = 1.f / sum;
    }
}

// ---------------- w[b,s] = sum_t attn[b,t,s] ----------------
__global__ void k_colsum() {
    int s = blockIdx.x * 256 + threadIdx.x;
    int b = blockIdx.y;
    float acc = 0.f;
    const float* sc = g_scores + (size_t)b * TT * TT + s;
    const float* rm = g_rowmax + b * TT;
    const float* ri = g_rowinv + b * TT;
    for (int t = 0; t < TT; t++)
        acc += expf(sc[(size_t)t * TT] - rm[t]) * ri[t];
    g_w[b * TT + s] = acc;
}

// ---------------- pre[b,h] = sum_s w[b,s] * out[s,b,h] ----------------
__global__ void k_ctxpre(const float* __restrict__ outp) {
    int h = blockIdx.x * 256 + threadIdx.x;
    int b = blockIdx.y;
    const float* w = g_w + b * TT;
    float acc = 0.f;
    for (int s = 0; s < TT; s++)
        acc += w[s] * outp[(size_t)s * (BB * HH) + b * HH + h];
    g_pre[b * HH + h] = acc;
}

// ---------------- context projection ----------------
__global__ void __launch_bounds__(128) k_ctxgemm(
    const float* __restrict__ Wctx, const float* __restrict__ bctx,
    float* __restrict__ outp)
{
    __shared__ float sp[HH];
    int tid = threadIdx.x;
    int b = blockIdx.y;
    for (int i = tid; i < HH; i += 128) sp[i] = g_pre[b * HH + i];
    __syncthreads();
    int n = blockIdx.x * 128 + tid;
    const float* wr = Wctx + (size_t)n * HH;
    float acc = bctx[n];
    for (int h = 0; h < HH; h += 4) {
        float4 w4 = *(const float4*)(wr + h);
        acc += sp[h] * w4.x + sp[h + 1] * w4.y + sp[h + 2] * w4.z + sp[h + 3] * w4.w;
    }
    outp[OFF_CTX + b * HH + n] = acc;
}

// ---------------- launch ----------------
extern "C" void kernel_launch(void* const* d_in, const int* in_sizes, int n_in,
                              void* d_out, int out_size)
{
    const float* x      = (const float*)d_in[0];
    const int*   length = (const int*)  d_in[1];
    const float* Wih_f  = (const float*)d_in[2];
    const float* Whh_f  = (const float*)d_in[3];
    const float* bih_f  = (const float*)d_in[4];
    const float* bhh_f  = (const float*)d_in[5];
    const float* Wih_b  = (const float*)d_in[6];
    const float* Whh_b  = (const float*)d_in[7];
    const float* bih_b  = (const float*)d_in[8];
    const float* bhh_b  = (const float*)d_in[9];
    const float* Wctx   = (const float*)d_in[10];
    const float* bctx   = (const float*)d_in[11];
    float* out = (float*)d_out;

    cudaFuncSetAttribute(k_gatesx3, cudaFuncAttributeMaxDynamicSharedMemorySize, GX_SMEM_BYTES);
    cudaFuncSetAttribute(k_step3,   cudaFuncAttributeMaxDynamicSharedMemorySize, STEP_SMEM_BYTES);

    k_zero<<<256, 256>>>();
    k_prep<<<dim3(4096, 2), 256>>>(Whh_f, Whh_b);
    k_gatesx3<<<dim3(32, 256, 2), 256, GX_SMEM_BYTES>>>(x, Wih_f, Wih_b, bih_f, bhh_f, bih_b, bhh_b);
    for (int s = 0; s < TT; s++)
        k_step3<<<64, 256, STEP_SMEM_BYTES>>>(length, out, s);
    k_final<<<256, 256>>>(out);
    k_scores<<<dim3(8, 8, 64), 256>>>(out);
    k_rowstats<<<TT * BB / 8, 256>>>();
    k_colsum<<<dim3(2, 64), 256>>>();
    k_ctxpre<<<dim3(4, 64), 256>>>(out);
    k_ctxgemm<<<dim3(8, 64), 128>>>(Wctx, bctx, out);
}

// round 8
// speedup vs baseline: 1.4456x; 1.0382x over previous
#include <cuda_runtime.h>
#include <cuda_bf16.h>
#include <math.h>

// Problem constants
#define TT   512
#define BB   64
#define II   512
#define CC   512            // cell size
#define HH   1024           // output hidden (2*CC)
#define G4   2048           // 4*CC gate rows
#define M1   (TT*BB)        // 32768 rows for input gemm

// d_out layout: output [T,B,H] | final_h [1,B,H] | final_c [1,B,H] | context [B,H]
#define OFF_OUT  0
#define OFF_H    ((size_t)TT*BB*HH)
#define OFF_C    (OFF_H + (size_t)BB*HH)
#define OFF_CTX  (OFF_C + (size_t)BB*HH)

// ---------------- device scratch ----------------
__device__ float    g_gx[(size_t)2 * M1 * G4];       // x@Wih^T + bih + bhh per dir
__device__ float    g_scores[(size_t)BB * TT * TT];
__device__ float    g_hbuf[2 * 2 * BB * CC];         // fp32 h (for k_final): [parity][dir][b][c]
// h in mma-fragment-major tf32-split form: [parity*2+dir][kt 0..63][mi 0..3][lane 0..31][hi0..3, lo0..3]
__device__ unsigned g_hfrag[(size_t)4 * 64 * 4 * 32 * 8];
// Whh fragment-major per step-block: [blk 0..63][kt 0..63][jn 0..7][lane 0..31][bh0,bh1,bl0,bl1]
__device__ unsigned g_wtf[(size_t)64 * 64 * 8 * 32 * 4];
__device__ float    g_c[2 * BB * CC];                // [dir][b][c]
__device__ float    g_rowmax[BB * TT];
__device__ float    g_rowinv[BB * TT];
__device__ float    g_w[BB * TT];
__device__ float    g_pre[BB * HH];

// ---------------- helpers ----------------
__device__ __forceinline__ unsigned f2tf(float f) {
    unsigned r;
    asm("cvt.rna.tf32.f32 %0, %1;" : "=r"(r) : "f"(f));
    return r;
}
__device__ __forceinline__ void split_tf(float v, unsigned& hi, unsigned& lo) {
    hi = f2tf(v);
    lo = f2tf(v - __uint_as_float(hi));
}
__device__ __forceinline__ void mma8(float* d, const unsigned* a, const unsigned* b) {
    asm volatile(
        "mma.sync.aligned.m16n8k8.row.col.f32.tf32.tf32.f32 "
        "{%0,%1,%2,%3},{%4,%5,%6,%7},{%8,%9},{%0,%1,%2,%3};"
        : "+f"(d[0]), "+f"(d[1]), "+f"(d[2]), "+f"(d[3])
        : "r"(a[0]), "r"(a[1]), "r"(a[2]), "r"(a[3]), "r"(b[0]), "r"(b[1]));
}
__device__ __forceinline__ void cp16(void* dst, const void* src) {
    unsigned d = (unsigned)__cvta_generic_to_shared(dst);
    asm volatile("cp.async.cg.shared.global [%0], [%1], 16;" :: "r"(d), "l"(src));
}
#define CP_COMMIT() asm volatile("cp.async.commit_group;" ::: "memory")
#define CP_WAIT0()  asm volatile("cp.async.wait_group 0;" ::: "memory")
#define CP_WAIT1()  asm volatile("cp.async.wait_group 1;" ::: "memory")
#define CP_WAIT2()  asm volatile("cp.async.wait_group 2;" ::: "memory")

// ---------------- init ----------------
__global__ void k_zero() {
    int i = blockIdx.x * 256 + threadIdx.x;   // 131072 threads
    g_hfrag[i] = 0u;                          // parity-0 region (both dirs) = first 131072 words
    if (i < 2 * BB * CC) {
        g_hbuf[i] = 0.f;                      // parity-0 fp32 h
        g_c[i]    = 0.f;
    }
}

// ---------------- weight prep: Whh -> fragment-major tf32 split ----------------
// step block blk (0..63): dir = blk>>5, blkc = blk&31, cells c0=blkc*16, gate cols j 0..63
// G = (j>>4)*512 + blkc*16 + (j&15)
__global__ void k_prep(const float* __restrict__ Whhf, const float* __restrict__ Whhb) {
    int v = blockIdx.x * 256 + threadIdx.x;    // 0..2097151
    int k = v & 511;
    int rj = v >> 9;
    int j = rj & 63;
    int blk = rj >> 6;                         // 0..63
    int dir = blk >> 5, blkc = blk & 31;
    const float* W = dir ? Whhb : Whhf;
    int G = ((j >> 4) << 9) + blkc * 16 + (j & 15);
    float val = W[(size_t)G * CC + k];
    unsigned hi, lo;
    split_tf(val, hi, lo);
    int kt = k >> 3, kk = k & 7;
    int jn = j >> 3;
    int lane = ((j & 7) << 2) + (kk & 3);
    int rh = kk >> 2;                          // 0 or 1
    size_t addr = ((size_t)blk * 65536) + kt * 1024 + jn * 128 + lane * 4;
    g_wtf[addr + rh]     = hi;                 // bh0/bh1
    g_wtf[addr + 2 + rh] = lo;                 // bl0/bl1
}

// ---------------- phase 1: gx = x @ Wih^T + bih + bhh  (3xTF32 mma) — unchanged from R6 ----------------
#define GX_SMEM_WORDS ((128 + 128 + 64 + 64) * 36)
#define GX_SMEM_BYTES (GX_SMEM_WORDS * 4)

__global__ void __launch_bounds__(256) k_gatesx3(
    const float* __restrict__ x,
    const float* __restrict__ Wf, const float* __restrict__ Wb,
    const float* __restrict__ bif, const float* __restrict__ bhf,
    const float* __restrict__ bib, const float* __restrict__ bhb)
{
    extern __shared__ unsigned sg[];
    unsigned* Ahi = sg;
    unsigned* Alo = sg + 4608;
    unsigned* Bhi = sg + 9216;
    unsigned* Blo = sg + 11520;

    const int dir = blockIdx.z;
    const float* W  = dir ? Wb  : Wf;
    const float* bi = dir ? bib : bif;
    const float* bh = dir ? bhb : bhf;
    float* out = g_gx + (size_t)dir * M1 * G4;

    const int m0 = blockIdx.y * 128;
    const int n0 = blockIdx.x * 64;
    const int tid = threadIdx.x;
    const int w = tid >> 5, lane = tid & 31;
    const int mg = w & 3;
    const int ng = w >> 2;

    float d[2][4][4];
#pragma unroll
    for (int i = 0; i < 2; i++)
#pragma unroll
        for (int j = 0; j < 4; j++)
#pragma unroll
            for (int r = 0; r < 4; r++) d[i][j][r] = 0.f;

    const unsigned aoff = (mg * 32 + (lane >> 2)) * 36 + (lane & 3);
    const unsigned boff = (ng * 32 + (lane >> 2)) * 36 + (lane & 3);

    for (int kc = 0; kc < 16; kc++) {
        const int k0 = kc * 32;
        float4 av[4], bv[2];
#pragma unroll
        for (int it = 0; it < 4; it++) {
            int v = it * 256 + tid, r = v >> 3, kq = v & 7;
            av[it] = *(const float4*)(x + (size_t)(m0 + r) * II + k0 + kq * 4);
        }
#pragma unroll
        for (int it = 0; it < 2; it++) {
            int v = it * 256 + tid, r = v >> 3, kq = v & 7;
            bv[it] = *(const float4*)(W + (size_t)(n0 + r) * II + k0 + kq * 4);
        }
        __syncthreads();
#pragma unroll
        for (int it = 0; it < 4; it++) {
            int v = it * 256 + tid, r = v >> 3, kq = v & 7;
            unsigned* dh = Ahi + r * 36 + kq * 4;
            unsigned* dl = Alo + r * 36 + kq * 4;
            split_tf(av[it].x, dh[0], dl[0]); split_tf(av[it].y, dh[1], dl[1]);
            split_tf(av[it].z, dh[2], dl[2]); split_tf(av[it].w, dh[3], dl[3]);
        }
#pragma unroll
        for (int it = 0; it < 2; it++) {
            int v = it * 256 + tid, r = v >> 3, kq = v & 7;
            unsigned* dh = Bhi + r * 36 + kq * 4;
            unsigned* dl = Blo + r * 36 + kq * 4;
            split_tf(bv[it].x, dh[0], dl[0]); split_tf(bv[it].y, dh[1], dl[1]);
            split_tf(bv[it].z, dh[2], dl[2]); split_tf(bv[it].w, dh[3], dl[3]);
        }
        __syncthreads();
        unsigned* ah = Ahi + aoff;  unsigned* al = Alo + aoff;
        unsigned* bhp = Bhi + boff; unsigned* blp = Blo + boff;
#pragma unroll
        for (int kt = 0; kt < 4; kt++) {
            unsigned ahi[2][4], alo[2][4];
            ahi[0][0] = ah[0];            ahi[0][1] = ah[8 * 36];
            ahi[0][2] = ah[4];            ahi[0][3] = ah[8 * 36 + 4];
            ahi[1][0] = ah[16 * 36];      ahi[1][1] = ah[24 * 36];
            ahi[1][2] = ah[16 * 36 + 4];  ahi[1][3] = ah[24 * 36 + 4];
            alo[0][0] = al[0];            alo[0][1] = al[8 * 36];
            alo[0][2] = al[4];            alo[0][3] = al[8 * 36 + 4];
            alo[1][0] = al[16 * 36];      alo[1][1] = al[24 * 36];
            alo[1][2] = al[16 * 36 + 4];  alo[1][3] = al[24 * 36 + 4];
#pragma unroll
            for (int j = 0; j < 4; j++) {
                unsigned bhi2[2], blo2[2];
                bhi2[0] = bhp[j * 8 * 36];     bhi2[1] = bhp[j * 8 * 36 + 4];
                blo2[0] = blp[j * 8 * 36];     blo2[1] = blp[j * 8 * 36 + 4];
#pragma unroll
                for (int i = 0; i < 2; i++) {
                    mma8(d[i][j], alo[i], bhi2);
                    mma8(d[i][j], ahi[i], blo2);
                    mma8(d[i][j], ahi[i], bhi2);
                }
            }
            ah += 8; al += 8; bhp += 8; blp += 8;
        }
    }

#pragma unroll
    for (int i = 0; i < 2; i++) {
        int rb = m0 + mg * 32 + i * 16 + (lane >> 2);
#pragma unroll
        for (int j = 0; j < 4; j++) {
            int cb = n0 + ng * 32 + j * 8 + 2 * (lane & 3);
            float bs0 = bi[cb] + bh[cb];
            float bs1 = bi[cb + 1] + bh[cb + 1];
            out[(size_t)rb * G4 + cb]           = d[i][j][0] + bs0;
            out[(size_t)rb * G4 + cb + 1]       = d[i][j][1] + bs1;
            out[(size_t)(rb + 8) * G4 + cb]     = d[i][j][2] + bs0;
            out[(size_t)(rb + 8) * G4 + cb + 1] = d[i][j][3] + bs1;
        }
    }
}

// ---------------- phase 2: one LSTM timestep — fragment-major, 512 threads, depth-3 cp.async ----------------
// grid 64: dir = blk>>5, blkc = blk&31, 16 cells (=64 gate cols). Tile C[64 batch, 64 gates], K=512.
// 16 warps: kh = w>>3 (K half), mw = w&1 (32 rows), nw = (w>>1)&3 (16 cols).
// smem: 3 chunk buffers of 16384 words (h 8192 | W 8192), then gsm f32[64][65].
#define CH_WORDS 16384
#define GSM_OFF  (3 * CH_WORDS)                 // 49152
#define STEP_SMEM_WORDS (GSM_OFF + 64 * 65)     // 53312
#define STEP_SMEM_BYTES (STEP_SMEM_WORDS * 4)   // 213248

__global__ void __launch_bounds__(512, 1) k_step2(
    const int* __restrict__ length, float* __restrict__ outp, int step)
{
    extern __shared__ unsigned sm[];
    float* gsm = (float*)(sm + GSM_OFF);

    const int tid = threadIdx.x, w = tid >> 5, lane = tid & 31;
    const int dir  = blockIdx.x >> 5;
    const int blkc = blockIdx.x & 31;
    const int c0   = blkc << 4;
    const int t    = dir ? (TT - 1 - step) : step;
    const int p    = step & 1;
    const int pd_in  = p * 2 + dir;
    const int pd_out = (p ^ 1) * 2 + dir;
    const unsigned* hsrc = g_hfrag + (size_t)pd_in * 65536;
    const unsigned* wsrc = g_wtf + (size_t)blockIdx.x * 65536;

    // stage chunk c (0..7) into buffer buf: both K halves, h then W, 4096 cp16
    auto stage = [&](int c, int buf) {
        unsigned* hb = sm + buf * CH_WORDS;
        unsigned* wb = hb + 8192;
#pragma unroll
        for (int it = 0; it < 8; it++) {
            int v = it * 512 + tid;              // 0..4095
            int arr = v >> 11;                   // 0 = h, 1 = W
            int rem = v & 2047;
            int eta = rem >> 10;                 // k half
            int q   = rem & 1023;                // cp16 index within 4096-word region
            unsigned off = eta * 4096 + q * 4;
            unsigned gsrc = (eta * 32 + c * 4) * 1024 + q * 4;
            if (arr == 0) cp16(hb + off, hsrc + gsrc);
            else          cp16(wb + off, wsrc + gsrc);
        }
    };

    stage(0, 0); CP_COMMIT();
    stage(1, 1); CP_COMMIT();

    // preload gsm with precomputed x-gates (overlaps with cp.async)
    {
        const float* gx = g_gx + ((size_t)dir * M1 + (size_t)t * BB) * G4;
#pragma unroll
        for (int u = 0; u < 8; u++) {
            int v = u * 512 + tid;               // 0..4095
            int b = v >> 6, j = v & 63;
            int G = ((j >> 4) << 9) + c0 + (j & 15);
            gsm[b * 65 + j] = gx[(size_t)b * G4 + G];
        }
    }

    const int kh = w >> 3;
    const int mw = w & 1;
    const int nw = (w >> 1) & 3;

    float d[2][2][4];
#pragma unroll
    for (int i = 0; i < 2; i++)
#pragma unroll
        for (int j = 0; j < 2; j++)
#pragma unroll
            for (int r = 0; r < 4; r++) d[i][j][r] = 0.f;

    for (int c = 0; c < 8; c++) {
        if (c < 6)      { stage(c + 2, (c + 2) % 3); CP_COMMIT(); CP_WAIT2(); }
        else if (c == 6){ CP_WAIT1(); }
        else            { CP_WAIT0(); }
        __syncthreads();
        const unsigned* hb = sm + (c % 3) * CH_WORDS + kh * 4096;
        const unsigned* wb = sm + (c % 3) * CH_WORDS + 8192 + kh * 4096;
#pragma unroll
        for (int ktl = 0; ktl < 4; ktl++) {
            // A fragments: 2 m16 tiles (mi = mw*2 + im), hi quad + lo quad each
            unsigned ahi[2][4], alo[2][4];
#pragma unroll
            for (int im = 0; im < 2; im++) {
                const unsigned* ap = hb + (ktl * 4 + (mw * 2 + im)) * 256 + lane * 8;
                uint4 h4 = *(const uint4*)(ap);
                uint4 l4 = *(const uint4*)(ap + 4);
                ahi[im][0] = h4.x; ahi[im][1] = h4.y; ahi[im][2] = h4.z; ahi[im][3] = h4.w;
                alo[im][0] = l4.x; alo[im][1] = l4.y; alo[im][2] = l4.z; alo[im][3] = l4.w;
            }
            // B fragments: 2 n8 tiles (jn = nw*2 + jj), (bh0,bh1,bl0,bl1)
#pragma unroll
            for (int jj = 0; jj < 2; jj++) {
                const unsigned* bp = wb + ktl * 1024 + (nw * 2 + jj) * 128 + lane * 4;
                uint4 b4 = *(const uint4*)(bp);
                unsigned bhi2[2] = {b4.x, b4.y};
                unsigned blo2[2] = {b4.z, b4.w};
#pragma unroll
                for (int im = 0; im < 2; im++) {
                    mma8(d[im][jj], alo[im], bhi2);
                    mma8(d[im][jj], ahi[im], blo2);
                    mma8(d[im][jj], ahi[im], bhi2);
                }
            }
        }
        __syncthreads();
    }

    // two-phase accumulation into gsm (k halves collide)
    {
        const int gr = lane >> 2, q2 = 2 * (lane & 3);
        if (kh == 0) {
#pragma unroll
            for (int im = 0; im < 2; im++)
#pragma unroll
                for (int jj = 0; jj < 2; jj++) {
                    int rb = mw * 32 + im * 16 + gr;
                    int cb = nw * 16 + jj * 8 + q2;
                    gsm[rb * 65 + cb]           += d[im][jj][0];
                    gsm[rb * 65 + cb + 1]       += d[im][jj][1];
                    gsm[(rb + 8) * 65 + cb]     += d[im][jj][2];
                    gsm[(rb + 8) * 65 + cb + 1] += d[im][jj][3];
                }
        }
        __syncthreads();
        if (kh == 1) {
#pragma unroll
            for (int im = 0; im < 2; im++)
#pragma unroll
                for (int jj = 0; jj < 2; jj++) {
                    int rb = mw * 32 + im * 16 + gr;
                    int cb = nw * 16 + jj * 8 + q2;
                    gsm[rb * 65 + cb]           += d[im][jj][0];
                    gsm[rb * 65 + cb + 1]       += d[im][jj][1];
                    gsm[(rb + 8) * 65 + cb]     += d[im][jj][2];
                    gsm[(rb + 8) * 65 + cb + 1] += d[im][jj][3];
                }
        }
        __syncthreads();
    }

    // activations + masked state update: 64 b x 16 cells = 1024 states, 2 per thread
    const float* hb_in  = g_hbuf + (size_t)pd_in * BB * CC;
    float*       hb_out = g_hbuf + (size_t)pd_out * BB * CC;
    unsigned*    hf_out = g_hfrag + (size_t)pd_out * 65536;
#pragma unroll
    for (int u = 0; u < 2; u++) {
        int idx = u * 512 + tid;          // 0..1023
        int b = idx >> 4, lc = idx & 15;
        int cell = c0 + lc;
        float ig = gsm[b * 65 + lc];
        float fg = gsm[b * 65 + 16 + lc];
        float gg = gsm[b * 65 + 32 + lc];
        float og = gsm[b * 65 + 48 + lc];
        ig = 1.f / (1.f + expf(-ig));
        fg = 1.f / (1.f + expf(-fg));
        gg = tanhf(gg);
        og = 1.f / (1.f + expf(-og));
        int ci = (dir * BB + b) * CC + cell;
        float c_old = g_c[ci];
        float h_old = hb_in[b * CC + cell];
        float cn = fg * c_old + ig * gg;
        float hn = og * tanhf(cn);
        bool m = (t < length[b]);
        float hf = m ? hn : h_old;
        g_c[ci] = m ? cn : c_old;
        hb_out[b * CC + cell] = hf;
        // fragment-major h write
        unsigned hi, lo;
        split_tf(hf, hi, lo);
        int kt = cell >> 3, kk = cell & 7;
        int mi = b >> 4, r = b & 15;
        int lane_w = ((r & 7) << 2) + (kk & 3);
        int reg = (r >> 3) + 2 * (kk >> 2);
        unsigned base = kt * 1024 + mi * 256 + lane_w * 8;
        hf_out[base + reg]     = hi;
        hf_out[base + reg + 4] = lo;
        outp[(size_t)t * (BB * HH) + b * HH + (dir << 9) + cell] = m ? hn : 0.f;
    }
}

// ---------------- final states ----------------
__global__ void k_final(float* __restrict__ outp) {
    int idx = blockIdx.x * 256 + threadIdx.x;   // 0..65535
    int dir = idx >> 15;
    int r = idx & 32767;
    int b = r >> 9, c = r & 511;
    // after 512 steps, final h lives in parity-0 fp32 buffer
    outp[OFF_H + b * HH + dir * CC + c] = g_hbuf[(size_t)dir * BB * CC + b * CC + c];
    outp[OFF_C + b * HH + dir * CC + c] = g_c[(dir * BB + b) * CC + c];
}

// ---------------- attention scores (fp32, symmetric) ----------------
__global__ void __launch_bounds__(256) k_scores(const float* __restrict__ outp) {
    const int tj = blockIdx.x, ti = blockIdx.y, b = blockIdx.z;
    if (ti > tj) return;
    __shared__ __align__(16) float As[16][64];
    __shared__ __align__(16) float Bs[16][64];
    const int tid = threadIdx.x;
    const int rg = tid & 15, cg = tid >> 4;
    const int lr = tid >> 2, lk = (tid & 3) << 2;
    const float* Ap = outp + (size_t)(ti * 64 + lr) * (BB * HH) + b * HH + lk;
    const float* Bp = outp + (size_t)(tj * 64 + lr) * (BB * HH) + b * HH + lk;
    float acc[4][4];
#pragma unroll
    for (int i = 0; i < 4; i++)
#pragma unroll
        for (int j = 0; j < 4; j++) acc[i][j] = 0.f;

    for (int k0 = 0; k0 < HH; k0 += 16) {
        float4 av = *(const float4*)(Ap + k0);
        float4 bv = *(const float4*)(Bp + k0);
        __syncthreads();
        As[lk + 0][lr] = av.x; As[lk + 1][lr] = av.y; As[lk + 2][lr] = av.z; As[lk + 3][lr] = av.w;
        Bs[lk + 0][lr] = bv.x; Bs[lk + 1][lr] = bv.y; Bs[lk + 2][lr] = bv.z; Bs[lk + 3][lr] = bv.w;
        __syncthreads();
#pragma unroll
        for (int k = 0; k < 16; k++) {
            float4 a4 = *(const float4*)&As[k][rg * 4];
            float4 b4 = *(const float4*)&Bs[k][cg * 4];
            acc[0][0] += a4.x * b4.x; acc[0][1] += a4.x * b4.y; acc[0][2] += a4.x * b4.z; acc[0][3] += a4.x * b4.w;
            acc[1][0] += a4.y * b4.x; acc[1][1] += a4.y * b4.y; acc[1][2] += a4.y * b4.z; acc[1][3] += a4.y * b4.w;
            acc[2][0] += a4.z * b4.x; acc[2][1] += a4.z * b4.y; acc[2][2] += a4.z * b4.z; acc[2][3] += a4.z * b4.w;
            acc[3][0] += a4.w * b4.x; acc[3][1] += a4.w * b4.y; acc[3][2] += a4.w * b4.z; acc[3][3] += a4.w * b4.w;
        }
    }
#pragma unroll
    for (int i = 0; i < 4; i++) {
        int trow = ti * 64 + rg * 4 + i;
#pragma unroll
        for (int j = 0; j < 4; j++) {
            int scol = tj * 64 + cg * 4 + j;
            g_scores[((size_t)b * TT + trow) * TT + scol] = acc[i][j];
            if (ti < tj)
                g_scores[((size_t)b * TT + scol) * TT + trow] = acc[i][j];
        }
    }
}

// ---------------- per-row softmax stats ----------------
__global__ void k_rowstats() {
    int warp = threadIdx.x >> 5, lane = threadIdx.x & 31;
    int row = blockIdx.x * 8 + warp;
    const float* sc = g_scores + (size_t)row * TT;
    float mx = -1e30f;
    for (int s = lane; s < TT; s += 32) mx = fmaxf(mx, sc[s]);
#pragma unroll
    for (int o = 16; o > 0; o >>= 1) mx = fmaxf(mx, __shfl_xor_sync(0xffffffffu, mx, o));
    float sum = 0.f;
    for (int s = lane; s < TT; s += 32) sum += expf(sc[s] - mx);
#pragma unroll
    for (int o = 16; o > 0; o >>= 1) sum += __shfl_xor_sync(0xffffffffu, sum, o);
    if (lane == 0) {
        g_rowmax[row] = mx;
        g_rowinv[row] = 1.f / sum;
    }
}

// ---------------- w[b,s] = sum_t attn[b,t,s] ----------------
__global__ void k_colsum() {
    int s = blockIdx.x * 256 + threadIdx.x;
    int b = blockIdx.y;
    float acc = 0.f;
    const float* sc = g_scores + (size_t)b * TT * TT + s;
    const float* rm = g_rowmax + b * TT;
    const float* ri = g_rowinv + b * TT;
    for (int t = 0; t < TT; t++)
        acc += expf(sc[(size_t)t * TT] - rm[t]) * ri[t];
    g_w[b * TT + s] = acc;
}

// ---------------- pre[b,h] = sum_s w[b,s] * out[s,b,h] ----------------
__global__ void k_ctxpre(const float* __restrict__ outp) {
    int h = blockIdx.x * 256 + threadIdx.x;
    int b = blockIdx.y;
    const float* w = g_w + b * TT;
    float acc = 0.f;
    for (int s = 0; s < TT; s++)
        acc += w[s] * outp[(size_t)s * (BB * HH) + b * HH + h];
    g_pre[b * HH + h] = acc;
}

// ---------------- context projection ----------------
__global__ void __launch_bounds__(128) k_ctxgemm(
    const float* __restrict__ Wctx, const float* __restrict__ bctx,
    float* __restrict__ outp)
{
    __shared__ float sp[HH];
    int tid = threadIdx.x;
    int b = blockIdx.y;
    for (int i = tid; i < HH; i += 128) sp[i] = g_pre[b * HH + i];
    __syncthreads();
    int n = blockIdx.x * 128 + tid;
    const float* wr = Wctx + (size_t)n * HH;
    float acc = bctx[n];
    for (int h = 0; h < HH; h += 4) {
        float4 w4 = *(const float4*)(wr + h);
        acc += sp[h] * w4.x + sp[h + 1] * w4.y + sp[h + 2] * w4.z + sp[h + 3] * w4.w;
    }
    outp[OFF_CTX + b * HH + n] = acc;
}

// ---------------- launch ----------------
extern "C" void kernel_launch(void* const* d_in, const int* in_sizes, int n_in,
                              void* d_out, int out_size)
{
    const float* x      = (const float*)d_in[0];
    const int*   length = (const int*)  d_in[1];
    const float* Wih_f  = (const float*)d_in[2];
    const float* Whh_f  = (const float*)d_in[3];
    const float* bih_f  = (const float*)d_in[4];
    const float* bhh_f  = (const float*)d_in[5];
    const float* Wih_b  = (const float*)d_in[6];
    const float* Whh_b  = (const float*)d_in[7];
    const float* bih_b  = (const float*)d_in[8];
    const float* bhh_b  = (const float*)d_in[9];
    const float* Wctx   = (const float*)d_in[10];
    const float* bctx   = (const float*)d_in[11];
    float* out = (float*)d_out;

    cudaFuncSetAttribute(k_gatesx3, cudaFuncAttributeMaxDynamicSharedMemorySize, GX_SMEM_BYTES);
    cudaFuncSetAttribute(k_step2,   cudaFuncAttributeMaxDynamicSharedMemorySize, STEP_SMEM_BYTES);

    k_zero<<<512, 256>>>();
    k_prep<<<8192, 256>>>(Whh_f, Whh_b);
    k_gatesx3<<<dim3(32, 256, 2), 256, GX_SMEM_BYTES>>>(x, Wih_f, Wih_b, bih_f, bhh_f, bih_b, bhh_b);
    for (int s = 0; s < TT; s++)
        k_step2<<<64, 512, STEP_SMEM_BYTES>>>(length, out, s);
    k_final<<<256, 256>>>(out);
    k_scores<<<dim3(8, 8, 64), 256>>>(out);
    k_rowstats<<<TT * BB / 8, 256>>>();
    k_colsum<<<dim3(2, 64), 256>>>();
    k_ctxpre<<<dim3(4, 64), 256>>>(out);
    k_ctxgemm<<<dim3(8, 64), 128>>>(Wctx, bctx, out);
}

// round 9
// speedup vs baseline: 2.2466x; 1.5541x over previous
#include <cuda_runtime.h>
#include <cuda_bf16.h>
#include <math.h>

// Problem constants
#define TT   512
#define BB   64
#define II   512
#define CC   512            // cell size
#define HH   1024           // output hidden (2*CC)
#define G4   2048           // 4*CC gate rows
#define M1   (TT*BB)        // 32768 rows for input gemm

// d_out layout: output [T,B,H] | final_h [1,B,H] | final_c [1,B,H] | context [B,H]
#define OFF_OUT  0
#define OFF_H    ((size_t)TT*BB*HH)
#define OFF_C    (OFF_H + (size_t)BB*HH)
#define OFF_CTX  (OFF_C + (size_t)BB*HH)

// ---------------- device scratch ----------------
__device__ float    g_gx[(size_t)2 * M1 * G4];       // x@Wih^T + bih + bhh per dir
__device__ float    g_scores[(size_t)BB * TT * TT];
__device__ float    g_hbuf[2 * 2 * BB * CC];         // fp32 h: [parity][dir][b][c]
// h in bf16-split mma-fragment-major form: [pd 0..3][kt 0..31][mi 0..3][lane 0..31][hi0..3 | lo0..3]
__device__ unsigned g_hfragB[4 * 32768];
// Whh bf16-split fragment-major per step-block: [blk 0..127][kt 0..31][jn 0..3][lane 0..31][bh0,bh1,bl0,bl1]
__device__ unsigned g_wtfB[(size_t)128 * 16384];
__device__ float    g_c[2 * BB * CC];                // [dir][b][c]
__device__ float    g_rowmax[BB * TT];
__device__ float    g_rowinv[BB * TT];
__device__ float    g_w[BB * TT];
__device__ float    g_pre[BB * HH];

// ---------------- helpers ----------------
__device__ __forceinline__ unsigned f2tf(float f) {
    unsigned r;
    asm("cvt.rna.tf32.f32 %0, %1;" : "=r"(r) : "f"(f));
    return r;
}
__device__ __forceinline__ void split_tf(float v, unsigned& hi, unsigned& lo) {
    hi = f2tf(v);
    lo = f2tf(v - __uint_as_float(hi));
}
// bf16 2-way split: v ~= hi + lo with ~16 mantissa bits total
__device__ __forceinline__ void split_bf(float v, unsigned short& hi, unsigned short& lo) {
    __nv_bfloat16 h = __float2bfloat16(v);
    __nv_bfloat16 l = __float2bfloat16(v - __bfloat162float(h));
    hi = __bfloat16_as_ushort(h);
    lo = __bfloat16_as_ushort(l);
}
__device__ __forceinline__ void mma8(float* d, const unsigned* a, const unsigned* b) {
    asm volatile(
        "mma.sync.aligned.m16n8k8.row.col.f32.tf32.tf32.f32 "
        "{%0,%1,%2,%3},{%4,%5,%6,%7},{%8,%9},{%0,%1,%2,%3};"
        : "+f"(d[0]), "+f"(d[1]), "+f"(d[2]), "+f"(d[3])
        : "r"(a[0]), "r"(a[1]), "r"(a[2]), "r"(a[3]), "r"(b[0]), "r"(b[1]));
}
__device__ __forceinline__ void mmabf(float* d, const unsigned* a, const unsigned* b) {
    asm volatile(
        "mma.sync.aligned.m16n8k16.row.col.f32.bf16.bf16.f32 "
        "{%0,%1,%2,%3},{%4,%5,%6,%7},{%8,%9},{%0,%1,%2,%3};"
        : "+f"(d[0]), "+f"(d[1]), "+f"(d[2]), "+f"(d[3])
        : "r"(a[0]), "r"(a[1]), "r"(a[2]), "r"(a[3]), "r"(b[0]), "r"(b[1]));
}
__device__ __forceinline__ void cp16(void* dst, const void* src) {
    unsigned d = (unsigned)__cvta_generic_to_shared(dst);
    asm volatile("cp.async.cg.shared.global [%0], [%1], 16;" :: "r"(d), "l"(src));
}
#define CP_COMMIT() asm volatile("cp.async.commit_group;" ::: "memory")
#define CP_WAIT0()  asm volatile("cp.async.wait_group 0;" ::: "memory")
#define CP_WAIT1()  asm volatile("cp.async.wait_group 1;" ::: "memory")
#define CP_WAIT2()  asm volatile("cp.async.wait_group 2;" ::: "memory")
#define CP_WAIT3()  asm volatile("cp.async.wait_group 3;" ::: "memory")

// ---------------- init ----------------
__global__ void k_zero() {
    int i = blockIdx.x * 256 + threadIdx.x;   // 65536 threads
    if (i < 2 * 32768) g_hfragB[i] = 0u;      // parity-0 fragment h (both dirs)
    g_hbuf[i] = 0.f;                          // parity-0 fp32 h region
    g_c[i]    = 0.f;
}

// ---------------- weight prep: Whh -> bf16-split fragment-major ----------------
// step block blk (0..127): dir = blk>>6, blkc = blk&63, 8 cells c0=blkc*8, 32 gate cols j.
// G = (j>>3)*512 + blkc*8 + (j&7). Thread handles one (G, k-pair).
__global__ void k_prep(const float* __restrict__ Whhf, const float* __restrict__ Whhb) {
    int v = blockIdx.x * 256 + threadIdx.x;    // 0..1048575
    int kp = v & 255;                          // k pair index
    int rj = v >> 8;                           // 0..4095
    int j = rj & 31;
    int blk = rj >> 5;                         // 0..127
    int dir = blk >> 6, blkc = blk & 63;
    const float* W = dir ? Whhb : Whhf;
    int G = ((j >> 3) << 9) + blkc * 8 + (j & 7);
    int k0 = kp * 2;
    float v0 = W[(size_t)G * CC + k0];
    float v1 = W[(size_t)G * CC + k0 + 1];
    unsigned short h0, l0, h1, l1;
    split_bf(v0, h0, l0);
    split_bf(v1, h1, l1);
    unsigned hi01 = (unsigned)h0 | ((unsigned)h1 << 16);
    unsigned lo01 = (unsigned)l0 | ((unsigned)l1 << 16);
    int kt = k0 >> 4, kk0 = k0 & 15;
    int jn = j >> 3;
    int lane = (j & 7) * 4 + ((kk0 & 7) >> 1);
    int reg = (kk0 >= 8) ? 1 : 0;
    size_t addr = (size_t)blk * 16384 + kt * 512 + jn * 128 + lane * 4;
    g_wtfB[addr + reg]     = hi01;
    g_wtfB[addr + 2 + reg] = lo01;
}

// ---------------- phase 1: gx = x @ Wih^T + bih + bhh  (3xTF32 mma) — unchanged ----------------
#define GX_SMEM_WORDS ((128 + 128 + 64 + 64) * 36)
#define GX_SMEM_BYTES (GX_SMEM_WORDS * 4)

__global__ void __launch_bounds__(256) k_gatesx3(
    const float* __restrict__ x,
    const float* __restrict__ Wf, const float* __restrict__ Wb,
    const float* __restrict__ bif, const float* __restrict__ bhf,
    const float* __restrict__ bib, const float* __restrict__ bhb)
{
    extern __shared__ unsigned sg[];
    unsigned* Ahi = sg;
    unsigned* Alo = sg + 4608;
    unsigned* Bhi = sg + 9216;
    unsigned* Blo = sg + 11520;

    const int dir = blockIdx.z;
    const float* W  = dir ? Wb  : Wf;
    const float* bi = dir ? bib : bif;
    const float* bh = dir ? bhb : bhf;
    float* out = g_gx + (size_t)dir * M1 * G4;

    const int m0 = blockIdx.y * 128;
    const int n0 = blockIdx.x * 64;
    const int tid = threadIdx.x;
    const int w = tid >> 5, lane = tid & 31;
    const int mg = w & 3;
    const int ng = w >> 2;

    float d[2][4][4];
#pragma unroll
    for (int i = 0; i < 2; i++)
#pragma unroll
        for (int j = 0; j < 4; j++)
#pragma unroll
            for (int r = 0; r < 4; r++) d[i][j][r] = 0.f;

    const unsigned aoff = (mg * 32 + (lane >> 2)) * 36 + (lane & 3);
    const unsigned boff = (ng * 32 + (lane >> 2)) * 36 + (lane & 3);

    for (int kc = 0; kc < 16; kc++) {
        const int k0 = kc * 32;
        float4 av[4], bv[2];
#pragma unroll
        for (int it = 0; it < 4; it++) {
            int v = it * 256 + tid, r = v >> 3, kq = v & 7;
            av[it] = *(const float4*)(x + (size_t)(m0 + r) * II + k0 + kq * 4);
        }
#pragma unroll
        for (int it = 0; it < 2; it++) {
            int v = it * 256 + tid, r = v >> 3, kq = v & 7;
            bv[it] = *(const float4*)(W + (size_t)(n0 + r) * II + k0 + kq * 4);
        }
        __syncthreads();
#pragma unroll
        for (int it = 0; it < 4; it++) {
            int v = it * 256 + tid, r = v >> 3, kq = v & 7;
            unsigned* dh = Ahi + r * 36 + kq * 4;
            unsigned* dl = Alo + r * 36 + kq * 4;
            split_tf(av[it].x, dh[0], dl[0]); split_tf(av[it].y, dh[1], dl[1]);
            split_tf(av[it].z, dh[2], dl[2]); split_tf(av[it].w, dh[3], dl[3]);
        }
#pragma unroll
        for (int it = 0; it < 2; it++) {
            int v = it * 256 + tid, r = v >> 3, kq = v & 7;
            unsigned* dh = Bhi + r * 36 + kq * 4;
            unsigned* dl = Blo + r * 36 + kq * 4;
            split_tf(bv[it].x, dh[0], dl[0]); split_tf(bv[it].y, dh[1], dl[1]);
            split_tf(bv[it].z, dh[2], dl[2]); split_tf(bv[it].w, dh[3], dl[3]);
        }
        __syncthreads();
        unsigned* ah = Ahi + aoff;  unsigned* al = Alo + aoff;
        unsigned* bhp = Bhi + boff; unsigned* blp = Blo + boff;
#pragma unroll
        for (int kt = 0; kt < 4; kt++) {
            unsigned ahi[2][4], alo[2][4];
            ahi[0][0] = ah[0];            ahi[0][1] = ah[8 * 36];
            ahi[0][2] = ah[4];            ahi[0][3] = ah[8 * 36 + 4];
            ahi[1][0] = ah[16 * 36];      ahi[1][1] = ah[24 * 36];
            ahi[1][2] = ah[16 * 36 + 4];  ahi[1][3] = ah[24 * 36 + 4];
            alo[0][0] = al[0];            alo[0][1] = al[8 * 36];
            alo[0][2] = al[4];            alo[0][3] = al[8 * 36 + 4];
            alo[1][0] = al[16 * 36];      alo[1][1] = al[24 * 36];
            alo[1][2] = al[16 * 36 + 4];  alo[1][3] = al[24 * 36 + 4];
#pragma unroll
            for (int j = 0; j < 4; j++) {
                unsigned bhi2[2], blo2[2];
                bhi2[0] = bhp[j * 8 * 36];     bhi2[1] = bhp[j * 8 * 36 + 4];
                blo2[0] = blp[j * 8 * 36];     blo2[1] = blp[j * 8 * 36 + 4];
#pragma unroll
                for (int i = 0; i < 2; i++) {
                    mma8(d[i][j], alo[i], bhi2);
                    mma8(d[i][j], ahi[i], blo2);
                    mma8(d[i][j], ahi[i], bhi2);
                }
            }
            ah += 8; al += 8; bhp += 8; blp += 8;
        }
    }

#pragma unroll
    for (int i = 0; i < 2; i++) {
        int rb = m0 + mg * 32 + i * 16 + (lane >> 2);
#pragma unroll
        for (int j = 0; j < 4; j++) {
            int cb = n0 + ng * 32 + j * 8 + 2 * (lane & 3);
            float bs0 = bi[cb] + bh[cb];
            float bs1 = bi[cb + 1] + bh[cb + 1];
            out[(size_t)rb * G4 + cb]           = d[i][j][0] + bs0;
            out[(size_t)rb * G4 + cb + 1]       = d[i][j][1] + bs1;
            out[(size_t)(rb + 8) * G4 + cb]     = d[i][j][2] + bs0;
            out[(size_t)(rb + 8) * G4 + cb + 1] = d[i][j][3] + bs1;
        }
    }
}

// ---------------- phase 2: one LSTM timestep — bf16 3-mma split, 128 blocks, all-staged ----------------
// grid 128: dir = blk>>6, blkc = blk&63, 8 cells (=32 gate cols). Tile C[64 batch, 32 gates], K=512.
// 16 warps: kh = w>>3 (K half of each chunk), mw = (w&7)&1 (2 m16 tiles), nw = (w&7)>>1 (1 n8 tile = gate).
// smem: 4 chunk buffers of 12288 words (h 8192 | W 4096), then gsm f32[64][33].
#define CHB_WORDS 12288
#define GSMB_OFF  (4 * CHB_WORDS)                 // 49152
#define STEP_SMEM_WORDS (GSMB_OFF + 64 * 33)      // 51264
#define STEP_SMEM_BYTES (STEP_SMEM_WORDS * 4)     // 205056

__global__ void __launch_bounds__(512, 1) k_stepb(
    const int* __restrict__ length, float* __restrict__ outp, int step)
{
    extern __shared__ unsigned sm[];
    float* gsm = (float*)(sm + GSMB_OFF);

    const int tid = threadIdx.x, w = tid >> 5, lane = tid & 31;
    const int dir  = blockIdx.x >> 6;
    const int blkc = blockIdx.x & 63;
    const int c0   = blkc << 3;
    const int t    = dir ? (TT - 1 - step) : step;
    const int p    = step & 1;
    const int pd_in  = p * 2 + dir;
    const int pd_out = (p ^ 1) * 2 + dir;
    const unsigned* hsrc = g_hfragB + pd_in * 32768;
    const unsigned* wsrc = g_wtfB + (size_t)blockIdx.x * 16384;

    // stage ALL 4 K-chunks upfront (max MLP); one commit group per chunk
#pragma unroll
    for (int c = 0; c < 4; c++) {
        unsigned* hb = sm + c * CHB_WORDS;
        unsigned* wb = hb + 8192;
        const unsigned* hs = hsrc + c * 8192;
        const unsigned* ws = wsrc + c * 4096;
#pragma unroll
        for (int it = 0; it < 4; it++) {
            int q = it * 512 + tid;              // 0..2047 h cp16s
            cp16(hb + q * 4, hs + q * 4);
        }
#pragma unroll
        for (int it = 0; it < 2; it++) {
            int q = it * 512 + tid;              // 0..1023 W cp16s
            cp16(wb + q * 4, ws + q * 4);
        }
        CP_COMMIT();
    }

    // preload gsm with precomputed x-gates (overlaps cp.async)
    {
        const float* gx = g_gx + ((size_t)dir * M1 + (size_t)t * BB) * G4;
#pragma unroll
        for (int u = 0; u < 4; u++) {
            int v = u * 512 + tid;               // 0..2047
            int b = v >> 5, j = v & 31;
            int G = ((j >> 3) << 9) + c0 + (j & 7);
            gsm[b * 33 + j] = gx[(size_t)b * G4 + G];
        }
    }

    const int kh = w >> 3;
    const int mw = w & 1;
    const int nw = (w >> 1) & 3;                 // gate index (jn)

    float d[2][4];
#pragma unroll
    for (int im = 0; im < 2; im++)
#pragma unroll
        for (int r = 0; r < 4; r++) d[im][r] = 0.f;

#pragma unroll
    for (int c = 0; c < 4; c++) {
        if (c == 0)      { CP_WAIT3(); }
        else if (c == 1) { CP_WAIT2(); }
        else if (c == 2) { CP_WAIT1(); }
        else             { CP_WAIT0(); }
        __syncthreads();
        const unsigned* hb = sm + c * CHB_WORDS;
        const unsigned* wb = hb + 8192;
#pragma unroll
        for (int ktl = 0; ktl < 4; ktl++) {
            const int ktL = kh * 4 + ktl;        // kt within chunk (0..7)
            // B fragment for this warp's gate tile: (bh0,bh1,bl0,bl1)
            uint4 b4 = *(const uint4*)(wb + ktL * 512 + nw * 128 + lane * 4);
            unsigned bhi2[2] = {b4.x, b4.y};
            unsigned blo2[2] = {b4.z, b4.w};
#pragma unroll
            for (int im = 0; im < 2; im++) {
                const unsigned* ap = hb + (ktL * 4 + (mw * 2 + im)) * 256 + lane * 8;
                uint4 h4 = *(const uint4*)(ap);
                uint4 l4 = *(const uint4*)(ap + 4);
                unsigned ahi[4] = {h4.x, h4.y, h4.z, h4.w};
                unsigned alo[4] = {l4.x, l4.y, l4.z, l4.w};
                mmabf(d[im], alo, bhi2);
                mmabf(d[im], ahi, blo2);
                mmabf(d[im], ahi, bhi2);
            }
        }
    }
    __syncthreads();

    // two-phase accumulation into gsm (K halves collide)
    {
        const int gr = lane >> 2, q2 = 2 * (lane & 3);
        if (kh == 0) {
#pragma unroll
            for (int im = 0; im < 2; im++) {
                int rb = mw * 32 + im * 16 + gr;
                int cb = nw * 8 + q2;
                gsm[rb * 33 + cb]           += d[im][0];
                gsm[rb * 33 + cb + 1]       += d[im][1];
                gsm[(rb + 8) * 33 + cb]     += d[im][2];
                gsm[(rb + 8) * 33 + cb + 1] += d[im][3];
            }
        }
        __syncthreads();
        if (kh == 1) {
#pragma unroll
            for (int im = 0; im < 2; im++) {
                int rb = mw * 32 + im * 16 + gr;
                int cb = nw * 8 + q2;
                gsm[rb * 33 + cb]           += d[im][0];
                gsm[rb * 33 + cb + 1]       += d[im][1];
                gsm[(rb + 8) * 33 + cb]     += d[im][2];
                gsm[(rb + 8) * 33 + cb + 1] += d[im][3];
            }
        }
        __syncthreads();
    }

    // activations + masked state update: 64 b x 8 cells = 512 states, cell PAIRS on threads 0..255
    if (tid < 256) {
        int b = tid >> 2, q = tid & 3;
        int lc0 = 2 * q;
        int cell0 = c0 + lc0;
        float gate[2][4];
#pragma unroll
        for (int u = 0; u < 2; u++) {
            int lc = lc0 + u;
            gate[u][0] = gsm[b * 33 + lc];            // i
            gate[u][1] = gsm[b * 33 + 8 + lc];        // f
            gate[u][2] = gsm[b * 33 + 16 + lc];       // g
            gate[u][3] = gsm[b * 33 + 24 + lc];       // o
        }
        int ci = (dir * BB + b) * CC + cell0;
        float2 c_old = *(const float2*)(g_c + ci);
        const float* hb_in = g_hbuf + (size_t)pd_in * BB * CC;
        float2 h_old = *(const float2*)(hb_in + b * CC + cell0);
        bool m = (t < length[b]);
        float hf[2], cf[2], ho[2];
#pragma unroll
        for (int u = 0; u < 2; u++) {
            float ig = 1.f / (1.f + expf(-gate[u][0]));
            float fg = 1.f / (1.f + expf(-gate[u][1]));
            float gg = tanhf(gate[u][2]);
            float og = 1.f / (1.f + expf(-gate[u][3]));
            float co = u ? c_old.y : c_old.x;
            float hol = u ? h_old.y : h_old.x;
            float cn = fg * co + ig * gg;
            float hn = og * tanhf(cn);
            cf[u] = m ? cn : co;
            hf[u] = m ? hn : hol;
            ho[u] = m ? hn : 0.f;
        }
        *(float2*)(g_c + ci) = make_float2(cf[0], cf[1]);
        float* hb_out = g_hbuf + (size_t)pd_out * BB * CC;
        *(float2*)(hb_out + b * CC + cell0) = make_float2(hf[0], hf[1]);
        *(float2*)(outp + (size_t)t * (BB * HH) + b * HH + (dir << 9) + cell0) = make_float2(ho[0], ho[1]);
        // bf16-split fragment-major h write
        unsigned short h0, l0, h1, l1;
        split_bf(hf[0], h0, l0);
        split_bf(hf[1], h1, l1);
        unsigned hi01 = (unsigned)h0 | ((unsigned)h1 << 16);
        unsigned lo01 = (unsigned)l0 | ((unsigned)l1 << 16);
        int kt = blkc >> 1;
        int kk0 = ((blkc & 1) << 3) + lc0;
        int mi = b >> 4, r = b & 15;
        int lane_w = (r & 7) * 4 + q;
        int reg = ((r >> 3) & 1) + ((blkc & 1) << 1);
        unsigned* hf_out = g_hfragB + pd_out * 32768;
        unsigned base = kt * 1024 + mi * 256 + lane_w * 8;
        (void)kk0;
        hf_out[base + reg]     = hi01;
        hf_out[base + 4 + reg] = lo01;
    }
}

// ---------------- final states ----------------
__global__ void k_final(float* __restrict__ outp) {
    int idx = blockIdx.x * 256 + threadIdx.x;   // 0..65535
    int dir = idx >> 15;
    int r = idx & 32767;
    int b = r >> 9, c = r & 511;
    outp[OFF_H + b * HH + dir * CC + c] = g_hbuf[(size_t)dir * BB * CC + b * CC + c];
    outp[OFF_C + b * HH + dir * CC + c] = g_c[(dir * BB + b) * CC + c];
}

// ---------------- attention scores (fp32, symmetric) ----------------
__global__ void __launch_bounds__(256) k_scores(const float* __restrict__ outp) {
    const int tj = blockIdx.x, ti = blockIdx.y, b = blockIdx.z;
    if (ti > tj) return;
    __shared__ __align__(16) float As[16][64];
    __shared__ __align__(16) float Bs[16][64];
    const int tid = threadIdx.x;
    const int rg = tid & 15, cg = tid >> 4;
    const int lr = tid >> 2, lk = (tid & 3) << 2;
    const float* Ap = outp + (size_t)(ti * 64 + lr) * (BB * HH) + b * HH + lk;
    const float* Bp = outp + (size_t)(tj * 64 + lr) * (BB * HH) + b * HH + lk;
    float acc[4][4];
#pragma unroll
    for (int i = 0; i < 4; i++)
#pragma unroll
        for (int j = 0; j < 4; j++) acc[i][j] = 0.f;

    for (int k0 = 0; k0 < HH; k0 += 16) {
        float4 av = *(const float4*)(Ap + k0);
        float4 bv = *(const float4*)(Bp + k0);
        __syncthreads();
        As[lk + 0][lr] = av.x; As[lk + 1][lr] = av.y; As[lk + 2][lr] = av.z; As[lk + 3][lr] = av.w;
        Bs[lk + 0][lr] = bv.x; Bs[lk + 1][lr] = bv.y; Bs[lk + 2][lr] = bv.z; Bs[lk + 3][lr] = bv.w;
        __syncthreads();
#pragma unroll
        for (int k = 0; k < 16; k++) {
            float4 a4 = *(const float4*)&As[k][rg * 4];
            float4 b4 = *(const float4*)&Bs[k][cg * 4];
            acc[0][0] += a4.x * b4.x; acc[0][1] += a4.x * b4.y; acc[0][2] += a4.x * b4.z; acc[0][3] += a4.x * b4.w;
            acc[1][0] += a4.y * b4.x; acc[1][1] += a4.y * b4.y; acc[1][2] += a4.y * b4.z; acc[1][3] += a4.y * b4.w;
            acc[2][0] += a4.z * b4.x; acc[2][1] += a4.z * b4.y; acc[2][2] += a4.z * b4.z; acc[2][3] += a4.z * b4.w;
            acc[3][0] += a4.w * b4.x; acc[3][1] += a4.w * b4.y; acc[3][2] += a4.w * b4.z; acc[3][3] += a4.w * b4.w;
        }
    }
#pragma unroll
    for (int i = 0; i < 4; i++) {
        int trow = ti * 64 + rg * 4 + i;
#pragma unroll
        for (int j = 0; j < 4; j++) {
            int scol = tj * 64 + cg * 4 + j;
            g_scores[((size_t)b * TT + trow) * TT + scol] = acc[i][j];
            if (ti < tj)
                g_scores[((size_t)b * TT + scol) * TT + trow] = acc[i][j];
        }
    }
}

// ---------------- per-row softmax stats ----------------
__global__ void k_rowstats() {
    int warp = threadIdx.x >> 5, lane = threadIdx.x & 31;
    int row = blockIdx.x * 8 + warp;
    const float* sc = g_scores + (size_t)row * TT;
    float mx = -1e30f;
    for (int s = lane; s < TT; s += 32) mx = fmaxf(mx, sc[s]);
#pragma unroll
    for (int o = 16; o > 0; o >>= 1) mx = fmaxf(mx, __shfl_xor_sync(0xffffffffu, mx, o));
    float sum = 0.f;
    for (int s = lane; s < TT; s += 32) sum += expf(sc[s] - mx);
#pragma unroll
    for (int o = 16; o > 0; o >>= 1) sum += __shfl_xor_sync(0xffffffffu, sum, o);
    if (lane == 0) {
        g_rowmax[row] = mx;
        g_rowinv[row] = 1.f / sum;
    }
}

// ---------------- w[b,s] = sum_t attn[b,t,s] ----------------
__global__ void k_colsum() {
    int s = blockIdx.x * 256 + threadIdx.x;
    int b = blockIdx.y;
    float acc = 0.f;
    const float* sc = g_scores + (size_t)b * TT * TT + s;
    const float* rm = g_rowmax + b * TT;
    const float* ri = g_rowinv + b * TT;
    for (int t = 0; t < TT; t++)
        acc += expf(sc[(size_t)t * TT] - rm[t]) * ri[t];
    g_w[b * TT + s] = acc;
}

// ---------------- pre[b,h] = sum_s w[b,s] * out[s,b,h] ----------------
__global__ void k_ctxpre(const float* __restrict__ outp) {
    int h = blockIdx.x * 256 + threadIdx.x;
    int b = blockIdx.y;
    const float* w = g_w + b * TT;
    float acc = 0.f;
    for (int s = 0; s < TT; s++)
        acc += w[s] * outp[(size_t)s * (BB * HH) + b * HH + h];
    g_pre[b * HH + h] = acc;
}

// ---------------- context projection ----------------
__global__ void __launch_bounds__(128) k_ctxgemm(
    const float* __restrict__ Wctx, const float* __restrict__ bctx,
    float* __restrict__ outp)
{
    __shared__ float sp[HH];
    int tid = threadIdx.x;
    int b = blockIdx.y;
    for (int i = tid; i < HH; i += 128) sp[i] = g_pre[b * HH + i];
    __syncthreads();
    int n = blockIdx.x * 128 + tid;
    const float* wr = Wctx + (size_t)n * HH;
    float acc = bctx[n];
    for (int h = 0; h < HH; h += 4) {
        float4 w4 = *(const float4*)(wr + h);
        acc += sp[h] * w4.x + sp[h + 1] * w4.y + sp[h + 2] * w4.z + sp[h + 3] * w4.w;
    }
    outp[OFF_CTX + b * HH + n] = acc;
}

// ---------------- launch ----------------
extern "C" void kernel_launch(void* const* d_in, const int* in_sizes, int n_in,
                              void* d_out, int out_size)
{
    const float* x      = (const float*)d_in[0];
    const int*   length = (const int*)  d_in[1];
    const float* Wih_f  = (const float*)d_in[2];
    const float* Whh_f  = (const float*)d_in[3];
    const float* bih_f  = (const float*)d_in[4];
    const float* bhh_f  = (const float*)d_in[5];
    const float* Wih_b  = (const float*)d_in[6];
    const float* Whh_b  = (const float*)d_in[7];
    const float* bih_b  = (const float*)d_in[8];
    const float* bhh_b  = (const float*)d_in[9];
    const float* Wctx   = (const float*)d_in[10];
    const float* bctx   = (const float*)d_in[11];
    float* out = (float*)d_out;

    cudaFuncSetAttribute(k_gatesx3, cudaFuncAttributeMaxDynamicSharedMemorySize, GX_SMEM_BYTES);
    cudaFuncSetAttribute(k_stepb,   cudaFuncAttributeMaxDynamicSharedMemorySize, STEP_SMEM_BYTES);

    k_zero<<<256, 256>>>();
    k_prep<<<4096, 256>>>(Whh_f, Whh_b);
    k_gatesx3<<<dim3(32, 256, 2), 256, GX_SMEM_BYTES>>>(x, Wih_f, Wih_b, bih_f, bhh_f, bih_b, bhh_b);
    for (int s = 0; s < TT; s++)
        k_stepb<<<128, 512, STEP_SMEM_BYTES>>>(length, out, s);
    k_final<<<256, 256>>>(out);
    k_scores<<<dim3(8, 8, 64), 256>>>(out);
    k_rowstats<<<TT * BB / 8, 256>>>();
    k_colsum<<<dim3(2, 64), 256>>>();
    k_ctxpre<<<dim3(4, 64), 256>>>(out);
    k_ctxgemm<<<dim3(8, 64), 128>>>(Wctx, bctx, out);
}

// round 10
// speedup vs baseline: 2.7447x; 1.2217x over previous
#include <cuda_runtime.h>
#include <cuda_bf16.h>
#include <math.h>

// Problem constants
#define TT   512
#define BB   64
#define II   512
#define CC   512            // cell size
#define HH   1024           // output hidden (2*CC)
#define G4   2048           // 4*CC gate rows
#define M1   (TT*BB)        // 32768 rows for input gemm

// d_out layout: output [T,B,H] | final_h [1,B,H] | final_c [1,B,H] | context [B,H]
#define OFF_OUT  0
#define OFF_H    ((size_t)TT*BB*HH)
#define OFF_C    (OFF_H + (size_t)BB*HH)
#define OFF_CTX  (OFF_C + (size_t)BB*HH)

// ---------------- device scratch ----------------
__device__ float    g_gx[(size_t)2 * M1 * G4];       // x@Wih^T + bih + bhh per dir
__device__ float    g_scores[(size_t)BB * TT * TT];
__device__ float    g_hbuf[2 * 2 * BB * CC];         // fp32 h: [parity][dir][b][c]
// h in bf16-split mma-fragment-major form: [pd 0..3][kt 0..31][mi 0..3][lane 0..31][8 words, hi/lo quads swizzled]
__device__ unsigned g_hfragB[4 * 32768];
// Whh bf16-split fragment-major per step-block: [blk 0..127][kt 0..31][jn 0..3][lane 0..31][bh0,bh1,bl0,bl1]
__device__ unsigned g_wtfB[(size_t)128 * 16384];
__device__ float    g_c[2 * BB * CC];                // [dir][b][c]
__device__ float    g_rowmax[BB * TT];
__device__ float    g_rowinv[BB * TT];
__device__ float    g_w[BB * TT];
__device__ float    g_pre[BB * HH];

// ---------------- helpers ----------------
__device__ __forceinline__ unsigned f2tf(float f) {
    unsigned r;
    asm("cvt.rna.tf32.f32 %0, %1;" : "=r"(r) : "f"(f));
    return r;
}
__device__ __forceinline__ void split_tf(float v, unsigned& hi, unsigned& lo) {
    hi = f2tf(v);
    lo = f2tf(v - __uint_as_float(hi));
}
// bf16 2-way split: v ~= hi + lo with ~16 mantissa bits total
__device__ __forceinline__ void split_bf(float v, unsigned short& hi, unsigned short& lo) {
    __nv_bfloat16 h = __float2bfloat16(v);
    __nv_bfloat16 l = __float2bfloat16(v - __bfloat162float(h));
    hi = __bfloat16_as_ushort(h);
    lo = __bfloat16_as_ushort(l);
}
__device__ __forceinline__ void mma8(float* d, const unsigned* a, const unsigned* b) {
    asm volatile(
        "mma.sync.aligned.m16n8k8.row.col.f32.tf32.tf32.f32 "
        "{%0,%1,%2,%3},{%4,%5,%6,%7},{%8,%9},{%0,%1,%2,%3};"
        : "+f"(d[0]), "+f"(d[1]), "+f"(d[2]), "+f"(d[3])
        : "r"(a[0]), "r"(a[1]), "r"(a[2]), "r"(a[3]), "r"(b[0]), "r"(b[1]));
}
__device__ __forceinline__ void mmabf(float* d, const unsigned* a, const unsigned* b) {
    asm volatile(
        "mma.sync.aligned.m16n8k16.row.col.f32.bf16.bf16.f32 "
        "{%0,%1,%2,%3},{%4,%5,%6,%7},{%8,%9},{%0,%1,%2,%3};"
        : "+f"(d[0]), "+f"(d[1]), "+f"(d[2]), "+f"(d[3])
        : "r"(a[0]), "r"(a[1]), "r"(a[2]), "r"(a[3]), "r"(b[0]), "r"(b[1]));
}
__device__ __forceinline__ void cp16(void* dst, const void* src) {
    unsigned d = (unsigned)__cvta_generic_to_shared(dst);
    asm volatile("cp.async.cg.shared.global [%0], [%1], 16;" :: "r"(d), "l"(src));
}
__device__ __forceinline__ void prefetchL2(const void* p) {
    asm volatile("prefetch.global.L2 [%0];" :: "l"(p));
}
#define CP_COMMIT() asm volatile("cp.async.commit_group;" ::: "memory")
#define CP_WAIT0()  asm volatile("cp.async.wait_group 0;" ::: "memory")
#define CP_WAIT1()  asm volatile("cp.async.wait_group 1;" ::: "memory")
#define CP_WAIT2()  asm volatile("cp.async.wait_group 2;" ::: "memory")
#define CP_WAIT3()  asm volatile("cp.async.wait_group 3;" ::: "memory")

// ---------------- init ----------------
__global__ void k_zero() {
    int i = blockIdx.x * 256 + threadIdx.x;   // 65536 threads
    if (i < 2 * 32768) g_hfragB[i] = 0u;      // parity-0 fragment h (both dirs)
    g_hbuf[i] = 0.f;                          // parity-0 fp32 h region
    g_c[i]    = 0.f;
}

// ---------------- weight prep: Whh -> bf16-split fragment-major (unchanged from R9) ----------------
__global__ void k_prep(const float* __restrict__ Whhf, const float* __restrict__ Whhb) {
    int v = blockIdx.x * 256 + threadIdx.x;    // 0..1048575
    int kp = v & 255;                          // k pair index
    int rj = v >> 8;                           // 0..4095
    int j = rj & 31;
    int blk = rj >> 5;                         // 0..127
    int dir = blk >> 6, blkc = blk & 63;
    const float* W = dir ? Whhb : Whhf;
    int G = ((j >> 3) << 9) + blkc * 8 + (j & 7);
    int k0 = kp * 2;
    float v0 = W[(size_t)G * CC + k0];
    float v1 = W[(size_t)G * CC + k0 + 1];
    unsigned short h0, l0, h1, l1;
    split_bf(v0, h0, l0);
    split_bf(v1, h1, l1);
    unsigned hi01 = (unsigned)h0 | ((unsigned)h1 << 16);
    unsigned lo01 = (unsigned)l0 | ((unsigned)l1 << 16);
    int kt = k0 >> 4, kk0 = k0 & 15;
    int jn = j >> 3;
    int lane = (j & 7) * 4 + ((kk0 & 7) >> 1);
    int reg = (kk0 >= 8) ? 1 : 0;
    size_t addr = (size_t)blk * 16384 + kt * 512 + jn * 128 + lane * 4;
    g_wtfB[addr + reg]     = hi01;
    g_wtfB[addr + 2 + reg] = lo01;
}

// ---------------- phase 1: gx = x @ Wih^T + bih + bhh  (3xTF32 mma) — unchanged ----------------
#define GX_SMEM_WORDS ((128 + 128 + 64 + 64) * 36)
#define GX_SMEM_BYTES (GX_SMEM_WORDS * 4)

__global__ void __launch_bounds__(256) k_gatesx3(
    const float* __restrict__ x,
    const float* __restrict__ Wf, const float* __restrict__ Wb,
    const float* __restrict__ bif, const float* __restrict__ bhf,
    const float* __restrict__ bib, const float* __restrict__ bhb)
{
    extern __shared__ unsigned sg[];
    unsigned* Ahi = sg;
    unsigned* Alo = sg + 4608;
    unsigned* Bhi = sg + 9216;
    unsigned* Blo = sg + 11520;

    const int dir = blockIdx.z;
    const float* W  = dir ? Wb  : Wf;
    const float* bi = dir ? bib : bif;
    const float* bh = dir ? bhb : bhf;
    float* out = g_gx + (size_t)dir * M1 * G4;

    const int m0 = blockIdx.y * 128;
    const int n0 = blockIdx.x * 64;
    const int tid = threadIdx.x;
    const int w = tid >> 5, lane = tid & 31;
    const int mg = w & 3;
    const int ng = w >> 2;

    float d[2][4][4];
#pragma unroll
    for (int i = 0; i < 2; i++)
#pragma unroll
        for (int j = 0; j < 4; j++)
#pragma unroll
            for (int r = 0; r < 4; r++) d[i][j][r] = 0.f;

    const unsigned aoff = (mg * 32 + (lane >> 2)) * 36 + (lane & 3);
    const unsigned boff = (ng * 32 + (lane >> 2)) * 36 + (lane & 3);

    for (int kc = 0; kc < 16; kc++) {
        const int k0 = kc * 32;
        float4 av[4], bv[2];
#pragma unroll
        for (int it = 0; it < 4; it++) {
            int v = it * 256 + tid, r = v >> 3, kq = v & 7;
            av[it] = *(const float4*)(x + (size_t)(m0 + r) * II + k0 + kq * 4);
        }
#pragma unroll
        for (int it = 0; it < 2; it++) {
            int v = it * 256 + tid, r = v >> 3, kq = v & 7;
            bv[it] = *(const float4*)(W + (size_t)(n0 + r) * II + k0 + kq * 4);
        }
        __syncthreads();
#pragma unroll
        for (int it = 0; it < 4; it++) {
            int v = it * 256 + tid, r = v >> 3, kq = v & 7;
            unsigned* dh = Ahi + r * 36 + kq * 4;
            unsigned* dl = Alo + r * 36 + kq * 4;
            split_tf(av[it].x, dh[0], dl[0]); split_tf(av[it].y, dh[1], dl[1]);
            split_tf(av[it].z, dh[2], dl[2]); split_tf(av[it].w, dh[3], dl[3]);
        }
#pragma unroll
        for (int it = 0; it < 2; it++) {
            int v = it * 256 + tid, r = v >> 3, kq = v & 7;
            unsigned* dh = Bhi + r * 36 + kq * 4;
            unsigned* dl = Blo + r * 36 + kq * 4;
            split_tf(bv[it].x, dh[0], dl[0]); split_tf(bv[it].y, dh[1], dl[1]);
            split_tf(bv[it].z, dh[2], dl[2]); split_tf(bv[it].w, dh[3], dl[3]);
        }
        __syncthreads();
        unsigned* ah = Ahi + aoff;  unsigned* al = Alo + aoff;
        unsigned* bhp = Bhi + boff; unsigned* blp = Blo + boff;
#pragma unroll
        for (int kt = 0; kt < 4; kt++) {
            unsigned ahi[2][4], alo[2][4];
            ahi[0][0] = ah[0];            ahi[0][1] = ah[8 * 36];
            ahi[0][2] = ah[4];            ahi[0][3] = ah[8 * 36 + 4];
            ahi[1][0] = ah[16 * 36];      ahi[1][1] = ah[24 * 36];
            ahi[1][2] = ah[16 * 36 + 4];  ahi[1][3] = ah[24 * 36 + 4];
            alo[0][0] = al[0];            alo[0][1] = al[8 * 36];
            alo[0][2] = al[4];            alo[0][3] = al[8 * 36 + 4];
            alo[1][0] = al[16 * 36];      alo[1][1] = al[24 * 36];
            alo[1][2] = al[16 * 36 + 4];  alo[1][3] = al[24 * 36 + 4];
#pragma unroll
            for (int j = 0; j < 4; j++) {
                unsigned bhi2[2], blo2[2];
                bhi2[0] = bhp[j * 8 * 36];     bhi2[1] = bhp[j * 8 * 36 + 4];
                blo2[0] = blp[j * 8 * 36];     blo2[1] = blp[j * 8 * 36 + 4];
#pragma unroll
                for (int i = 0; i < 2; i++) {
                    mma8(d[i][j], alo[i], bhi2);
                    mma8(d[i][j], ahi[i], blo2);
                    mma8(d[i][j], ahi[i], bhi2);
                }
            }
            ah += 8; al += 8; bhp += 8; blp += 8;
        }
    }

#pragma unroll
    for (int i = 0; i < 2; i++) {
        int rb = m0 + mg * 32 + i * 16 + (lane >> 2);
#pragma unroll
        for (int j = 0; j < 4; j++) {
            int cb = n0 + ng * 32 + j * 8 + 2 * (lane & 3);
            float bs0 = bi[cb] + bh[cb];
            float bs1 = bi[cb + 1] + bh[cb + 1];
            out[(size_t)rb * G4 + cb]           = d[i][j][0] + bs0;
            out[(size_t)rb * G4 + cb + 1]       = d[i][j][1] + bs1;
            out[(size_t)(rb + 8) * G4 + cb]     = d[i][j][2] + bs0;
            out[(size_t)(rb + 8) * G4 + cb + 1] = d[i][j][3] + bs1;
        }
    }
}

// ---------------- phase 2: one LSTM timestep — 8 warps, A-reuse tiling, swizzled frags ----------------
// grid 128: dir = blk>>6, blkc = blk&63, 8 cells (=32 gate cols). Tile C[64 batch, 32 gates], K=512.
// 8 warps: mw = w&3 (m16 tile), nw = w>>2 (gate half: n8 tiles 2nw, 2nw+1). Full K per warp.
// smem: 4 chunk buffers of 12288 words (h 8192 | W 4096), then gsm f32[64][33].
#define CHB_WORDS 12288
#define GSMB_OFF  (4 * CHB_WORDS)                 // 49152
#define STEP_SMEM_WORDS (GSMB_OFF + 64 * 33)      // 51264
#define STEP_SMEM_BYTES (STEP_SMEM_WORDS * 4)     // 205056

__global__ void __launch_bounds__(256, 1) k_stepc(
    const int* __restrict__ length, float* __restrict__ outp, int step)
{
    extern __shared__ unsigned sm[];
    float* gsm = (float*)(sm + GSMB_OFF);

    const int tid = threadIdx.x, w = tid >> 5, lane = tid & 31;
    const int dir  = blockIdx.x >> 6;
    const int blkc = blockIdx.x & 63;
    const int c0   = blkc << 3;
    const int t    = dir ? (TT - 1 - step) : step;
    const int p    = step & 1;
    const int pd_in  = p * 2 + dir;
    const int pd_out = (p ^ 1) * 2 + dir;
    const unsigned* hsrc = g_hfragB + pd_in * 32768;
    const unsigned* wsrc = g_wtfB + (size_t)blockIdx.x * 16384;

    // stage ALL 4 K-chunks upfront; one commit group per chunk (12 cp16/thread/chunk)
#pragma unroll
    for (int c = 0; c < 4; c++) {
        unsigned* hb = sm + c * CHB_WORDS;
        unsigned* wb = hb + 8192;
        const unsigned* hs = hsrc + c * 8192;
        const unsigned* ws = wsrc + c * 4096;
#pragma unroll
        for (int it = 0; it < 8; it++) {
            int q = it * 256 + tid;              // 0..2047 h cp16s
            cp16(hb + q * 4, hs + q * 4);
        }
#pragma unroll
        for (int it = 0; it < 4; it++) {
            int q = it * 256 + tid;              // 0..1023 W cp16s
            cp16(wb + q * 4, ws + q * 4);
        }
        CP_COMMIT();
    }

    // prefetch next step's gx slice into L2 (1 piece of 32B per thread)
    if (step + 1 < TT) {
        const int tn = dir ? (t - 1) : (t + 1);
        const float* gxn = g_gx + ((size_t)dir * M1 + (size_t)tn * BB) * G4;
        int b = tid >> 2, grp = tid & 3;
        prefetchL2(gxn + (size_t)b * G4 + grp * 512 + c0);
    }

    // preload gsm with precomputed x-gates (streaming loads; overlaps cp.async)
    {
        const float* gx = g_gx + ((size_t)dir * M1 + (size_t)t * BB) * G4;
#pragma unroll
        for (int u = 0; u < 8; u++) {
            int v = u * 256 + tid;               // 0..2047
            int b = v >> 5, j = v & 31;
            int G = ((j >> 3) << 9) + c0 + (j & 7);
            gsm[b * 33 + j] = __ldcs(gx + (size_t)b * G4 + G);
        }
    }

    const int mw = w & 3;
    const int nw = w >> 2;
    const int swz = ((lane >> 2) & 1) * 4;       // hi/lo quad swizzle (bank-conflict-free A loads)

    float d[2][4];
#pragma unroll
    for (int jj = 0; jj < 2; jj++)
#pragma unroll
        for (int r = 0; r < 4; r++) d[jj][r] = 0.f;

#pragma unroll
    for (int c = 0; c < 4; c++) {
        if (c == 0)      { CP_WAIT3(); }
        else if (c == 1) { CP_WAIT2(); }
        else if (c == 2) { CP_WAIT1(); }
        else             { CP_WAIT0(); }
        __syncthreads();
        const unsigned* hb = sm + c * CHB_WORDS;
        const unsigned* wb = hb + 8192;
#pragma unroll
        for (int ktl = 0; ktl < 8; ktl++) {
            const unsigned* ap = hb + ktl * 1024 + mw * 256 + lane * 8;
            uint4 h4 = *(const uint4*)(ap + swz);
            uint4 l4 = *(const uint4*)(ap + (swz ^ 4));
            unsigned ahi[4] = {h4.x, h4.y, h4.z, h4.w};
            unsigned alo[4] = {l4.x, l4.y, l4.z, l4.w};
#pragma unroll
            for (int jj = 0; jj < 2; jj++) {
                uint4 b4 = *(const uint4*)(wb + ktl * 512 + (nw * 2 + jj) * 128 + lane * 4);
                unsigned bhi2[2] = {b4.x, b4.y};
                unsigned blo2[2] = {b4.z, b4.w};
                mmabf(d[jj], alo, bhi2);
                mmabf(d[jj], ahi, blo2);
                mmabf(d[jj], ahi, bhi2);
            }
        }
    }

    // single-phase accumulation: each (m16, n8) region owned by exactly one warp
    {
        const int gr = lane >> 2, q2 = 2 * (lane & 3);
#pragma unroll
        for (int jj = 0; jj < 2; jj++) {
            int rb = mw * 16 + gr;
            int cb = (nw * 2 + jj) * 8 + q2;
            gsm[rb * 33 + cb]           += d[jj][0];
            gsm[rb * 33 + cb + 1]       += d[jj][1];
            gsm[(rb + 8) * 33 + cb]     += d[jj][2];
            gsm[(rb + 8) * 33 + cb + 1] += d[jj][3];
        }
    }
    __syncthreads();

    // activations + masked state update: 64 b x 8 cells = 512 states, cell pairs (all 256 threads)
    {
        int b = tid >> 2, q = tid & 3;
        int lc0 = 2 * q;
        int cell0 = c0 + lc0;
        float gate[2][4];
#pragma unroll
        for (int u = 0; u < 2; u++) {
            int lc = lc0 + u;
            gate[u][0] = gsm[b * 33 + lc];            // i
            gate[u][1] = gsm[b * 33 + 8 + lc];        // f
            gate[u][2] = gsm[b * 33 + 16 + lc];       // g
            gate[u][3] = gsm[b * 33 + 24 + lc];       // o
        }
        int ci = (dir * BB + b) * CC + cell0;
        float2 c_old = *(const float2*)(g_c + ci);
        const float* hb_in = g_hbuf + (size_t)pd_in * BB * CC;
        float2 h_old = *(const float2*)(hb_in + b * CC + cell0);
        bool m = (t < length[b]);
        float hf[2], cf[2], ho[2];
#pragma unroll
        for (int u = 0; u < 2; u++) {
            float ig = 1.f / (1.f + expf(-gate[u][0]));
            float fg = 1.f / (1.f + expf(-gate[u][1]));
            float gg = tanhf(gate[u][2]);
            float og = 1.f / (1.f + expf(-gate[u][3]));
            float co = u ? c_old.y : c_old.x;
            float hol = u ? h_old.y : h_old.x;
            float cn = fg * co + ig * gg;
            float hn = og * tanhf(cn);
            cf[u] = m ? cn : co;
            hf[u] = m ? hn : hol;
            ho[u] = m ? hn : 0.f;
        }
        *(float2*)(g_c + ci) = make_float2(cf[0], cf[1]);
        float* hb_out = g_hbuf + (size_t)pd_out * BB * CC;
        *(float2*)(hb_out + b * CC + cell0) = make_float2(hf[0], hf[1]);
        __stcs((float2*)(outp + (size_t)t * (BB * HH) + b * HH + (dir << 9) + cell0),
               make_float2(ho[0], ho[1]));
        // bf16-split fragment-major h write (with hi/lo quad swizzle)
        unsigned short h0, l0, h1, l1;
        split_bf(hf[0], h0, l0);
        split_bf(hf[1], h1, l1);
        unsigned hi01 = (unsigned)h0 | ((unsigned)h1 << 16);
        unsigned lo01 = (unsigned)l0 | ((unsigned)l1 << 16);
        int kt = blkc >> 1;
        int mi = b >> 4, r = b & 15;
        int lane_w = (r & 7) * 4 + q;
        int reg = ((r >> 3) & 1) + ((blkc & 1) << 1);
        int sw = ((lane_w >> 2) & 1) * 4;
        unsigned* hf_out = g_hfragB + pd_out * 32768;
        unsigned base = kt * 1024 + mi * 256 + lane_w * 8;
        hf_out[base + sw + reg]       = hi01;
        hf_out[base + (sw ^ 4) + reg] = lo01;
    }
}

// ---------------- final states ----------------
__global__ void k_final(float* __restrict__ outp) {
    int idx = blockIdx.x * 256 + threadIdx.x;   // 0..65535
    int dir = idx >> 15;
    int r = idx & 32767;
    int b = r >> 9, c = r & 511;
    outp[OFF_H + b * HH + dir * CC + c] = g_hbuf[(size_t)dir * BB * CC + b * CC + c];
    outp[OFF_C + b * HH + dir * CC + c] = g_c[(dir * BB + b) * CC + c];
}

// ---------------- attention scores (fp32, symmetric) ----------------
__global__ void __launch_bounds__(256) k_scores(const float* __restrict__ outp) {
    const int tj = blockIdx.x, ti = blockIdx.y, b = blockIdx.z;
    if (ti > tj) return;
    __shared__ __align__(16) float As[16][64];
    __shared__ __align__(16) float Bs[16][64];
    const int tid = threadIdx.x;
    const int rg = tid & 15, cg = tid >> 4;
    const int lr = tid >> 2, lk = (tid & 3) << 2;
    const float* Ap = outp + (size_t)(ti * 64 + lr) * (BB * HH) + b * HH + lk;
    const float* Bp = outp + (size_t)(tj * 64 + lr) * (BB * HH) + b * HH + lk;
    float acc[4][4];
#pragma unroll
    for (int i = 0; i < 4; i++)
#pragma unroll
        for (int j = 0; j < 4; j++) acc[i][j] = 0.f;

    for (int k0 = 0; k0 < HH; k0 += 16) {
        float4 av = *(const float4*)(Ap + k0);
        float4 bv = *(const float4*)(Bp + k0);
        __syncthreads();
        As[lk + 0][lr] = av.x; As[lk + 1][lr] = av.y; As[lk + 2][lr] = av.z; As[lk + 3][lr] = av.w;
        Bs[lk + 0][lr] = bv.x; Bs[lk + 1][lr] = bv.y; Bs[lk + 2][lr] = bv.z; Bs[lk + 3][lr] = bv.w;
        __syncthreads();
#pragma unroll
        for (int k = 0; k < 16; k++) {
            float4 a4 = *(const float4*)&As[k][rg * 4];
            float4 b4 = *(const float4*)&Bs[k][cg * 4];
            acc[0][0] += a4.x * b4.x; acc[0][1] += a4.x * b4.y; acc[0][2] += a4.x * b4.z; acc[0][3] += a4.x * b4.w;
            acc[1][0] += a4.y * b4.x; acc[1][1] += a4.y * b4.y; acc[1][2] += a4.y * b4.z; acc[1][3] += a4.y * b4.w;
            acc[2][0] += a4.z * b4.x; acc[2][1] += a4.z * b4.y; acc[2][2] += a4.z * b4.z; acc[2][3] += a4.z * b4.w;
            acc[3][0] += a4.w * b4.x; acc[3][1] += a4.w * b4.y; acc[3][2] += a4.w * b4.z; acc[3][3] += a4.w * b4.w;
        }
    }
#pragma unroll
    for (int i = 0; i < 4; i++) {
        int trow = ti * 64 + rg * 4 + i;
#pragma unroll
        for (int j = 0; j < 4; j++) {
            int scol = tj * 64 + cg * 4 + j;
            g_scores[((size_t)b * TT + trow) * TT + scol] = acc[i][j];
            if (ti < tj)
                g_scores[((size_t)b * TT + scol) * TT + trow] = acc[i][j];
        }
    }
}

// ---------------- per-row softmax stats ----------------
__global__ void k_rowstats() {
    int warp = threadIdx.x >> 5, lane = threadIdx.x & 31;
    int row = blockIdx.x * 8 + warp;
    const float* sc = g_scores + (size_t)row * TT;
    float mx = -1e30f;
    for (int s = lane; s < TT; s += 32) mx = fmaxf(mx, sc[s]);
#pragma unroll
    for (int o = 16; o > 0; o >>= 1) mx = fmaxf(mx, __shfl_xor_sync(0xffffffffu, mx, o));
    float sum = 0.f;
    for (int s = lane; s < TT; s += 32) sum += expf(sc[s] - mx);
#pragma unroll
    for (int o = 16; o > 0; o >>= 1) sum += __shfl_xor_sync(0xffffffffu, sum, o);
    if (lane == 0) {
        g_rowmax[row] = mx;
        g_rowinv[row] = 1.f / sum;
    }
}

// ---------------- w[b,s] = sum_t attn[b,t,s] ----------------
__global__ void k_colsum() {
    int s = blockIdx.x * 256 + threadIdx.x;
    int b = blockIdx.y;
    float acc = 0.f;
    const float* sc = g_scores + (size_t)b * TT * TT + s;
    const float* rm = g_rowmax + b * TT;
    const float* ri = g_rowinv + b * TT;
    for (int t = 0; t < TT; t++)
        acc += expf(sc[(size_t)t * TT] - rm[t]) * ri[t];
    g_w[b * TT + s] = acc;
}

// ---------------- pre[b,h] = sum_s w[b,s] * out[s,b,h] ----------------
__global__ void k_ctxpre(const float* __restrict__ outp) {
    int h = blockIdx.x * 256 + threadIdx.x;
    int b = blockIdx.y;
    const float* w = g_w + b * TT;
    float acc = 0.f;
    for (int s = 0; s < TT; s++)
        acc += w[s] * outp[(size_t)s * (BB * HH) + b * HH + h];
    g_pre[b * HH + h] = acc;
}

// ---------------- context projection ----------------
__global__ void __launch_bounds__(128) k_ctxgemm(
    const float* __restrict__ Wctx, const float* __restrict__ bctx,
    float* __restrict__ outp)
{
    __shared__ float sp[HH];
    int tid = threadIdx.x;
    int b = blockIdx.y;
    for (int i = tid; i < HH; i += 128) sp[i] = g_pre[b * HH + i];
    __syncthreads();
    int n = blockIdx.x * 128 + tid;
    const float* wr = Wctx + (size_t)n * HH;
    float acc = bctx[n];
    for (int h = 0; h < HH; h += 4) {
        float4 w4 = *(const float4*)(wr + h);
        acc += sp[h] * w4.x + sp[h + 1] * w4.y + sp[h + 2] * w4.z + sp[h + 3] * w4.w;
    }
    outp[OFF_CTX + b * HH + n] = acc;
}

// ---------------- launch ----------------
extern "C" void kernel_launch(void* const* d_in, const int* in_sizes, int n_in,
                              void* d_out, int out_size)
{
    const float* x      = (const float*)d_in[0];
    const int*   length = (const int*)  d_in[1];
    const float* Wih_f  = (const float*)d_in[2];
    const float* Whh_f  = (const float*)d_in[3];
    const float* bih_f  = (const float*)d_in[4];
    const float* bhh_f  = (const float*)d_in[5];
    const float* Wih_b  = (const float*)d_in[6];
    const float* Whh_b  = (const float*)d_in[7];
    const float* bih_b  = (const float*)d_in[8];
    const float* bhh_b  = (const float*)d_in[9];
    const float* Wctx   = (const float*)d_in[10];
    const float* bctx   = (const float*)d_in[11];
    float* out = (float*)d_out;

    cudaFuncSetAttribute(k_gatesx3, cudaFuncAttributeMaxDynamicSharedMemorySize, GX_SMEM_BYTES);
    cudaFuncSetAttribute(k_stepc,   cudaFuncAttributeMaxDynamicSharedMemorySize, STEP_SMEM_BYTES);

    k_zero<<<256, 256>>>();
    k_prep<<<4096, 256>>>(Whh_f, Whh_b);
    k_gatesx3<<<dim3(32, 256, 2), 256, GX_SMEM_BYTES>>>(x, Wih_f, Wih_b, bih_f, bhh_f, bih_b, bhh_b);
    for (int s = 0; s < TT; s++)
        k_stepc<<<128, 256, STEP_SMEM_BYTES>>>(length, out, s);
    k_final<<<256, 256>>>(out);
    k_scores<<<dim3(8, 8, 64), 256>>>(out);
    k_rowstats<<<TT * BB / 8, 256>>>();
    k_colsum<<<dim3(2, 64), 256>>>();
    k_ctxpre<<<dim3(4, 64), 256>>>(out);
    k_ctxgemm<<<dim3(8, 64), 128>>>(Wctx, bctx, out);
}

// round 13
// speedup vs baseline: 2.8454x; 1.0367x over previous
#include <cuda_runtime.h>
#include <cuda_bf16.h>
#include <math.h>

// Problem constants
#define TT   512
#define BB   64
#define II   512
#define CC   512            // cell size
#define HH   1024           // output hidden (2*CC)
#define G4   2048           // 4*CC gate rows
#define M1   (TT*BB)        // 32768 rows for input gemm

// d_out layout: output [T,B,H] | final_h [1,B,H] | final_c [1,B,H] | context [B,H]
#define OFF_OUT  0
#define OFF_H    ((size_t)TT*BB*HH)
#define OFF_C    (OFF_H + (size_t)BB*HH)
#define OFF_CTX  (OFF_C + (size_t)BB*HH)

// ---------------- device scratch ----------------
__device__ float    g_gx[(size_t)2 * M1 * G4];       // x@Wih^T + bih + bhh per dir
__device__ float    g_scores[(size_t)BB * TT * TT];
__device__ float    g_hbuf[2 * 2 * BB * CC];         // fp32 h: [parity][dir][b][c]
// h in bf16-split mma-fragment-major form: [pd 0..3][kt 0..31][mi 0..3][lane 0..31][8 words, hi/lo quads swizzled]
__device__ __align__(128) unsigned g_hfragB[4 * 32768];
// Whh bf16-split fragment-major per step-block: [blk 0..127][kt 0..31][jn 0..3][lane 0..31][bh0,bh1,bl0,bl1]
__device__ __align__(128) unsigned g_wtfB[(size_t)128 * 16384];
__device__ float    g_c[2 * BB * CC];                // [dir][b][c]
__device__ float    g_rowmax[BB * TT];
__device__ float    g_rowinv[BB * TT];
__device__ float    g_w[BB * TT];
__device__ float    g_pre[BB * HH];

// ---------------- helpers ----------------
__device__ __forceinline__ unsigned f2tf(float f) {
    unsigned r;
    asm("cvt.rna.tf32.f32 %0, %1;" : "=r"(r) : "f"(f));
    return r;
}
__device__ __forceinline__ void split_tf(float v, unsigned& hi, unsigned& lo) {
    hi = f2tf(v);
    lo = f2tf(v - __uint_as_float(hi));
}
// bf16 2-way split: v ~= hi + lo with ~16 mantissa bits total
__device__ __forceinline__ void split_bf(float v, unsigned short& hi, unsigned short& lo) {
    __nv_bfloat16 h = __float2bfloat16(v);
    __nv_bfloat16 l = __float2bfloat16(v - __bfloat162float(h));
    hi = __bfloat16_as_ushort(h);
    lo = __bfloat16_as_ushort(l);
}
__device__ __forceinline__ void mma8(float* d, const unsigned* a, const unsigned* b) {
    asm volatile(
        "mma.sync.aligned.m16n8k8.row.col.f32.tf32.tf32.f32 "
        "{%0,%1,%2,%3},{%4,%5,%6,%7},{%8,%9},{%0,%1,%2,%3};"
        : "+f"(d[0]), "+f"(d[1]), "+f"(d[2]), "+f"(d[3])
        : "r"(a[0]), "r"(a[1]), "r"(a[2]), "r"(a[3]), "r"(b[0]), "r"(b[1]));
}
__device__ __forceinline__ void mmabf(float* d, const unsigned* a, const unsigned* b) {
    asm volatile(
        "mma.sync.aligned.m16n8k16.row.col.f32.bf16.bf16.f32 "
        "{%0,%1,%2,%3},{%4,%5,%6,%7},{%8,%9},{%0,%1,%2,%3};"
        : "+f"(d[0]), "+f"(d[1]), "+f"(d[2]), "+f"(d[3])
        : "r"(a[0]), "r"(a[1]), "r"(a[2]), "r"(a[3]), "r"(b[0]), "r"(b[1]));
}
__device__ __forceinline__ void prefetchL2(const void* p) {
    asm volatile("prefetch.global.L2 [%0];" :: "l"(p));
}

// ---------------- init ----------------
__global__ void k_zero() {
    int i = blockIdx.x * 256 + threadIdx.x;   // 65536 threads
    if (i < 2 * 32768) g_hfragB[i] = 0u;      // parity-0 fragment h (both dirs)
    g_hbuf[i] = 0.f;                          // parity-0 fp32 h region
    g_c[i]    = 0.f;
}

// ---------------- weight prep: Whh -> bf16-split fragment-major (unchanged) ----------------
__global__ void k_prep(const float* __restrict__ Whhf, const float* __restrict__ Whhb) {
    int v = blockIdx.x * 256 + threadIdx.x;    // 0..1048575
    int kp = v & 255;                          // k pair index
    int rj = v >> 8;                           // 0..4095
    int j = rj & 31;
    int blk = rj >> 5;                         // 0..127
    int dir = blk >> 6, blkc = blk & 63;
    const float* W = dir ? Whhb : Whhf;
    int G = ((j >> 3) << 9) + blkc * 8 + (j & 7);
    int k0 = kp * 2;
    float v0 = W[(size_t)G * CC + k0];
    float v1 = W[(size_t)G * CC + k0 + 1];
    unsigned short h0, l0, h1, l1;
    split_bf(v0, h0, l0);
    split_bf(v1, h1, l1);
    unsigned hi01 = (unsigned)h0 | ((unsigned)h1 << 16);
    unsigned lo01 = (unsigned)l0 | ((unsigned)l1 << 16);
    int kt = k0 >> 4, kk0 = k0 & 15;
    int jn = j >> 3;
    int lane = (j & 7) * 4 + ((kk0 & 7) >> 1);
    int reg = (kk0 >= 8) ? 1 : 0;
    size_t addr = (size_t)blk * 16384 + kt * 512 + jn * 128 + lane * 4;
    g_wtfB[addr + reg]     = hi01;
    g_wtfB[addr + 2 + reg] = lo01;
}

// ---------------- phase 1: gx = x @ Wih^T + bih + bhh  (3xTF32 mma) — unchanged ----------------
#define GX_SMEM_WORDS ((128 + 128 + 64 + 64) * 36)
#define GX_SMEM_BYTES (GX_SMEM_WORDS * 4)

__global__ void __launch_bounds__(256) k_gatesx3(
    const float* __restrict__ x,
    const float* __restrict__ Wf, const float* __restrict__ Wb,
    const float* __restrict__ bif, const float* __restrict__ bhf,
    const float* __restrict__ bib, const float* __restrict__ bhb)
{
    extern __shared__ unsigned sg[];
    unsigned* Ahi = sg;
    unsigned* Alo = sg + 4608;
    unsigned* Bhi = sg + 9216;
    unsigned* Blo = sg + 11520;

    const int dir = blockIdx.z;
    const float* W  = dir ? Wb  : Wf;
    const float* bi = dir ? bib : bif;
    const float* bh = dir ? bhb : bhf;
    float* out = g_gx + (size_t)dir * M1 * G4;

    const int m0 = blockIdx.y * 128;
    const int n0 = blockIdx.x * 64;
    const int tid = threadIdx.x;
    const int w = tid >> 5, lane = tid & 31;
    const int mg = w & 3;
    const int ng = w >> 2;

    float d[2][4][4];
#pragma unroll
    for (int i = 0; i < 2; i++)
#pragma unroll
        for (int j = 0; j < 4; j++)
#pragma unroll
            for (int r = 0; r < 4; r++) d[i][j][r] = 0.f;

    const unsigned aoff = (mg * 32 + (lane >> 2)) * 36 + (lane & 3);
    const unsigned boff = (ng * 32 + (lane >> 2)) * 36 + (lane & 3);

    for (int kc = 0; kc < 16; kc++) {
        const int k0 = kc * 32;
        float4 av[4], bv[2];
#pragma unroll
        for (int it = 0; it < 4; it++) {
            int v = it * 256 + tid, r = v >> 3, kq = v & 7;
            av[it] = *(const float4*)(x + (size_t)(m0 + r) * II + k0 + kq * 4);
        }
#pragma unroll
        for (int it = 0; it < 2; it++) {
            int v = it * 256 + tid, r = v >> 3, kq = v & 7;
            bv[it] = *(const float4*)(W + (size_t)(n0 + r) * II + k0 + kq * 4);
        }
        __syncthreads();
#pragma unroll
        for (int it = 0; it < 4; it++) {
            int v = it * 256 + tid, r = v >> 3, kq = v & 7;
            unsigned* dh = Ahi + r * 36 + kq * 4;
            unsigned* dl = Alo + r * 36 + kq * 4;
            split_tf(av[it].x, dh[0], dl[0]); split_tf(av[it].y, dh[1], dl[1]);
            split_tf(av[it].z, dh[2], dl[2]); split_tf(av[it].w, dh[3], dl[3]);
        }
#pragma unroll
        for (int it = 0; it < 2; it++) {
            int v = it * 256 + tid, r = v >> 3, kq = v & 7;
            unsigned* dh = Bhi + r * 36 + kq * 4;
            unsigned* dl = Blo + r * 36 + kq * 4;
            split_tf(bv[it].x, dh[0], dl[0]); split_tf(bv[it].y, dh[1], dl[1]);
            split_tf(bv[it].z, dh[2], dl[2]); split_tf(bv[it].w, dh[3], dl[3]);
        }
        __syncthreads();
        unsigned* ah = Ahi + aoff;  unsigned* al = Alo + aoff;
        unsigned* bhp = Bhi + boff; unsigned* blp = Blo + boff;
#pragma unroll
        for (int kt = 0; kt < 4; kt++) {
            unsigned ahi[2][4], alo[2][4];
            ahi[0][0] = ah[0];            ahi[0][1] = ah[8 * 36];
            ahi[0][2] = ah[4];            ahi[0][3] = ah[8 * 36 + 4];
            ahi[1][0] = ah[16 * 36];      ahi[1][1] = ah[24 * 36];
            ahi[1][2] = ah[16 * 36 + 4];  ahi[1][3] = ah[24 * 36 + 4];
            alo[0][0] = al[0];            alo[0][1] = al[8 * 36];
            alo[0][2] = al[4];            alo[0][3] = al[8 * 36 + 4];
            alo[1][0] = al[16 * 36];      alo[1][1] = al[24 * 36];
            alo[1][2] = al[16 * 36 + 4];  alo[1][3] = al[24 * 36 + 4];
#pragma unroll
            for (int j = 0; j < 4; j++) {
                unsigned bhi2[2], blo2[2];
                bhi2[0] = bhp[j * 8 * 36];     bhi2[1] = bhp[j * 8 * 36 + 4];
                blo2[0] = blp[j * 8 * 36];     blo2[1] = blp[j * 8 * 36 + 4];
#pragma unroll
                for (int i = 0; i < 2; i++) {
                    mma8(d[i][j], alo[i], bhi2);
                    mma8(d[i][j], ahi[i], blo2);
                    mma8(d[i][j], ahi[i], bhi2);
                }
            }
            ah += 8; al += 8; bhp += 8; blp += 8;
        }
    }

#pragma unroll
    for (int i = 0; i < 2; i++) {
        int rb = m0 + mg * 32 + i * 16 + (lane >> 2);
#pragma unroll
        for (int j = 0; j < 4; j++) {
            int cb = n0 + ng * 32 + j * 8 + 2 * (lane & 3);
            float bs0 = bi[cb] + bh[cb];
            float bs1 = bi[cb + 1] + bh[cb + 1];
            out[(size_t)rb * G4 + cb]           = d[i][j][0] + bs0;
            out[(size_t)rb * G4 + cb + 1]       = d[i][j][1] + bs1;
            out[(size_t)(rb + 8) * G4 + cb]     = d[i][j][2] + bs0;
            out[(size_t)(rb + 8) * G4 + cb + 1] = d[i][j][3] + bs1;
        }
    }
}

// ---------------- phase 2: one LSTM timestep — direct-LDG fragments, no smem data path ----------------
// grid 128: dir = blk>>6, blkc = blk&63, 8 cells (=32 gate cols). Tile C[64 batch, 32 gates], K=512.
// 8 warps: mw = w&3 (m16 tile), nw = w>>2 (gate half). Fragments LDG.128'd straight from the
// fragment-major global arrays; duplicate reads across warps hit per-SM L1. No cp.async, no staging.
__global__ void __launch_bounds__(256, 1) k_stepd(
    const int* __restrict__ length, float* __restrict__ outp, int step)
{
    __shared__ float gsm[64][33];

    const int tid = threadIdx.x, w = tid >> 5, lane = tid & 31;
    const int dir  = blockIdx.x >> 6;
    const int blkc = blockIdx.x & 63;
    const int c0   = blkc << 3;
    const int t    = dir ? (TT - 1 - step) : step;
    const int p    = step & 1;
    const int pd_in  = p * 2 + dir;
    const int pd_out = (p ^ 1) * 2 + dir;
    const unsigned* hsrc = g_hfragB + pd_in * 32768;
    const unsigned* wsrc = g_wtfB + (size_t)blockIdx.x * 16384;

    // prefetch next step's gx slice into L2 (1 piece of 32B per thread)
    if (step + 1 < TT) {
        const int tn = dir ? (t - 1) : (t + 1);
        const float* gxn = g_gx + ((size_t)dir * M1 + (size_t)tn * BB) * G4;
        int b = tid >> 2, grp = tid & 3;
        prefetchL2(gxn + (size_t)b * G4 + grp * 512 + c0);
    }

    // preload gsm with precomputed x-gates (streaming loads)
    {
        const float* gx = g_gx + ((size_t)dir * M1 + (size_t)t * BB) * G4;
#pragma unroll
        for (int u = 0; u < 8; u++) {
            int v = u * 256 + tid;               // 0..2047
            int b = v >> 5, j = v & 31;
            int G = ((j >> 3) << 9) + c0 + (j & 7);
            gsm[b >> 0][0] = gsm[b][0];          // no-op to keep indices clear
            gsm[b][j] = __ldcs(gx + (size_t)b * G4 + G);
        }
    }

    const int mw = w & 3;
    const int nw = w >> 2;
    const int swz = ((lane >> 2) & 1) * 4;       // hi/lo quad swizzle (matches writer)

    const unsigned* ha = hsrc + mw * 256 + lane * 8;
    const unsigned* wa = wsrc + nw * 256 + lane * 4;

    float d[2][4];
#pragma unroll
    for (int jj = 0; jj < 2; jj++)
#pragma unroll
        for (int r = 0; r < 4; r++) d[jj][r] = 0.f;

#pragma unroll
    for (int kt = 0; kt < 32; kt++) {
        uint4 h4 = __ldg((const uint4*)(ha + kt * 1024 + swz));
        uint4 l4 = __ldg((const uint4*)(ha + kt * 1024 + (swz ^ 4)));
        unsigned ahi[4] = {h4.x, h4.y, h4.z, h4.w};
        unsigned alo[4] = {l4.x, l4.y, l4.z, l4.w};
        uint4 b0 = __ldg((const uint4*)(wa + kt * 512));
        uint4 b1 = __ldg((const uint4*)(wa + kt * 512 + 128));
        {
            unsigned bhi2[2] = {b0.x, b0.y};
            unsigned blo2[2] = {b0.z, b0.w};
            mmabf(d[0], alo, bhi2);
            mmabf(d[0], ahi, blo2);
            mmabf(d[0], ahi, bhi2);
        }
        {
            unsigned bhi2[2] = {b1.x, b1.y};
            unsigned blo2[2] = {b1.z, b1.w};
            mmabf(d[1], alo, bhi2);
            mmabf(d[1], ahi, blo2);
            mmabf(d[1], ahi, bhi2);
        }
    }
    __syncthreads();   // gsm preload visible to all before accumulation

    // single-phase accumulation: each (m16, n8) region owned by exactly one warp
    {
        const int gr = lane >> 2, q2 = 2 * (lane & 3);
#pragma unroll
        for (int jj = 0; jj < 2; jj++) {
            int rb = mw * 16 + gr;
            int cb = (nw * 2 + jj) * 8 + q2;
            gsm[rb][cb]           += d[jj][0];
            gsm[rb][cb + 1]       += d[jj][1];
            gsm[rb + 8][cb]       += d[jj][2];
            gsm[rb + 8][cb + 1]   += d[jj][3];
        }
    }
    __syncthreads();

    // activations + masked state update: 64 b x 8 cells = 512 states, cell pairs (all 256 threads)
    {
        int b = tid >> 2, q = tid & 3;
        int lc0 = 2 * q;
        int cell0 = c0 + lc0;
        float gate[2][4];
#pragma unroll
        for (int u = 0; u < 2; u++) {
            int lc = lc0 + u;
            gate[u][0] = gsm[b][lc];            // i
            gate[u][1] = gsm[b][8 + lc];        // f
            gate[u][2] = gsm[b][16 + lc];       // g
            gate[u][3] = gsm[b][24 + lc];       // o
        }
        int ci = (dir * BB + b) * CC + cell0;
        float2 c_old = *(const float2*)(g_c + ci);
        const float* hb_in = g_hbuf + (size_t)pd_in * BB * CC;
        float2 h_old = *(const float2*)(hb_in + b * CC + cell0);
        bool m = (t < length[b]);
        float hf[2], cf[2], ho[2];
#pragma unroll
        for (int u = 0; u < 2; u++) {
            float ig = 1.f / (1.f + expf(-gate[u][0]));
            float fg = 1.f / (1.f + expf(-gate[u][1]));
            float gg = tanhf(gate[u][2]);
            float og = 1.f / (1.f + expf(-gate[u][3]));
            float co = u ? c_old.y : c_old.x;
            float hol = u ? h_old.y : h_old.x;
            float cn = fg * co + ig * gg;
            float hn = og * tanhf(cn);
            cf[u] = m ? cn : co;
            hf[u] = m ? hn : hol;
            ho[u] = m ? hn : 0.f;
        }
        *(float2*)(g_c + ci) = make_float2(cf[0], cf[1]);
        float* hb_out = g_hbuf + (size_t)pd_out * BB * CC;
        *(float2*)(hb_out + b * CC + cell0) = make_float2(hf[0], hf[1]);
        __stcs((float2*)(outp + (size_t)t * (BB * HH) + b * HH + (dir << 9) + cell0),
               make_float2(ho[0], ho[1]));
        // bf16-split fragment-major h write (with hi/lo quad swizzle)
        unsigned short h0, l0, h1, l1;
        split_bf(hf[0], h0, l0);
        split_bf(hf[1], h1, l1);
        unsigned hi01 = (unsigned)h0 | ((unsigned)h1 << 16);
        unsigned lo01 = (unsigned)l0 | ((unsigned)l1 << 16);
        int kt = blkc >> 1;
        int mi = b >> 4, r = b & 15;
        int lane_w = (r & 7) * 4 + q;
        int reg = ((r >> 3) & 1) + ((blkc & 1) << 1);
        int sw = ((lane_w >> 2) & 1) * 4;
        unsigned* hf_out = g_hfragB + pd_out * 32768;
        unsigned base = kt * 1024 + mi * 256 + lane_w * 8;
        hf_out[base + sw + reg]       = hi01;
        hf_out[base + (sw ^ 4) + reg] = lo01;
    }
}

// ---------------- final states ----------------
__global__ void k_final(float* __restrict__ outp) {
    int idx = blockIdx.x * 256 + threadIdx.x;   // 0..65535
    int dir = idx >> 15;
    int r = idx & 32767;
    int b = r >> 9, c = r & 511;
    outp[OFF_H + b * HH + dir * CC + c] = g_hbuf[(size_t)dir * BB * CC + b * CC + c];
    outp[OFF_C + b * HH + dir * CC + c] = g_c[(dir * BB + b) * CC + c];
}

// ---------------- attention scores (fp32, symmetric) ----------------
__global__ void __launch_bounds__(256) k_scores(const float* __restrict__ outp) {
    const int tj = blockIdx.x, ti = blockIdx.y, b = blockIdx.z;
    if (ti > tj) return;
    __shared__ __align__(16) float As[16][64];
    __shared__ __align__(16) float Bs[16][64];
    const int tid = threadIdx.x;
    const int rg = tid & 15, cg = tid >> 4;
    const int lr = tid >> 2, lk = (tid & 3) << 2;
    const float* Ap = outp + (size_t)(ti * 64 + lr) * (BB * HH) + b * HH + lk;
    const float* Bp = outp + (size_t)(tj * 64 + lr) * (BB * HH) + b * HH + lk;
    float acc[4][4];
#pragma unroll
    for (int i = 0; i < 4; i++)
#pragma unroll
        for (int j = 0; j < 4; j++) acc[i][j] = 0.f;

    for (int k0 = 0; k0 < HH; k0 += 16) {
        float4 av = *(const float4*)(Ap + k0);
        float4 bv = *(const float4*)(Bp + k0);
        __syncthreads();
        As[lk + 0][lr] = av.x; As[lk + 1][lr] = av.y; As[lk + 2][lr] = av.z; As[lk + 3][lr] = av.w;
        Bs[lk + 0][lr] = bv.x; Bs[lk + 1][lr] = bv.y; Bs[lk + 2][lr] = bv.z; Bs[lk + 3][lr] = bv.w;
        __syncthreads();
#pragma unroll
        for (int k = 0; k < 16; k++) {
            float4 a4 = *(const float4*)&As[k][rg * 4];
            float4 b4 = *(const float4*)&Bs[k][cg * 4];
            acc[0][0] += a4.x * b4.x; acc[0][1] += a4.x * b4.y; acc[0][2] += a4.x * b4.z; acc[0][3] += a4.x * b4.w;
            acc[1][0] += a4.y * b4.x; acc[1][1] += a4.y * b4.y; acc[1][2] += a4.y * b4.z; acc[1][3] += a4.y * b4.w;
            acc[2][0] += a4.z * b4.x; acc[2][1] += a4.z * b4.y; acc[2][2] += a4.z * b4.z; acc[2][3] += a4.z * b4.w;
            acc[3][0] += a4.w * b4.x; acc[3][1] += a4.w * b4.y; acc[3][2] += a4.w * b4.z; acc[3][3] += a4.w * b4.w;
        }
    }
#pragma unroll
    for (int i = 0; i < 4; i++) {
        int trow = ti * 64 + rg * 4 + i;
#pragma unroll
        for (int j = 0; j < 4; j++) {
            int scol = tj * 64 + cg * 4 + j;
            g_scores[((size_t)b * TT + trow) * TT + scol] = acc[i][j];
            if (ti < tj)
                g_scores[((size_t)b * TT + scol) * TT + trow] = acc[i][j];
        }
    }
}

// ---------------- per-row softmax stats ----------------
__global__ void k_rowstats() {
    int warp = threadIdx.x >> 5, lane = threadIdx.x & 31;
    int row = blockIdx.x * 8 + warp;
    const float* sc = g_scores + (size_t)row * TT;
    float mx = -1e30f;
    for (int s = lane; s < TT; s += 32) mx = fmaxf(mx, sc[s]);
#pragma unroll
    for (int o = 16; o > 0; o >>= 1) mx = fmaxf(mx, __shfl_xor_sync(0xffffffffu, mx, o));
    float sum = 0.f;
    for (int s = lane; s < TT; s += 32) sum += expf(sc[s] - mx);
#pragma unroll
    for (int o = 16; o > 0; o >>= 1) sum += __shfl_xor_sync(0xffffffffu, sum, o);
    if (lane == 0) {
        g_rowmax[row] = mx;
        g_rowinv[row] = 1.f / sum;
    }
}

// ---------------- w[b,s] = sum_t attn[b,t,s] ----------------
__global__ void k_colsum() {
    int s = blockIdx.x * 256 + threadIdx.x;
    int b = blockIdx.y;
    float acc = 0.f;
    const float* sc = g_scores + (size_t)b * TT * TT + s;
    const float* rm = g_rowmax + b * TT;
    const float* ri = g_rowinv + b * TT;
    for (int t = 0; t < TT; t++)
        acc += expf(sc[(size_t)t * TT] - rm[t]) * ri[t];
    g_w[b * TT + s] = acc;
}

// ---------------- pre[b,h] = sum_s w[b,s] * out[s,b,h] ----------------
__global__ void k_ctxpre(const float* __restrict__ outp) {
    int h = blockIdx.x * 256 + threadIdx.x;
    int b = blockIdx.y;
    const float* w = g_w + b * TT;
    float acc = 0.f;
    for (int s = 0; s < TT; s++)
        acc += w[s] * outp[(size_t)s * (BB * HH) + b * HH + h];
    g_pre[b * HH + h] = acc;
}

// ---------------- context projection ----------------
__global__ void __launch_bounds__(128) k_ctxgemm(
    const float* __restrict__ Wctx, const float* __restrict__ bctx,
    float* __restrict__ outp)
{
    __shared__ float sp[HH];
    int tid = threadIdx.x;
    int b = blockIdx.y;
    for (int i = tid; i < HH; i += 128) sp[i] = g_pre[b * HH + i];
    __syncthreads();
    int n = blockIdx.x * 128 + tid;
    const float* wr = Wctx + (size_t)n * HH;
    float acc = bctx[n];
    for (int h = 0; h < HH; h += 4) {
        float4 w4 = *(const float4*)(wr + h);
        acc += sp[h] * w4.x + sp[h + 1] * w4.y + sp[h + 2] * w4.z + sp[h + 3] * w4.w;
    }
    outp[OFF_CTX + b * HH + n] = acc;
}

// ---------------- launch ----------------
extern "C" void kernel_launch(void* const* d_in, const int* in_sizes, int n_in,
                              void* d_out, int out_size)
{
    const float* x      = (const float*)d_in[0];
    const int*   length = (const int*)  d_in[1];
    const float* Wih_f  = (const float*)d_in[2];
    const float* Whh_f  = (const float*)d_in[3];
    const float* bih_f  = (const float*)d_in[4];
    const float* bhh_f  = (const float*)d_in[5];
    const float* Wih_b  = (const float*)d_in[6];
    const float* Whh_b  = (const float*)d_in[7];
    const float* bih_b  = (const float*)d_in[8];
    const float* bhh_b  = (const float*)d_in[9];
    const float* Wctx   = (const float*)d_in[10];
    const float* bctx   = (const float*)d_in[11];
    float* out = (float*)d_out;

    cudaFuncSetAttribute(k_gatesx3, cudaFuncAttributeMaxDynamicSharedMemorySize, GX_SMEM_BYTES);

    k_zero<<<256, 256>>>();
    k_prep<<<4096, 256>>>(Whh_f, Whh_b);
    k_gatesx3<<<dim3(32, 256, 2), 256, GX_SMEM_BYTES>>>(x, Wih_f, Wih_b, bih_f, bhh_f, bih_b, bhh_b);
    for (int s = 0; s < TT; s++)
        k_stepd<<<128, 256>>>(length, out, s);
    k_final<<<256, 256>>>(out);
    k_scores<<<dim3(8, 8, 64), 256>>>(out);
    k_rowstats<<<TT * BB / 8, 256>>>();
    k_colsum<<<dim3(2, 64), 256>>>();
    k_ctxpre<<<dim3(4, 64), 256>>>(out);
    k_ctxgemm<<<dim3(8, 64), 128>>>(Wctx, bctx, out);
}

// round 14
// speedup vs baseline: 2.9112x; 1.0231x over previous
#include <cuda_runtime.h>
#include <cuda_bf16.h>
#include <math.h>

// Problem constants
#define TT   512
#define BB   64
#define II   512
#define CC   512            // cell size
#define HH   1024           // output hidden (2*CC)
#define G4   2048           // 4*CC gate rows
#define M1   (TT*BB)        // 32768 rows for input gemm

// d_out layout: output [T,B,H] | final_h [1,B,H] | final_c [1,B,H] | context [B,H]
#define OFF_OUT  0
#define OFF_H    ((size_t)TT*BB*HH)
#define OFF_C    (OFF_H + (size_t)BB*HH)
#define OFF_CTX  (OFF_C + (size_t)BB*HH)

// ---------------- device scratch ----------------
__device__ float    g_gx[(size_t)2 * M1 * G4];       // x@Wih^T + bih + bhh per dir
__device__ float    g_scores[(size_t)BB * TT * TT];
__device__ float    g_hbuf[2 * 2 * BB * CC];         // fp32 h: [parity][dir][b][c]
// h in bf16-split mma-fragment-major form: [pd 0..3][kt 0..31][mi 0..3][lane 0..31][8 words, hi/lo quads swizzled]
__device__ __align__(128) unsigned g_hfragB[4 * 32768];
// Whh bf16-split fragment-major per step-block: [blk 0..127][kt 0..31][jn 0..3][lane 0..31][bh0,bh1,bl0,bl1]
__device__ __align__(128) unsigned g_wtfB[(size_t)128 * 16384];
__device__ float    g_c[2 * BB * CC];                // [dir][b][c]
__device__ float    g_rowmax[BB * TT];
__device__ float    g_rowinv[BB * TT];
__device__ float    g_w[BB * TT];
__device__ float    g_pre[BB * HH];

// ---------------- helpers ----------------
__device__ __forceinline__ unsigned f2tf(float f) {
    unsigned r;
    asm("cvt.rna.tf32.f32 %0, %1;" : "=r"(r) : "f"(f));
    return r;
}
__device__ __forceinline__ void split_tf(float v, unsigned& hi, unsigned& lo) {
    hi = f2tf(v);
    lo = f2tf(v - __uint_as_float(hi));
}
// bf16 2-way split: v ~= hi + lo with ~16 mantissa bits total
__device__ __forceinline__ void split_bf(float v, unsigned short& hi, unsigned short& lo) {
    __nv_bfloat16 h = __float2bfloat16(v);
    __nv_bfloat16 l = __float2bfloat16(v - __bfloat162float(h));
    hi = __bfloat16_as_ushort(h);
    lo = __bfloat16_as_ushort(l);
}
__device__ __forceinline__ void mma8(float* d, const unsigned* a, const unsigned* b) {
    asm volatile(
        "mma.sync.aligned.m16n8k8.row.col.f32.tf32.tf32.f32 "
        "{%0,%1,%2,%3},{%4,%5,%6,%7},{%8,%9},{%0,%1,%2,%3};"
        : "+f"(d[0]), "+f"(d[1]), "+f"(d[2]), "+f"(d[3])
        : "r"(a[0]), "r"(a[1]), "r"(a[2]), "r"(a[3]), "r"(b[0]), "r"(b[1]));
}
__device__ __forceinline__ void mmabf(float* d, const unsigned* a, const unsigned* b) {
    asm volatile(
        "mma.sync.aligned.m16n8k16.row.col.f32.bf16.bf16.f32 "
        "{%0,%1,%2,%3},{%4,%5,%6,%7},{%8,%9},{%0,%1,%2,%3};"
        : "+f"(d[0]), "+f"(d[1]), "+f"(d[2]), "+f"(d[3])
        : "r"(a[0]), "r"(a[1]), "r"(a[2]), "r"(a[3]), "r"(b[0]), "r"(b[1]));
}
__device__ __forceinline__ void prefetchL2(const void* p) {
    asm volatile("prefetch.global.L2 [%0];" :: "l"(p));
}

// ---------------- init ----------------
__global__ void k_zero() {
    int i = blockIdx.x * 256 + threadIdx.x;   // 65536 threads
    if (i < 2 * 32768) g_hfragB[i] = 0u;      // parity-0 fragment h (both dirs)
    g_hbuf[i] = 0.f;                          // parity-0 fp32 h region
    g_c[i]    = 0.f;
}

// ---------------- weight prep: Whh -> bf16-split fragment-major (unchanged) ----------------
__global__ void k_prep(const float* __restrict__ Whhf, const float* __restrict__ Whhb) {
    int v = blockIdx.x * 256 + threadIdx.x;    // 0..1048575
    int kp = v & 255;                          // k pair index
    int rj = v >> 8;                           // 0..4095
    int j = rj & 31;
    int blk = rj >> 5;                         // 0..127
    int dir = blk >> 6, blkc = blk & 63;
    const float* W = dir ? Whhb : Whhf;
    int G = ((j >> 3) << 9) + blkc * 8 + (j & 7);
    int k0 = kp * 2;
    float v0 = W[(size_t)G * CC + k0];
    float v1 = W[(size_t)G * CC + k0 + 1];
    unsigned short h0, l0, h1, l1;
    split_bf(v0, h0, l0);
    split_bf(v1, h1, l1);
    unsigned hi01 = (unsigned)h0 | ((unsigned)h1 << 16);
    unsigned lo01 = (unsigned)l0 | ((unsigned)l1 << 16);
    int kt = k0 >> 4, kk0 = k0 & 15;
    int jn = j >> 3;
    int lane = (j & 7) * 4 + ((kk0 & 7) >> 1);
    int reg = (kk0 >= 8) ? 1 : 0;
    size_t addr = (size_t)blk * 16384 + kt * 512 + jn * 128 + lane * 4;
    g_wtfB[addr + reg]     = hi01;
    g_wtfB[addr + 2 + reg] = lo01;
}

// ---------------- phase 1: gx = x @ Wih^T + bih + bhh  (3xTF32 mma) — unchanged ----------------
#define GX_SMEM_WORDS ((128 + 128 + 64 + 64) * 36)
#define GX_SMEM_BYTES (GX_SMEM_WORDS * 4)

__global__ void __launch_bounds__(256) k_gatesx3(
    const float* __restrict__ x,
    const float* __restrict__ Wf, const float* __restrict__ Wb,
    const float* __restrict__ bif, const float* __restrict__ bhf,
    const float* __restrict__ bib, const float* __restrict__ bhb)
{
    extern __shared__ unsigned sg[];
    unsigned* Ahi = sg;
    unsigned* Alo = sg + 4608;
    unsigned* Bhi = sg + 9216;
    unsigned* Blo = sg + 11520;

    const int dir = blockIdx.z;
    const float* W  = dir ? Wb  : Wf;
    const float* bi = dir ? bib : bif;
    const float* bh = dir ? bhb : bhf;
    float* out = g_gx + (size_t)dir * M1 * G4;

    const int m0 = blockIdx.y * 128;
    const int n0 = blockIdx.x * 64;
    const int tid = threadIdx.x;
    const int w = tid >> 5, lane = tid & 31;
    const int mg = w & 3;
    const int ng = w >> 2;

    float d[2][4][4];
#pragma unroll
    for (int i = 0; i < 2; i++)
#pragma unroll
        for (int j = 0; j < 4; j++)
#pragma unroll
            for (int r = 0; r < 4; r++) d[i][j][r] = 0.f;

    const unsigned aoff = (mg * 32 + (lane >> 2)) * 36 + (lane & 3);
    const unsigned boff = (ng * 32 + (lane >> 2)) * 36 + (lane & 3);

    for (int kc = 0; kc < 16; kc++) {
        const int k0 = kc * 32;
        float4 av[4], bv[2];
#pragma unroll
        for (int it = 0; it < 4; it++) {
            int v = it * 256 + tid, r = v >> 3, kq = v & 7;
            av[it] = *(const float4*)(x + (size_t)(m0 + r) * II + k0 + kq * 4);
        }
#pragma unroll
        for (int it = 0; it < 2; it++) {
            int v = it * 256 + tid, r = v >> 3, kq = v & 7;
            bv[it] = *(const float4*)(W + (size_t)(n0 + r) * II + k0 + kq * 4);
        }
        __syncthreads();
#pragma unroll
        for (int it = 0; it < 4; it++) {
            int v = it * 256 + tid, r = v >> 3, kq = v & 7;
            unsigned* dh = Ahi + r * 36 + kq * 4;
            unsigned* dl = Alo + r * 36 + kq * 4;
            split_tf(av[it].x, dh[0], dl[0]); split_tf(av[it].y, dh[1], dl[1]);
            split_tf(av[it].z, dh[2], dl[2]); split_tf(av[it].w, dh[3], dl[3]);
        }
#pragma unroll
        for (int it = 0; it < 2; it++) {
            int v = it * 256 + tid, r = v >> 3, kq = v & 7;
            unsigned* dh = Bhi + r * 36 + kq * 4;
            unsigned* dl = Blo + r * 36 + kq * 4;
            split_tf(bv[it].x, dh[0], dl[0]); split_tf(bv[it].y, dh[1], dl[1]);
            split_tf(bv[it].z, dh[2], dl[2]); split_tf(bv[it].w, dh[3], dl[3]);
        }
        __syncthreads();
        unsigned* ah = Ahi + aoff;  unsigned* al = Alo + aoff;
        unsigned* bhp = Bhi + boff; unsigned* blp = Blo + boff;
#pragma unroll
        for (int kt = 0; kt < 4; kt++) {
            unsigned ahi[2][4], alo[2][4];
            ahi[0][0] = ah[0];            ahi[0][1] = ah[8 * 36];
            ahi[0][2] = ah[4];            ahi[0][3] = ah[8 * 36 + 4];
            ahi[1][0] = ah[16 * 36];      ahi[1][1] = ah[24 * 36];
            ahi[1][2] = ah[16 * 36 + 4];  ahi[1][3] = ah[24 * 36 + 4];
            alo[0][0] = al[0];            alo[0][1] = al[8 * 36];
            alo[0][2] = al[4];            alo[0][3] = al[8 * 36 + 4];
            alo[1][0] = al[16 * 36];      alo[1][1] = al[24 * 36];
            alo[1][2] = al[16 * 36 + 4];  alo[1][3] = al[24 * 36 + 4];
#pragma unroll
            for (int j = 0; j < 4; j++) {
                unsigned bhi2[2], blo2[2];
                bhi2[0] = bhp[j * 8 * 36];     bhi2[1] = bhp[j * 8 * 36 + 4];
                blo2[0] = blp[j * 8 * 36];     blo2[1] = blp[j * 8 * 36 + 4];
#pragma unroll
                for (int i = 0; i < 2; i++) {
                    mma8(d[i][j], alo[i], bhi2);
                    mma8(d[i][j], ahi[i], blo2);
                    mma8(d[i][j], ahi[i], bhi2);
                }
            }
            ah += 8; al += 8; bhp += 8; blp += 8;
        }
    }

#pragma unroll
    for (int i = 0; i < 2; i++) {
        int rb = m0 + mg * 32 + i * 16 + (lane >> 2);
#pragma unroll
        for (int j = 0; j < 4; j++) {
            int cb = n0 + ng * 32 + j * 8 + 2 * (lane & 3);
            float bs0 = bi[cb] + bh[cb];
            float bs1 = bi[cb + 1] + bh[cb + 1];
            out[(size_t)rb * G4 + cb]           = d[i][j][0] + bs0;
            out[(size_t)rb * G4 + cb + 1]       = d[i][j][1] + bs1;
            out[(size_t)(rb + 8) * G4 + cb]     = d[i][j][2] + bs0;
            out[(size_t)(rb + 8) * G4 + cb + 1] = d[i][j][3] + bs1;
        }
    }
}

// ---------------- phase 2: one LSTM timestep — direct-LDG, 16 warps, K-split ----------------
// grid 128: dir = blk>>6, blkc = blk&63, 8 cells (=32 gate cols). Tile C[64 batch, 32 gates], K=512.
// 16 warps: kh = w>>3 (K half, 16 kt each), mw = w&3 (m16 tile), nw = (w>>2)&1 (gate half).
// Fragments LDG.128'd straight from fragment-major global arrays; duplicates hit L1.
__global__ void __launch_bounds__(512, 1) k_stepe(
    const int* __restrict__ length, float* __restrict__ outp, int step)
{
    __shared__ float gsm[64][33];

    const int tid = threadIdx.x, w = tid >> 5, lane = tid & 31;
    const int dir  = blockIdx.x >> 6;
    const int blkc = blockIdx.x & 63;
    const int c0   = blkc << 3;
    const int t    = dir ? (TT - 1 - step) : step;
    const int p    = step & 1;
    const int pd_in  = p * 2 + dir;
    const int pd_out = (p ^ 1) * 2 + dir;
    const unsigned* hsrc = g_hfragB + pd_in * 32768;
    const unsigned* wsrc = g_wtfB + (size_t)blockIdx.x * 16384;

    // prefetch next step's gx slice into L2 (threads 0..255, 32B each)
    if (tid < 256 && step + 1 < TT) {
        const int tn = dir ? (t - 1) : (t + 1);
        const float* gxn = g_gx + ((size_t)dir * M1 + (size_t)tn * BB) * G4;
        int b = tid >> 2, grp = tid & 3;
        prefetchL2(gxn + (size_t)b * G4 + grp * 512 + c0);
    }

    // preload gsm with precomputed x-gates (streaming loads)
    {
        const float* gx = g_gx + ((size_t)dir * M1 + (size_t)t * BB) * G4;
#pragma unroll
        for (int u = 0; u < 4; u++) {
            int v = u * 512 + tid;               // 0..2047
            int b = v >> 5, j = v & 31;
            int G = ((j >> 3) << 9) + c0 + (j & 7);
            gsm[b][j] = __ldcs(gx + (size_t)b * G4 + G);
        }
    }

    const int kh = w >> 3;
    const int mw = w & 3;
    const int nw = (w >> 2) & 1;
    const int swz = ((lane >> 2) & 1) * 4;       // hi/lo quad swizzle (matches writer)

    const unsigned* ha = hsrc + kh * 16 * 1024 + mw * 256 + lane * 8;
    const unsigned* wa = wsrc + kh * 16 * 512 + nw * 256 + lane * 4;

    float d[2][4];
#pragma unroll
    for (int jj = 0; jj < 2; jj++)
#pragma unroll
        for (int r = 0; r < 4; r++) d[jj][r] = 0.f;

#pragma unroll
    for (int kt = 0; kt < 16; kt++) {
        uint4 h4 = __ldg((const uint4*)(ha + kt * 1024 + swz));
        uint4 l4 = __ldg((const uint4*)(ha + kt * 1024 + (swz ^ 4)));
        unsigned ahi[4] = {h4.x, h4.y, h4.z, h4.w};
        unsigned alo[4] = {l4.x, l4.y, l4.z, l4.w};
        uint4 b0 = __ldg((const uint4*)(wa + kt * 512));
        uint4 b1 = __ldg((const uint4*)(wa + kt * 512 + 128));
        {
            unsigned bhi2[2] = {b0.x, b0.y};
            unsigned blo2[2] = {b0.z, b0.w};
            mmabf(d[0], alo, bhi2);
            mmabf(d[0], ahi, blo2);
            mmabf(d[0], ahi, bhi2);
        }
        {
            unsigned bhi2[2] = {b1.x, b1.y};
            unsigned blo2[2] = {b1.z, b1.w};
            mmabf(d[1], alo, bhi2);
            mmabf(d[1], ahi, blo2);
            mmabf(d[1], ahi, bhi2);
        }
    }
    __syncthreads();   // gsm preload visible before accumulation

    // two-phase accumulation (K halves collide on the same gsm entries)
    {
        const int gr = lane >> 2, q2 = 2 * (lane & 3);
        if (kh == 0) {
#pragma unroll
            for (int jj = 0; jj < 2; jj++) {
                int rb = mw * 16 + gr;
                int cb = (nw * 2 + jj) * 8 + q2;
                gsm[rb][cb]         += d[jj][0];
                gsm[rb][cb + 1]     += d[jj][1];
                gsm[rb + 8][cb]     += d[jj][2];
                gsm[rb + 8][cb + 1] += d[jj][3];
            }
        }
        __syncthreads();
        if (kh == 1) {
#pragma unroll
            for (int jj = 0; jj < 2; jj++) {
                int rb = mw * 16 + gr;
                int cb = (nw * 2 + jj) * 8 + q2;
                gsm[rb][cb]         += d[jj][0];
                gsm[rb][cb + 1]     += d[jj][1];
                gsm[rb + 8][cb]     += d[jj][2];
                gsm[rb + 8][cb + 1] += d[jj][3];
            }
        }
        __syncthreads();
    }

    // activations + masked state update: threads 0..255 handle 64 b x 8 cells as pairs
    if (tid < 256) {
        int b = tid >> 2, q = tid & 3;
        int lc0 = 2 * q;
        int cell0 = c0 + lc0;
        float gate[2][4];
#pragma unroll
        for (int u = 0; u < 2; u++) {
            int lc = lc0 + u;
            gate[u][0] = gsm[b][lc];            // i
            gate[u][1] = gsm[b][8 + lc];        // f
            gate[u][2] = gsm[b][16 + lc];       // g
            gate[u][3] = gsm[b][24 + lc];       // o
        }
        int ci = (dir * BB + b) * CC + cell0;
        float2 c_old = *(const float2*)(g_c + ci);
        const float* hb_in = g_hbuf + (size_t)pd_in * BB * CC;
        float2 h_old = *(const float2*)(hb_in + b * CC + cell0);
        bool m = (t < length[b]);
        float hf[2], cf[2], ho[2];
#pragma unroll
        for (int u = 0; u < 2; u++) {
            float ig = 1.f / (1.f + expf(-gate[u][0]));
            float fg = 1.f / (1.f + expf(-gate[u][1]));
            float gg = tanhf(gate[u][2]);
            float og = 1.f / (1.f + expf(-gate[u][3]));
            float co = u ? c_old.y : c_old.x;
            float hol = u ? h_old.y : h_old.x;
            float cn = fg * co + ig * gg;
            float hn = og * tanhf(cn);
            cf[u] = m ? cn : co;
            hf[u] = m ? hn : hol;
            ho[u] = m ? hn : 0.f;
        }
        *(float2*)(g_c + ci) = make_float2(cf[0], cf[1]);
        float* hb_out = g_hbuf + (size_t)pd_out * BB * CC;
        *(float2*)(hb_out + b * CC + cell0) = make_float2(hf[0], hf[1]);
        __stcs((float2*)(outp + (size_t)t * (BB * HH) + b * HH + (dir << 9) + cell0),
               make_float2(ho[0], ho[1]));
        // bf16-split fragment-major h write (with hi/lo quad swizzle)
        unsigned short h0, l0, h1, l1;
        split_bf(hf[0], h0, l0);
        split_bf(hf[1], h1, l1);
        unsigned hi01 = (unsigned)h0 | ((unsigned)h1 << 16);
        unsigned lo01 = (unsigned)l0 | ((unsigned)l1 << 16);
        int kt = blkc >> 1;
        int mi = b >> 4, r = b & 15;
        int lane_w = (r & 7) * 4 + q;
        int reg = ((r >> 3) & 1) + ((blkc & 1) << 1);
        int sw = ((lane_w >> 2) & 1) * 4;
        unsigned* hf_out = g_hfragB + pd_out * 32768;
        unsigned base = kt * 1024 + mi * 256 + lane_w * 8;
        hf_out[base + sw + reg]       = hi01;
        hf_out[base + (sw ^ 4) + reg] = lo01;
    }
}

// ---------------- final states ----------------
__global__ void k_final(float* __restrict__ outp) {
    int idx = blockIdx.x * 256 + threadIdx.x;   // 0..65535
    int dir = idx >> 15;
    int r = idx & 32767;
    int b = r >> 9, c = r & 511;
    outp[OFF_H + b * HH + dir * CC + c] = g_hbuf[(size_t)dir * BB * CC + b * CC + c];
    outp[OFF_C + b * HH + dir * CC + c] = g_c[(dir * BB + b) * CC + c];
}

// ---------------- attention scores (fp32, symmetric) ----------------
__global__ void __launch_bounds__(256) k_scores(const float* __restrict__ outp) {
    const int tj = blockIdx.x, ti = blockIdx.y, b = blockIdx.z;
    if (ti > tj) return;
    __shared__ __align__(16) float As[16][64];
    __shared__ __align__(16) float Bs[16][64];
    const int tid = threadIdx.x;
    const int rg = tid & 15, cg = tid >> 4;
    const int lr = tid >> 2, lk = (tid & 3) << 2;
    const float* Ap = outp + (size_t)(ti * 64 + lr) * (BB * HH) + b * HH + lk;
    const float* Bp = outp + (size_t)(tj * 64 + lr) * (BB * HH) + b * HH + lk;
    float acc[4][4];
#pragma unroll
    for (int i = 0; i < 4; i++)
#pragma unroll
        for (int j = 0; j < 4; j++) acc[i][j] = 0.f;

    for (int k0 = 0; k0 < HH; k0 += 16) {
        float4 av = *(const float4*)(Ap + k0);
        float4 bv = *(const float4*)(Bp + k0);
        __syncthreads();
        As[lk + 0][lr] = av.x; As[lk + 1][lr] = av.y; As[lk + 2][lr] = av.z; As[lk + 3][lr] = av.w;
        Bs[lk + 0][lr] = bv.x; Bs[lk + 1][lr] = bv.y; Bs[lk + 2][lr] = bv.z; Bs[lk + 3][lr] = bv.w;
        __syncthreads();
#pragma unroll
        for (int k = 0; k < 16; k++) {
            float4 a4 = *(const float4*)&As[k][rg * 4];
            float4 b4 = *(const float4*)&Bs[k][cg * 4];
            acc[0][0] += a4.x * b4.x; acc[0][1] += a4.x * b4.y; acc[0][2] += a4.x * b4.z; acc[0][3] += a4.x * b4.w;
            acc[1][0] += a4.y * b4.x; acc[1][1] += a4.y * b4.y; acc[1][2] += a4.y * b4.z; acc[1][3] += a4.y * b4.w;
            acc[2][0] += a4.z * b4.x; acc[2][1] += a4.z * b4.y; acc[2][2] += a4.z * b4.z; acc[2][3] += a4.z * b4.w;
            acc[3][0] += a4.w * b4.x; acc[3][1] += a4.w * b4.y; acc[3][2] += a4.w * b4.z; acc[3][3] += a4.w * b4.w;
        }
    }
#pragma unroll
    for (int i = 0; i < 4; i++) {
        int trow = ti * 64 + rg * 4 + i;
#pragma unroll
        for (int j = 0; j < 4; j++) {
            int scol = tj * 64 + cg * 4 + j;
            g_scores[((size_t)b * TT + trow) * TT + scol] = acc[i][j];
            if (ti < tj)
                g_scores[((size_t)b * TT + scol) * TT + trow] = acc[i][j];
        }
    }
}

// ---------------- per-row softmax stats ----------------
__global__ void k_rowstats() {
    int warp = threadIdx.x >> 5, lane = threadIdx.x & 31;
    int row = blockIdx.x * 8 + warp;
    const float* sc = g_scores + (size_t)row * TT;
    float mx = -1e30f;
    for (int s = lane; s < TT; s += 32) mx = fmaxf(mx, sc[s]);
#pragma unroll
    for (int o = 16; o > 0; o >>= 1) mx = fmaxf(mx, __shfl_xor_sync(0xffffffffu, mx, o));
    float sum = 0.f;
    for (int s = lane; s < TT; s += 32) sum += expf(sc[s] - mx);
#pragma unroll
    for (int o = 16; o > 0; o >>= 1) sum += __shfl_xor_sync(0xffffffffu, sum, o);
    if (lane == 0) {
        g_rowmax[row] = mx;
        g_rowinv[row] = 1.f / sum;
    }
}

// ---------------- w[b,s] = sum_t attn[b,t,s] ----------------
__global__ void k_colsum() {
    int s = blockIdx.x * 256 + threadIdx.x;
    int b = blockIdx.y;
    float acc = 0.f;
    const float* sc = g_scores + (size_t)b * TT * TT + s;
    const float* rm = g_rowmax + b * TT;
    const float* ri = g_rowinv + b * TT;
    for (int t = 0; t < TT; t++)
        acc += expf(sc[(size_t)t * TT] - rm[t]) * ri[t];
    g_w[b * TT + s] = acc;
}

// ---------------- pre[b,h] = sum_s w[b,s] * out[s,b,h] ----------------
__global__ void k_ctxpre(const float* __restrict__ outp) {
    int h = blockIdx.x * 256 + threadIdx.x;
    int b = blockIdx.y;
    const float* w = g_w + b * TT;
    float acc = 0.f;
    for (int s = 0; s < TT; s++)
        acc += w[s] * outp[(size_t)s * (BB * HH) + b * HH + h];
    g_pre[b * HH + h] = acc;
}

// ---------------- context projection ----------------
__global__ void __launch_bounds__(128) k_ctxgemm(
    const float* __restrict__ Wctx, const float* __restrict__ bctx,
    float* __restrict__ outp)
{
    __shared__ float sp[HH];
    int tid = threadIdx.x;
    int b = blockIdx.y;
    for (int i = tid; i < HH; i += 128) sp[i] = g_pre[b * HH + i];
    __syncthreads();
    int n = blockIdx.x * 128 + tid;
    const float* wr = Wctx + (size_t)n * HH;
    float acc = bctx[n];
    for (int h = 0; h < HH; h += 4) {
        float4 w4 = *(const float4*)(wr + h);
        acc += sp[h] * w4.x + sp[h + 1] * w4.y + sp[h + 2] * w4.z + sp[h + 3] * w4.w;
    }
    outp[OFF_CTX + b * HH + n] = acc;
}

// ---------------- launch ----------------
extern "C" void kernel_launch(void* const* d_in, const int* in_sizes, int n_in,
                              void* d_out, int out_size)
{
    const float* x      = (const float*)d_in[0];
    const int*   length = (const int*)  d_in[1];
    const float* Wih_f  = (const float*)d_in[2];
    const float* Whh_f  = (const float*)d_in[3];
    const float* bih_f  = (const float*)d_in[4];
    const float* bhh_f  = (const float*)d_in[5];
    const float* Wih_b  = (const float*)d_in[6];
    const float* Whh_b  = (const float*)d_in[7];
    const float* bih_b  = (const float*)d_in[8];
    const float* bhh_b  = (const float*)d_in[9];
    const float* Wctx   = (const float*)d_in[10];
    const float* bctx   = (const float*)d_in[11];
    float* out = (float*)d_out;

    cudaFuncSetAttribute(k_gatesx3, cudaFuncAttributeMaxDynamicSharedMemorySize, GX_SMEM_BYTES);

    k_zero<<<256, 256>>>();
    k_prep<<<4096, 256>>>(Whh_f, Whh_b);
    k_gatesx3<<<dim3(32, 256, 2), 256, GX_SMEM_BYTES>>>(x, Wih_f, Wih_b, bih_f, bhh_f, bih_b, bhh_b);
    for (int s = 0; s < TT; s++)
        k_stepe<<<128, 512>>>(length, out, s);
    k_final<<<256, 256>>>(out);
    k_scores<<<dim3(8, 8, 64), 256>>>(out);
    k_rowstats<<<TT * BB / 8, 256>>>();
    k_colsum<<<dim3(2, 64), 256>>>();
    k_ctxpre<<<dim3(4, 64), 256>>>(out);
    k_ctxgemm<<<dim3(8, 64), 128>>>(Wctx, bctx, out);
}

// round 16
// speedup vs baseline: 3.3345x; 1.1454x over previous
#include <cuda_runtime.h>
#include <cuda_bf16.h>
#include <math.h>

// Problem constants
#define TT   512
#define BB   64
#define II   512
#define CC   512            // cell size
#define HH   1024           // output hidden (2*CC)
#define G4   2048           // 4*CC gate rows
#define M1   (TT*BB)        // 32768 rows for input gemm

// d_out layout: output [T,B,H] | final_h [1,B,H] | final_c [1,B,H] | context [B,H]
#define OFF_OUT  0
#define OFF_H    ((size_t)TT*BB*HH)
#define OFF_C    (OFF_H + (size_t)BB*HH)
#define OFF_CTX  (OFF_C + (size_t)BB*HH)

// ---------------- device scratch ----------------
__device__ float    g_gx[(size_t)2 * M1 * G4];       // x@Wih^T + bih + bhh per dir
__device__ float    g_scores[(size_t)BB * TT * TT];
__device__ float    g_hbuf[2 * 2 * BB * CC];         // fp32 h: [parity][dir][b][c]
// h in bf16-split mma-fragment-major form: [pd 0..3][kt 0..31][mi 0..3][lane 0..31][8 words, hi/lo quads swizzled]
__device__ __align__(128) unsigned g_hfragB[4 * 32768];
// Whh bf16-split fragment-major per step-block: [blk 0..127][kt 0..31][jn 0..3][lane 0..31][bh0,bh1,bl0,bl1]
__device__ __align__(128) unsigned g_wtfB[(size_t)128 * 16384];
__device__ float    g_c[2 * BB * CC];                // [dir][b][c]
__device__ float    g_rowmax[BB * TT];
__device__ float    g_rowinv[BB * TT];
__device__ float    g_w[BB * TT];
__device__ float    g_pre[BB * HH];

// ---------------- helpers ----------------
// bf16 2-way split: v ~= hi + lo with ~16 mantissa bits total
__device__ __forceinline__ void split_bf(float v, unsigned short& hi, unsigned short& lo) {
    __nv_bfloat16 h = __float2bfloat16(v);
    __nv_bfloat16 l = __float2bfloat16(v - __bfloat162float(h));
    hi = __bfloat16_as_ushort(h);
    lo = __bfloat16_as_ushort(l);
}
// split two floats -> packed bf16x2 hi word + lo word
__device__ __forceinline__ void split_bf2(float f0, float f1, unsigned& hi, unsigned& lo) {
    unsigned short h0, l0, h1, l1;
    split_bf(f0, h0, l0);
    split_bf(f1, h1, l1);
    hi = (unsigned)h0 | ((unsigned)h1 << 16);
    lo = (unsigned)l0 | ((unsigned)l1 << 16);
}
__device__ __forceinline__ void mmabf(float* d, const unsigned* a, const unsigned* b) {
    asm volatile(
        "mma.sync.aligned.m16n8k16.row.col.f32.bf16.bf16.f32 "
        "{%0,%1,%2,%3},{%4,%5,%6,%7},{%8,%9},{%0,%1,%2,%3};"
        : "+f"(d[0]), "+f"(d[1]), "+f"(d[2]), "+f"(d[3])
        : "r"(a[0]), "r"(a[1]), "r"(a[2]), "r"(a[3]), "r"(b[0]), "r"(b[1]));
}
__device__ __forceinline__ void prefetchL2(const void* p) {
    asm volatile("prefetch.global.L2 [%0];" :: "l"(p));
}

// ---------------- init ----------------
__global__ void k_zero() {
    int i = blockIdx.x * 256 + threadIdx.x;   // 65536 threads
    if (i < 2 * 32768) g_hfragB[i] = 0u;      // parity-0 fragment h (both dirs)
    g_hbuf[i] = 0.f;                          // parity-0 fp32 h region
    g_c[i]    = 0.f;
}

// ---------------- weight prep: Whh -> bf16-split fragment-major (unchanged) ----------------
__global__ void k_prep(const float* __restrict__ Whhf, const float* __restrict__ Whhb) {
    int v = blockIdx.x * 256 + threadIdx.x;    // 0..1048575
    int kp = v & 255;                          // k pair index
    int rj = v >> 8;                           // 0..4095
    int j = rj & 31;
    int blk = rj >> 5;                         // 0..127
    int dir = blk >> 6, blkc = blk & 63;
    const float* W = dir ? Whhb : Whhf;
    int G = ((j >> 3) << 9) + blkc * 8 + (j & 7);
    int k0 = kp * 2;
    float v0 = W[(size_t)G * CC + k0];
    float v1 = W[(size_t)G * CC + k0 + 1];
    unsigned hi01, lo01;
    split_bf2(v0, v1, hi01, lo01);
    int kt = k0 >> 4, kk0 = k0 & 15;
    int jn = j >> 3;
    int lane = (j & 7) * 4 + ((kk0 & 7) >> 1);
    int reg = (kk0 >= 8) ? 1 : 0;
    size_t addr = (size_t)blk * 16384 + kt * 512 + jn * 128 + lane * 4;
    g_wtfB[addr + reg]     = hi01;
    g_wtfB[addr + 2 + reg] = lo01;
}

// ---------------- phase 1: gx = x @ Wih^T + bih + bhh  (bf16-split 3-mma) ----------------
// M=32768, N=2048 per dir, K=512. Block tile 128x64, BK=32 (16 bf16x2 pairs), 256 threads.
// Warp tile 32x32: 2 m16 x 4 n8, 2 k16 tiles per chunk. Smem rows stride 20 (conflict-free).
__global__ void __launch_bounds__(256) k_gatesxb(
    const float* __restrict__ x,
    const float* __restrict__ Wf, const float* __restrict__ Wb,
    const float* __restrict__ bif, const float* __restrict__ bhf,
    const float* __restrict__ bib, const float* __restrict__ bhb)
{
    __shared__ unsigned AH[128 * 20];
    __shared__ unsigned AL[128 * 20];
    __shared__ unsigned BH[64 * 20];
    __shared__ unsigned BL[64 * 20];

    const int dir = blockIdx.z;
    const float* W  = dir ? Wb  : Wf;
    const float* bi = dir ? bib : bif;
    const float* bh = dir ? bhb : bhf;
    float* out = g_gx + (size_t)dir * M1 * G4;

    const int m0 = blockIdx.y * 128;
    const int n0 = blockIdx.x * 64;
    const int tid = threadIdx.x;
    const int w = tid >> 5, lane = tid & 31;
    const int mg = w & 3;       // rows mg*32 .. +31
    const int ng = w >> 2;      // cols ng*32 .. +31
    const int lr = lane >> 2, lq = lane & 3;

    float d[2][4][4];
#pragma unroll
    for (int i = 0; i < 2; i++)
#pragma unroll
        for (int j = 0; j < 4; j++)
#pragma unroll
            for (int r = 0; r < 4; r++) d[i][j][r] = 0.f;

    for (int kc = 0; kc < 16; kc++) {
        const int k0 = kc * 32;
        float4 av[4], bv[2];
#pragma unroll
        for (int it = 0; it < 4; it++) {
            int v = it * 256 + tid, r = v >> 3, kq = v & 7;
            av[it] = *(const float4*)(x + (size_t)(m0 + r) * II + k0 + kq * 4);
        }
#pragma unroll
        for (int it = 0; it < 2; it++) {
            int v = it * 256 + tid, r = v >> 3, kq = v & 7;
            bv[it] = *(const float4*)(W + (size_t)(n0 + r) * II + k0 + kq * 4);
        }
        __syncthreads();
#pragma unroll
        for (int it = 0; it < 4; it++) {
            int v = it * 256 + tid, r = v >> 3, kq = v & 7;
            unsigned h01, l01, h23, l23;
            split_bf2(av[it].x, av[it].y, h01, l01);
            split_bf2(av[it].z, av[it].w, h23, l23);
            AH[r * 20 + kq * 2]     = h01;  AH[r * 20 + kq * 2 + 1] = h23;
            AL[r * 20 + kq * 2]     = l01;  AL[r * 20 + kq * 2 + 1] = l23;
        }
#pragma unroll
        for (int it = 0; it < 2; it++) {
            int v = it * 256 + tid, r = v >> 3, kq = v & 7;
            unsigned h01, l01, h23, l23;
            split_bf2(bv[it].x, bv[it].y, h01, l01);
            split_bf2(bv[it].z, bv[it].w, h23, l23);
            BH[r * 20 + kq * 2]     = h01;  BH[r * 20 + kq * 2 + 1] = h23;
            BL[r * 20 + kq * 2]     = l01;  BL[r * 20 + kq * 2 + 1] = l23;
        }
        __syncthreads();
#pragma unroll
        for (int kt = 0; kt < 2; kt++) {
            const int pb = kt * 8 + lq;          // pair base for this lane
            unsigned ahi[2][4], alo[2][4];
#pragma unroll
            for (int im = 0; im < 2; im++) {
                int row = mg * 32 + im * 16 + lr;
                ahi[im][0] = AH[row * 20 + pb];
                ahi[im][1] = AH[(row + 8) * 20 + pb];
                ahi[im][2] = AH[row * 20 + pb + 4];
                ahi[im][3] = AH[(row + 8) * 20 + pb + 4];
                alo[im][0] = AL[row * 20 + pb];
                alo[im][1] = AL[(row + 8) * 20 + pb];
                alo[im][2] = AL[row * 20 + pb + 4];
                alo[im][3] = AL[(row + 8) * 20 + pb + 4];
            }
#pragma unroll
            for (int j = 0; j < 4; j++) {
                int col = ng * 32 + j * 8 + lr;
                unsigned bhi2[2], blo2[2];
                bhi2[0] = BH[col * 20 + pb];
                bhi2[1] = BH[col * 20 + pb + 4];
                blo2[0] = BL[col * 20 + pb];
                blo2[1] = BL[col * 20 + pb + 4];
#pragma unroll
                for (int im = 0; im < 2; im++) {
                    mmabf(d[im][j], alo[im], bhi2);
                    mmabf(d[im][j], ahi[im], blo2);
                    mmabf(d[im][j], ahi[im], bhi2);
                }
            }
        }
    }

    // epilogue: add bias, store (same accumulator layout as before)
#pragma unroll
    for (int i = 0; i < 2; i++) {
        int rb = m0 + mg * 32 + i * 16 + lr;
#pragma unroll
        for (int j = 0; j < 4; j++) {
            int cb = n0 + ng * 32 + j * 8 + 2 * lq;
            float bs0 = bi[cb] + bh[cb];
            float bs1 = bi[cb + 1] + bh[cb + 1];
            out[(size_t)rb * G4 + cb]           = d[i][j][0] + bs0;
            out[(size_t)rb * G4 + cb + 1]       = d[i][j][1] + bs1;
            out[(size_t)(rb + 8) * G4 + cb]     = d[i][j][2] + bs0;
            out[(size_t)(rb + 8) * G4 + cb + 1] = d[i][j][3] + bs1;
        }
    }
}

// ---------------- phase 2: one LSTM timestep — direct-LDG, 16 warps, K-split (unchanged R14) ----------------
__global__ void __launch_bounds__(512, 1) k_stepe(
    const int* __restrict__ length, float* __restrict__ outp, int step)
{
    __shared__ float gsm[64][33];

    const int tid = threadIdx.x, w = tid >> 5, lane = tid & 31;
    const int dir  = blockIdx.x >> 6;
    const int blkc = blockIdx.x & 63;
    const int c0   = blkc << 3;
    const int t    = dir ? (TT - 1 - step) : step;
    const int p    = step & 1;
    const int pd_in  = p * 2 + dir;
    const int pd_out = (p ^ 1) * 2 + dir;
    const unsigned* hsrc = g_hfragB + pd_in * 32768;
    const unsigned* wsrc = g_wtfB + (size_t)blockIdx.x * 16384;

    if (tid < 256 && step + 1 < TT) {
        const int tn = dir ? (t - 1) : (t + 1);
        const float* gxn = g_gx + ((size_t)dir * M1 + (size_t)tn * BB) * G4;
        int b = tid >> 2, grp = tid & 3;
        prefetchL2(gxn + (size_t)b * G4 + grp * 512 + c0);
    }

    {
        const float* gx = g_gx + ((size_t)dir * M1 + (size_t)t * BB) * G4;
#pragma unroll
        for (int u = 0; u < 4; u++) {
            int v = u * 512 + tid;               // 0..2047
            int b = v >> 5, j = v & 31;
            int G = ((j >> 3) << 9) + c0 + (j & 7);
            gsm[b][j] = __ldcs(gx + (size_t)b * G4 + G);
        }
    }

    const int kh = w >> 3;
    const int mw = w & 3;
    const int nw = (w >> 2) & 1;
    const int swz = ((lane >> 2) & 1) * 4;

    const unsigned* ha = hsrc + kh * 16 * 1024 + mw * 256 + lane * 8;
    const unsigned* wa = wsrc + kh * 16 * 512 + nw * 256 + lane * 4;

    float d[2][4];
#pragma unroll
    for (int jj = 0; jj < 2; jj++)
#pragma unroll
        for (int r = 0; r < 4; r++) d[jj][r] = 0.f;

#pragma unroll
    for (int kt = 0; kt < 16; kt++) {
        uint4 h4 = __ldg((const uint4*)(ha + kt * 1024 + swz));
        uint4 l4 = __ldg((const uint4*)(ha + kt * 1024 + (swz ^ 4)));
        unsigned ahi[4] = {h4.x, h4.y, h4.z, h4.w};
        unsigned alo[4] = {l4.x, l4.y, l4.z, l4.w};
        uint4 b0 = __ldg((const uint4*)(wa + kt * 512));
        uint4 b1 = __ldg((const uint4*)(wa + kt * 512 + 128));
        {
            unsigned bhi2[2] = {b0.x, b0.y};
            unsigned blo2[2] = {b0.z, b0.w};
            mmabf(d[0], alo, bhi2);
            mmabf(d[0], ahi, blo2);
            mmabf(d[0], ahi, bhi2);
        }
        {
            unsigned bhi2[2] = {b1.x, b1.y};
            unsigned blo2[2] = {b1.z, b1.w};
            mmabf(d[1], alo, bhi2);
            mmabf(d[1], ahi, blo2);
            mmabf(d[1], ahi, bhi2);
        }
    }
    __syncthreads();

    {
        const int gr = lane >> 2, q2 = 2 * (lane & 3);
        if (kh == 0) {
#pragma unroll
            for (int jj = 0; jj < 2; jj++) {
                int rb = mw * 16 + gr;
                int cb = (nw * 2 + jj) * 8 + q2;
                gsm[rb][cb]         += d[jj][0];
                gsm[rb][cb + 1]     += d[jj][1];
                gsm[rb + 8][cb]     += d[jj][2];
                gsm[rb + 8][cb + 1] += d[jj][3];
            }
        }
        __syncthreads();
        if (kh == 1) {
#pragma unroll
            for (int jj = 0; jj < 2; jj++) {
                int rb = mw * 16 + gr;
                int cb = (nw * 2 + jj) * 8 + q2;
                gsm[rb][cb]         += d[jj][0];
                gsm[rb][cb + 1]     += d[jj][1];
                gsm[rb + 8][cb]     += d[jj][2];
                gsm[rb + 8][cb + 1] += d[jj][3];
            }
        }
        __syncthreads();
    }

    if (tid < 256) {
        int b = tid >> 2, q = tid & 3;
        int lc0 = 2 * q;
        int cell0 = c0 + lc0;
        float gate[2][4];
#pragma unroll
        for (int u = 0; u < 2; u++) {
            int lc = lc0 + u;
            gate[u][0] = gsm[b][lc];
            gate[u][1] = gsm[b][8 + lc];
            gate[u][2] = gsm[b][16 + lc];
            gate[u][3] = gsm[b][24 + lc];
        }
        int ci = (dir * BB + b) * CC + cell0;
        float2 c_old = *(const float2*)(g_c + ci);
        const float* hb_in = g_hbuf + (size_t)pd_in * BB * CC;
        float2 h_old = *(const float2*)(hb_in + b * CC + cell0);
        bool m = (t < length[b]);
        float hf[2], cf[2], ho[2];
#pragma unroll
        for (int u = 0; u < 2; u++) {
            float ig = 1.f / (1.f + expf(-gate[u][0]));
            float fg = 1.f / (1.f + expf(-gate[u][1]));
            float gg = tanhf(gate[u][2]);
            float og = 1.f / (1.f + expf(-gate[u][3]));
            float co = u ? c_old.y : c_old.x;
            float hol = u ? h_old.y : h_old.x;
            float cn = fg * co + ig * gg;
            float hn = og * tanhf(cn);
            cf[u] = m ? cn : co;
            hf[u] = m ? hn : hol;
            ho[u] = m ? hn : 0.f;
        }
        *(float2*)(g_c + ci) = make_float2(cf[0], cf[1]);
        float* hb_out = g_hbuf + (size_t)pd_out * BB * CC;
        *(float2*)(hb_out + b * CC + cell0) = make_float2(hf[0], hf[1]);
        __stcs((float2*)(outp + (size_t)t * (BB * HH) + b * HH + (dir << 9) + cell0),
               make_float2(ho[0], ho[1]));
        unsigned short h0, l0, h1, l1;
        split_bf(hf[0], h0, l0);
        split_bf(hf[1], h1, l1);
        unsigned hi01 = (unsigned)h0 | ((unsigned)h1 << 16);
        unsigned lo01 = (unsigned)l0 | ((unsigned)l1 << 16);
        int kt = blkc >> 1;
        int mi = b >> 4, r = b & 15;
        int lane_w = (r & 7) * 4 + q;
        int reg = ((r >> 3) & 1) + ((blkc & 1) << 1);
        int sw = ((lane_w >> 2) & 1) * 4;
        unsigned* hf_out = g_hfragB + pd_out * 32768;
        unsigned base = kt * 1024 + mi * 256 + lane_w * 8;
        hf_out[base + sw + reg]       = hi01;
        hf_out[base + (sw ^ 4) + reg] = lo01;
    }
}

// ---------------- final states ----------------
__global__ void k_final(float* __restrict__ outp) {
    int idx = blockIdx.x * 256 + threadIdx.x;   // 0..65535
    int dir = idx >> 15;
    int r = idx & 32767;
    int b = r >> 9, c = r & 511;
    outp[OFF_H + b * HH + dir * CC + c] = g_hbuf[(size_t)dir * BB * CC + b * CC + c];
    outp[OFF_C + b * HH + dir * CC + c] = g_c[(dir * BB + b) * CC + c];
}

// ---------------- attention scores (fp32, symmetric) ----------------
__global__ void __launch_bounds__(256) k_scores(const float* __restrict__ outp) {
    const int tj = blockIdx.x, ti = blockIdx.y, b = blockIdx.z;
    if (ti > tj) return;
    __shared__ __align__(16) float As[16][64];
    __shared__ __align__(16) float Bs[16][64];
    const int tid = threadIdx.x;
    const int rg = tid & 15, cg = tid >> 4;
    const int lr = tid >> 2, lk = (tid & 3) << 2;
    const float* Ap = outp + (size_t)(ti * 64 + lr) * (BB * HH) + b * HH + lk;
    const float* Bp = outp + (size_t)(tj * 64 + lr) * (BB * HH) + b * HH + lk;
    float acc[4][4];
#pragma unroll
    for (int i = 0; i < 4; i++)
#pragma unroll
        for (int j = 0; j < 4; j++) acc[i][j] = 0.f;

    for (int k0 = 0; k0 < HH; k0 += 16) {
        float4 av = *(const float4*)(Ap + k0);
        float4 bv = *(const float4*)(Bp + k0);
        __syncthreads();
        As[lk + 0][lr] = av.x; As[lk + 1][lr] = av.y; As[lk + 2][lr] = av.z; As[lk + 3][lr] = av.w;
        Bs[lk + 0][lr] = bv.x; Bs[lk + 1][lr] = bv.y; Bs[lk + 2][lr] = bv.z; Bs[lk + 3][lr] = bv.w;
        __syncthreads();
#pragma unroll
        for (int k = 0; k < 16; k++) {
            float4 a4 = *(const float4*)&As[k][rg * 4];
            float4 b4 = *(const float4*)&Bs[k][cg * 4];
            acc[0][0] += a4.x * b4.x; acc[0][1] += a4.x * b4.y; acc[0][2] += a4.x * b4.z; acc[0][3] += a4.x * b4.w;
            acc[1][0] += a4.y * b4.x; acc[1][1] += a4.y * b4.y; acc[1][2] += a4.y * b4.z; acc[1][3] += a4.y * b4.w;
            acc[2][0] += a4.z * b4.x; acc[2][1] += a4.z * b4.y; acc[2][2] += a4.z * b4.z; acc[2][3] += a4.z * b4.w;
            acc[3][0] += a4.w * b4.x; acc[3][1] += a4.w * b4.y; acc[3][2] += a4.w * b4.z; acc[3][3] += a4.w * b4.w;
        }
    }
#pragma unroll
    for (int i = 0; i < 4; i++) {
        int trow = ti * 64 + rg * 4 + i;
#pragma unroll
        for (int j = 0; j < 4; j++) {
            int scol = tj * 64 + cg * 4 + j;
            g_scores[((size_t)b * TT + trow) * TT + scol] = acc[i][j];
            if (ti < tj)
                g_scores[((size_t)b * TT + scol) * TT + trow] = acc[i][j];
        }
    }
}

// ---------------- per-row softmax stats ----------------
__global__ void k_rowstats() {
    int warp = threadIdx.x >> 5, lane = threadIdx.x & 31;
    int row = blockIdx.x * 8 + warp;
    const float* sc = g_scores + (size_t)row * TT;
    float mx = -1e30f;
    for (int s = lane; s < TT; s += 32) mx = fmaxf(mx, sc[s]);
#pragma unroll
    for (int o = 16; o > 0; o >>= 1) mx = fmaxf(mx, __shfl_xor_sync(0xffffffffu, mx, o));
    float sum = 0.f;
    for (int s = lane; s < TT; s += 32) sum += expf(sc[s] - mx);
#pragma unroll
    for (int o = 16; o > 0; o >>= 1) sum += __shfl_xor_sync(0xffffffffu, sum, o);
    if (lane == 0) {
        g_rowmax[row] = mx;
        g_rowinv[row] = 1.f / sum;
    }
}

// ---------------- w[b,s] = sum_t attn[b,t,s] ----------------
__global__ void k_colsum() {
    int s = blockIdx.x * 256 + threadIdx.x;
    int b = blockIdx.y;
    float acc = 0.f;
    const float* sc = g_scores + (size_t)b * TT * TT + s;
    const float* rm = g_rowmax + b * TT;
    const float* ri = g_rowinv + b * TT;
    for (int t = 0; t < TT; t++)
        acc += expf(sc[(size_t)t * TT] - rm[t]) * ri[t];
    g_w[b * TT + s] = acc;
}

// ---------------- pre[b,h] = sum_s w[b,s] * out[s,b,h] ----------------
__global__ void k_ctxpre(const float* __restrict__ outp) {
    int h = blockIdx.x * 256 + threadIdx.x;
    int b = blockIdx.y;
    const float* w = g_w + b * TT;
    float acc = 0.f;
    for (int s = 0; s < TT; s++)
        acc += w[s] * outp[(size_t)s * (BB * HH) + b * HH + h];
    g_pre[b * HH + h] = acc;
}

// ---------------- context projection ----------------
__global__ void __launch_bounds__(128) k_ctxgemm(
    const float* __restrict__ Wctx, const float* __restrict__ bctx,
    float* __restrict__ outp)
{
    __shared__ float sp[HH];
    int tid = threadIdx.x;
    int b = blockIdx.y;
    for (int i = tid; i < HH; i += 128) sp[i] = g_pre[b * HH + i];
    __syncthreads();
    int n = blockIdx.x * 128 + tid;
    const float* wr = Wctx + (size_t)n * HH;
    float acc = bctx[n];
    for (int h = 0; h < HH; h += 4) {
        float4 w4 = *(const float4*)(wr + h);
        acc += sp[h] * w4.x + sp[h + 1] * w4.y + sp[h + 2] * w4.z + sp[h + 3] * w4.w;
    }
    outp[OFF_CTX + b * HH + n] = acc;
}

// ---------------- launch ----------------
extern "C" void kernel_launch(void* const* d_in, const int* in_sizes, int n_in,
                              void* d_out, int out_size)
{
    const float* x      = (const float*)d_in[0];
    const int*   length = (const int*)  d_in[1];
    const float* Wih_f  = (const float*)d_in[2];
    const float* Whh_f  = (const float*)d_in[3];
    const float* bih_f  = (const float*)d_in[4];
    const float* bhh_f  = (const float*)d_in[5];
    const float* Wih_b  = (const float*)d_in[6];
    const float* Whh_b  = (const float*)d_in[7];
    const float* bih_b  = (const float*)d_in[8];
    const float* bhh_b  = (const float*)d_in[9];
    const float* Wctx   = (const float*)d_in[10];
    const float* bctx   = (const float*)d_in[11];
    float* out = (float*)d_out;

    k_zero<<<256, 256>>>();
    k_prep<<<4096, 256>>>(Whh_f, Whh_b);
    k_gatesxb<<<dim3(32, 256, 2), 256>>>(x, Wih_f, Wih_b, bih_f, bhh_f, bih_b, bhh_b);
    for (int s = 0; s < TT; s++)
        k_stepe<<<128, 512>>>(length, out, s);
    k_final<<<256, 256>>>(out);
    k_scores<<<dim3(8, 8, 64), 256>>>(out);
    k_rowstats<<<TT * BB / 8, 256>>>();
    k_colsum<<<dim3(2, 64), 256>>>();
    k_ctxpre<<<dim3(4, 64), 256>>>(out);
    k_ctxgemm<<<dim3(8, 64), 128>>>(Wctx, bctx, out);
}